// round 1
// baseline (speedup 1.0000x reference)
#include <cuda_runtime.h>
#include <math.h>

#define NTOK   65536
#define DMODEL 128
#define HDIM   256
#define NEXP   32
#define TM     64

// ---------------- device scratch (allocation-free) ----------------
__device__ float g_top_v[2 * NTOK];
__device__ int   g_top_e[2 * NTOK];
__device__ float g_importance[NEXP];
__device__ int   g_counts[NEXP];
__device__ int   g_offsets[NEXP + 1];
__device__ int   g_cursor[NEXP];
__device__ int   g_tile_off[NEXP + 1];
__device__ int   g_total_tiles;
__device__ int   g_bucket_tok[2 * NTOK];
__device__ float g_bucket_w[2 * NTOK];
__device__ int   g_tok_slot[2 * NTOK];
__device__ float g_partial[(size_t)2 * NTOK * DMODEL];   // 64 MB

// ---------------- kernel 1: init ----------------
__global__ void init_kernel() {
    int t = threadIdx.x;
    if (t < NEXP) {
        g_counts[t] = 0;
        g_importance[t] = 0.f;
    }
}

// ---------------- kernel 2: router (warp per token) ----------------
__global__ void __launch_bounds__(256) router_kernel(
    const float* __restrict__ x, const float* __restrict__ Wr,
    const float* __restrict__ br)
{
    __shared__ float wr_s[DMODEL * NEXP];   // 16 KB
    __shared__ float imp_s[NEXP];
    __shared__ int   cnt_s[NEXP];

    const int tid = threadIdx.x;
    if (tid < NEXP) { imp_s[tid] = 0.f; cnt_s[tid] = 0; }
    for (int i = tid; i < DMODEL * NEXP; i += 256) wr_s[i] = Wr[i];
    __syncthreads();

    const int lane = tid & 31;
    const int warp = tid >> 5;
    const unsigned FULL = 0xffffffffu;
    const float brv = br[lane];

    for (int n = blockIdx.x * 8 + warp; n < NTOK; n += gridDim.x * 8) {
        float xr[4];
        #pragma unroll
        for (int q = 0; q < 4; ++q) xr[q] = x[(size_t)n * DMODEL + q * 32 + lane];

        float acc = brv;
        #pragma unroll
        for (int d = 0; d < DMODEL; ++d) {
            float xv = __shfl_sync(FULL, xr[d >> 5], d & 31);
            acc = fmaf(xv, wr_s[d * NEXP + lane], acc);
        }

        // softmax over 32 lanes
        float mx = acc;
        #pragma unroll
        for (int o = 16; o; o >>= 1) mx = fmaxf(mx, __shfl_xor_sync(FULL, mx, o));
        float p = expf(acc - mx);
        float s = p;
        #pragma unroll
        for (int o = 16; o; o >>= 1) s += __shfl_xor_sync(FULL, s, o);
        float prob = p / s;

        // top-1 (ties -> lower index, matching stable top_k)
        float v = prob; int idx = lane;
        #pragma unroll
        for (int o = 16; o; o >>= 1) {
            float ov = __shfl_xor_sync(FULL, v, o);
            int   oi = __shfl_xor_sync(FULL, idx, o);
            if (ov > v || (ov == v && oi < idx)) { v = ov; idx = oi; }
        }
        int i1 = idx; float v1 = v;

        // top-2
        float v2c = (lane == i1) ? -1e30f : prob;
        v = v2c; idx = lane;
        #pragma unroll
        for (int o = 16; o; o >>= 1) {
            float ov = __shfl_xor_sync(FULL, v, o);
            int   oi = __shfl_xor_sync(FULL, idx, o);
            if (ov > v || (ov == v && oi < idx)) { v = ov; idx = oi; }
        }
        int i2 = idx; float v2 = v;

        if (lane == 0) {
            g_top_e[2 * n]     = i1;  g_top_v[2 * n]     = v1;
            g_top_e[2 * n + 1] = i2;  g_top_v[2 * n + 1] = v2;
            atomicAdd(&imp_s[i1], v1);
            atomicAdd(&imp_s[i2], v2);
            atomicAdd(&cnt_s[i1], 1);
            atomicAdd(&cnt_s[i2], 1);
        }
    }
    __syncthreads();
    if (tid < NEXP) {
        atomicAdd(&g_importance[tid], imp_s[tid]);
        atomicAdd(&g_counts[tid], cnt_s[tid]);
    }
}

// ---------------- kernel 3: scan + load-balancing loss ----------------
__global__ void scan_loss_kernel(float* __restrict__ out, int out_size) {
    const int lane = threadIdx.x;           // 32 threads
    const unsigned FULL = 0xffffffffu;

    int c = g_counts[lane];
    int sc = c;
    #pragma unroll
    for (int o = 1; o < 32; o <<= 1) {
        int v = __shfl_up_sync(FULL, sc, o);
        if (lane >= o) sc += v;
    }
    g_offsets[lane] = sc - c;
    g_cursor[lane]  = sc - c;
    if (lane == 31) g_offsets[NEXP] = sc;

    int nt = (c + TM - 1) / TM;
    int st = nt;
    #pragma unroll
    for (int o = 1; o < 32; o <<= 1) {
        int v = __shfl_up_sync(FULL, st, o);
        if (lane >= o) st += v;
    }
    g_tile_off[lane] = st - nt;
    if (lane == 31) { g_tile_off[NEXP] = st; g_total_tiles = st; }

    float imp = g_importance[lane];
    float s = imp;
    #pragma unroll
    for (int o = 16; o; o >>= 1) s += __shfl_xor_sync(FULL, s, o);
    float mean = s / 32.f;
    float d = imp - mean;
    float ss = d * d;
    #pragma unroll
    for (int o = 16; o; o >>= 1) ss += __shfl_xor_sync(FULL, ss, o);
    float var = ss / 31.f;                  // unbiased (ddof=1)
    if (lane == 0 && out_size > NTOK * DMODEL)
        out[NTOK * DMODEL] = var / (mean * mean + 1e-9f);
}

// ---------------- kernel 4: scatter into expert buckets ----------------
__global__ void __launch_bounds__(256) scatter_kernel() {
    __shared__ int lcnt[NEXP];
    __shared__ int gbase[NEXP];
    __shared__ int lcur[NEXP];

    const int tid = threadIdx.x;
    const int n = blockIdx.x * 256 + tid;   // grid covers NTOK exactly
    if (tid < NEXP) lcnt[tid] = 0;
    __syncthreads();

    int e0 = 0, e1 = 0; float v0 = 0.f, v1 = 0.f;
    e0 = g_top_e[2 * n];     v0 = g_top_v[2 * n];
    e1 = g_top_e[2 * n + 1]; v1 = g_top_v[2 * n + 1];
    atomicAdd(&lcnt[e0], 1);
    atomicAdd(&lcnt[e1], 1);
    __syncthreads();

    if (tid < NEXP) {
        gbase[tid] = atomicAdd(&g_cursor[tid], lcnt[tid]);
        lcur[tid] = 0;
    }
    __syncthreads();

    int p0 = gbase[e0] + atomicAdd(&lcur[e0], 1);
    g_bucket_tok[p0] = n; g_bucket_w[p0] = v0; g_tok_slot[2 * n] = p0;
    int p1 = gbase[e1] + atomicAdd(&lcur[e1], 1);
    g_bucket_tok[p1] = n; g_bucket_w[p1] = v1; g_tok_slot[2 * n + 1] = p1;
}

// ---------------- kernel 5: grouped expert GEMM (fused FC1+ReLU+FC2) ----------------
// smem layout (floats, +4 padding for conflict-free LDS.128):
//   xsT  [128][68]  : x tile transposed  (d, m)
//   wbuf [128][68]  : W1 tile (d, j)  -- reused as W2 tile [64][132] (j, dd)
//   hsT  [64][68]   : hidden tile transposed (j, m)
//   wsm  [64], toks [64]
#define SMEM_FLOATS (128*68 + 128*68 + 64*68 + 64)
#define SMEM_BYTES  (SMEM_FLOATS * 4 + 64 * 4)

__global__ void __launch_bounds__(256, 2) expert_gemm_kernel(
    const float* __restrict__ x,  const float* __restrict__ W1,
    const float* __restrict__ b1, const float* __restrict__ W2,
    const float* __restrict__ b2)
{
    extern __shared__ float sm[];
    float* xsT  = sm;
    float* wbuf = sm + 128 * 68;
    float* hsT  = wbuf + 128 * 68;
    float* wsm  = hsT + 64 * 68;
    int*   toks = (int*)(wsm + 64);

    const int tid = threadIdx.x;
    const int total = g_total_tiles;

    for (int t = blockIdx.x; t < total; t += gridDim.x) {
        int e = 0;
        #pragma unroll 1
        while (t >= g_tile_off[e + 1]) ++e;
        const int mtile = t - g_tile_off[e];
        const int off   = g_offsets[e];
        const int cnt   = g_counts[e];
        const int m0g   = mtile * TM;
        const int valid = min(TM, cnt - m0g);

        __syncthreads();  // previous tile's smem fully consumed

        if (tid < TM) {
            if (tid < valid) {
                toks[tid] = g_bucket_tok[off + m0g + tid];
                wsm[tid]  = g_bucket_w[off + m0g + tid];
            } else {
                toks[tid] = 0; wsm[tid] = 0.f;
            }
        }
        __syncthreads();

        #pragma unroll
        for (int i = tid; i < TM * DMODEL; i += 256) {
            int m = i >> 7, d = i & 127;
            float v = (m < valid) ? x[(size_t)toks[m] * DMODEL + d] : 0.f;
            xsT[d * 68 + m] = v;
        }

        const int ty = tid >> 4, tx = tid & 15;
        const int m0 = ty * 4, j0 = tx * 4, dd0 = tx * 8;
        const float* W1e = W1 + (size_t)e * DMODEL * HDIM;
        const float* W2e = W2 + (size_t)e * HDIM * DMODEL;

        float acc[4][8];
        #pragma unroll
        for (int i = 0; i < 4; ++i)
            #pragma unroll
            for (int k = 0; k < 8; ++k) acc[i][k] = 0.f;

        for (int h0 = 0; h0 < HDIM; h0 += 64) {
            __syncthreads();  // xsT ready (1st iter) / wbuf free for W1
            #pragma unroll
            for (int i = tid; i < 128 * 64; i += 256) {
                int d = i >> 6, j = i & 63;
                wbuf[d * 68 + j] = W1e[d * HDIM + h0 + j];
            }
            __syncthreads();

            // FC1: hv[m][j] = sum_d x[m][d] * W1[d][j]
            float hv[4][4];
            #pragma unroll
            for (int i = 0; i < 4; ++i)
                #pragma unroll
                for (int j = 0; j < 4; ++j) hv[i][j] = 0.f;

            #pragma unroll 4
            for (int d = 0; d < DMODEL; ++d) {
                float4 a = *reinterpret_cast<const float4*>(&xsT[d * 68 + m0]);
                float4 b = *reinterpret_cast<const float4*>(&wbuf[d * 68 + j0]);
                float av[4] = {a.x, a.y, a.z, a.w};
                float bv[4] = {b.x, b.y, b.z, b.w};
                #pragma unroll
                for (int i = 0; i < 4; ++i)
                    #pragma unroll
                    for (int j = 0; j < 4; ++j)
                        hv[i][j] = fmaf(av[i], bv[j], hv[i][j]);
            }

            // ReLU + b1 -> hsT (transposed)
            #pragma unroll
            for (int jj = 0; jj < 4; ++jj) {
                float bb = b1[e * HDIM + h0 + j0 + jj];
                #pragma unroll
                for (int ii = 0; ii < 4; ++ii)
                    hsT[(j0 + jj) * 68 + m0 + ii] = fmaxf(hv[ii][jj] + bb, 0.f);
            }
            __syncthreads();  // hsT ready AND W1 reads done -> reuse wbuf

            #pragma unroll
            for (int i = tid; i < 64 * 128; i += 256) {
                int j = i >> 7, dd = i & 127;
                wbuf[j * 132 + dd] = W2e[(h0 + j) * DMODEL + dd];
            }
            __syncthreads();

            // FC2: acc[m][dd] += h[m][j] * W2[j][dd]
            #pragma unroll 2
            for (int j = 0; j < 64; ++j) {
                float4 a  = *reinterpret_cast<const float4*>(&hsT[j * 68 + m0]);
                float4 c0 = *reinterpret_cast<const float4*>(&wbuf[j * 132 + dd0]);
                float4 c1 = *reinterpret_cast<const float4*>(&wbuf[j * 132 + dd0 + 4]);
                float av[4] = {a.x, a.y, a.z, a.w};
                float bv[8] = {c0.x, c0.y, c0.z, c0.w, c1.x, c1.y, c1.z, c1.w};
                #pragma unroll
                for (int i = 0; i < 4; ++i)
                    #pragma unroll
                    for (int k = 0; k < 8; ++k)
                        acc[i][k] = fmaf(av[i], bv[k], acc[i][k]);
            }
        }

        // epilogue: w * (acc + b2) -> partial[slot]
        float bb2[8];
        #pragma unroll
        for (int k = 0; k < 8; ++k) bb2[k] = b2[e * DMODEL + dd0 + k];

        #pragma unroll
        for (int ii = 0; ii < 4; ++ii) {
            int m = m0 + ii;
            if (m < valid) {
                float w = wsm[m];
                size_t slot = (size_t)(off + m0g + m);
                float4 o0, o1;
                o0.x = w * (acc[ii][0] + bb2[0]);
                o0.y = w * (acc[ii][1] + bb2[1]);
                o0.z = w * (acc[ii][2] + bb2[2]);
                o0.w = w * (acc[ii][3] + bb2[3]);
                o1.x = w * (acc[ii][4] + bb2[4]);
                o1.y = w * (acc[ii][5] + bb2[5]);
                o1.z = w * (acc[ii][6] + bb2[6]);
                o1.w = w * (acc[ii][7] + bb2[7]);
                *reinterpret_cast<float4*>(&g_partial[slot * DMODEL + dd0])     = o0;
                *reinterpret_cast<float4*>(&g_partial[slot * DMODEL + dd0 + 4]) = o1;
            }
        }
    }
}

// ---------------- kernel 6: combine the two expert partials ----------------
__global__ void __launch_bounds__(256) combine_kernel(float* __restrict__ out) {
    int gid = blockIdx.x * 256 + threadIdx.x;   // NTOK*32 threads (float4 each)
    int n = gid >> 5;
    int q = gid & 31;
    int s0 = g_tok_slot[2 * n];
    int s1 = g_tok_slot[2 * n + 1];
    const float4* P = reinterpret_cast<const float4*>(g_partial);
    float4 p0 = P[(size_t)s0 * 32 + q];
    float4 p1 = P[(size_t)s1 * 32 + q];
    float4 o;
    o.x = p0.x + p1.x; o.y = p0.y + p1.y;
    o.z = p0.z + p1.z; o.w = p0.w + p1.w;
    reinterpret_cast<float4*>(out)[(size_t)n * 32 + q] = o;
}

// ---------------- launch ----------------
extern "C" void kernel_launch(void* const* d_in, const int* in_sizes, int n_in,
                              void* d_out, int out_size) {
    const float* x  = (const float*)d_in[0];
    const float* W1 = (const float*)d_in[1];
    const float* b1 = (const float*)d_in[2];
    const float* W2 = (const float*)d_in[3];
    const float* b2 = (const float*)d_in[4];
    const float* Wr = (const float*)d_in[5];
    const float* br = (const float*)d_in[6];
    float* out = (float*)d_out;

    cudaFuncSetAttribute(expert_gemm_kernel,
                         cudaFuncAttributeMaxDynamicSharedMemorySize, SMEM_BYTES);

    init_kernel<<<1, 64>>>();
    router_kernel<<<256, 256>>>(x, Wr, br);
    scan_loss_kernel<<<1, 32>>>(out, out_size);
    scatter_kernel<<<NTOK / 256, 256>>>();
    // max possible tiles = 2N/TM + NEXP = 2080
    expert_gemm_kernel<<<2080, 256, SMEM_BYTES>>>(x, W1, b1, W2, b2);
    combine_kernel<<<(NTOK * 32) / 256, 256>>>(out);
}

// round 3
// speedup vs baseline: 1.9689x; 1.9689x over previous
#include <cuda_runtime.h>
#include <cuda_bf16.h>
#include <math.h>
#include <stdint.h>

#define NTOK   65536
#define DMODEL 128
#define HDIM   256
#define NEXP   32
#define TM     128

// ================= helpers =================
__device__ __forceinline__ uint32_t smem_to_u32(const void* p) {
    uint32_t a;
    asm("{ .reg .u64 t; cvta.to.shared.u64 t, %1; cvt.u32.u64 %0, t; }" : "=r"(a) : "l"(p));
    return a;
}
__device__ __forceinline__ void ldsm4(uint32_t& r0, uint32_t& r1, uint32_t& r2, uint32_t& r3,
                                      uint32_t addr) {
    asm volatile("ldmatrix.sync.aligned.m8n8.x4.shared.b16 {%0,%1,%2,%3}, [%4];"
                 : "=r"(r0), "=r"(r1), "=r"(r2), "=r"(r3) : "r"(addr));
}
__device__ __forceinline__ void mma16816(float* c, uint32_t a0, uint32_t a1, uint32_t a2,
                                         uint32_t a3, uint32_t b0, uint32_t b1) {
    asm volatile("mma.sync.aligned.m16n8k16.row.col.f32.bf16.bf16.f32 "
                 "{%0,%1,%2,%3}, {%4,%5,%6,%7}, {%8,%9}, {%0,%1,%2,%3};"
                 : "+f"(c[0]), "+f"(c[1]), "+f"(c[2]), "+f"(c[3])
                 : "r"(a0), "r"(a1), "r"(a2), "r"(a3), "r"(b0), "r"(b1));
}
__device__ __forceinline__ void split2(float v, __nv_bfloat16& hi, __nv_bfloat16& lo) {
    hi = __float2bfloat16(v);
    lo = __float2bfloat16(v - __bfloat162float(hi));
}
__device__ __forceinline__ uint32_t packbf(__nv_bfloat16 a, __nv_bfloat16 b) {
    __nv_bfloat162 t(a, b);
    return *reinterpret_cast<uint32_t*>(&t);
}

// ================= device scratch =================
__device__ float g_top_v[2 * NTOK];
__device__ int   g_top_e[2 * NTOK];
__device__ float g_importance[NEXP];
__device__ int   g_counts[NEXP];
__device__ int   g_offsets[NEXP + 1];
__device__ int   g_cursor[NEXP];
__device__ int   g_tile_off[NEXP + 1];
__device__ int   g_total_tiles;
__device__ int   g_bucket_tok[2 * NTOK];
__device__ float g_bucket_w[2 * NTOK];
__device__ int   g_tok_slot[2 * NTOK];
__device__ float g_partial[(size_t)2 * NTOK * DMODEL];

__device__ __align__(16) __nv_bfloat16 g_w1hi[NEXP * HDIM * DMODEL];   // [E,H,D]
__device__ __align__(16) __nv_bfloat16 g_w1lo[NEXP * HDIM * DMODEL];
__device__ __align__(16) __nv_bfloat16 g_w2hi[NEXP * DMODEL * HDIM];   // [E,D,H]
__device__ __align__(16) __nv_bfloat16 g_w2lo[NEXP * DMODEL * HDIM];

// ================= kernel: init =================
__global__ void init_kernel() {
    int t = threadIdx.x;
    if (t < NEXP) { g_counts[t] = 0; g_importance[t] = 0.f; }
}

// ================= kernel: convert + transpose weights =================
__global__ void __launch_bounds__(256) convert_w_kernel(const float* __restrict__ W1,
                                                        const float* __restrict__ W2) {
    int idx = blockIdx.x * 256 + threadIdx.x;   // 1,048,576 total
    {   // W1T[e][h][d] = W1[e][d][h]
        int d = idx & 127, h = (idx >> 7) & 255, e = idx >> 15;
        float v = W1[((size_t)e * 128 + d) * 256 + h];
        __nv_bfloat16 hi, lo; split2(v, hi, lo);
        g_w1hi[idx] = hi; g_w1lo[idx] = lo;
    }
    {   // W2T[e][d][h] = W2[e][h][d]
        int h = idx & 255, d = (idx >> 8) & 127, e = idx >> 15;
        float v = W2[((size_t)e * 256 + h) * 128 + d];
        __nv_bfloat16 hi, lo; split2(v, hi, lo);
        g_w2hi[idx] = hi; g_w2lo[idx] = lo;
    }
}

// ================= kernel: router (warp per token) =================
__global__ void __launch_bounds__(256) router_kernel(
    const float* __restrict__ x, const float* __restrict__ Wr,
    const float* __restrict__ br)
{
    __shared__ float wr_s[DMODEL * NEXP];
    __shared__ float imp_s[NEXP];
    __shared__ int   cnt_s[NEXP];

    const int tid = threadIdx.x;
    if (tid < NEXP) { imp_s[tid] = 0.f; cnt_s[tid] = 0; }
    for (int i = tid; i < DMODEL * NEXP; i += 256) wr_s[i] = Wr[i];
    __syncthreads();

    const int lane = tid & 31;
    const int warp = tid >> 5;
    const unsigned FULL = 0xffffffffu;
    const float brv = br[lane];

    for (int n = blockIdx.x * 8 + warp; n < NTOK; n += gridDim.x * 8) {
        float xr[4];
        #pragma unroll
        for (int q = 0; q < 4; ++q) xr[q] = x[(size_t)n * DMODEL + q * 32 + lane];

        float acc = brv;
        #pragma unroll
        for (int d = 0; d < DMODEL; ++d) {
            float xv = __shfl_sync(FULL, xr[d >> 5], d & 31);
            acc = fmaf(xv, wr_s[d * NEXP + lane], acc);
        }
        float mx = acc;
        #pragma unroll
        for (int o = 16; o; o >>= 1) mx = fmaxf(mx, __shfl_xor_sync(FULL, mx, o));
        float p = expf(acc - mx);
        float s = p;
        #pragma unroll
        for (int o = 16; o; o >>= 1) s += __shfl_xor_sync(FULL, s, o);
        float prob = p / s;

        float v = prob; int idx = lane;
        #pragma unroll
        for (int o = 16; o; o >>= 1) {
            float ov = __shfl_xor_sync(FULL, v, o);
            int   oi = __shfl_xor_sync(FULL, idx, o);
            if (ov > v || (ov == v && oi < idx)) { v = ov; idx = oi; }
        }
        int i1 = idx; float v1 = v;

        float v2c = (lane == i1) ? -1e30f : prob;
        v = v2c; idx = lane;
        #pragma unroll
        for (int o = 16; o; o >>= 1) {
            float ov = __shfl_xor_sync(FULL, v, o);
            int   oi = __shfl_xor_sync(FULL, idx, o);
            if (ov > v || (ov == v && oi < idx)) { v = ov; idx = oi; }
        }
        int i2 = idx; float v2 = v;

        if (lane == 0) {
            g_top_e[2 * n]     = i1;  g_top_v[2 * n]     = v1;
            g_top_e[2 * n + 1] = i2;  g_top_v[2 * n + 1] = v2;
            atomicAdd(&imp_s[i1], v1);
            atomicAdd(&imp_s[i2], v2);
            atomicAdd(&cnt_s[i1], 1);
            atomicAdd(&cnt_s[i2], 1);
        }
    }
    __syncthreads();
    if (tid < NEXP) {
        atomicAdd(&g_importance[tid], imp_s[tid]);
        atomicAdd(&g_counts[tid], cnt_s[tid]);
    }
}

// ================= kernel: scan + loss =================
__global__ void scan_loss_kernel(float* __restrict__ out, int out_size) {
    const int lane = threadIdx.x;
    const unsigned FULL = 0xffffffffu;

    int c = g_counts[lane];
    int sc = c;
    #pragma unroll
    for (int o = 1; o < 32; o <<= 1) {
        int v = __shfl_up_sync(FULL, sc, o);
        if (lane >= o) sc += v;
    }
    g_offsets[lane] = sc - c;
    g_cursor[lane]  = sc - c;
    if (lane == 31) g_offsets[NEXP] = sc;

    int nt = (c + TM - 1) / TM;
    int st = nt;
    #pragma unroll
    for (int o = 1; o < 32; o <<= 1) {
        int v = __shfl_up_sync(FULL, st, o);
        if (lane >= o) st += v;
    }
    g_tile_off[lane] = st - nt;
    if (lane == 31) { g_tile_off[NEXP] = st; g_total_tiles = st; }

    float imp = g_importance[lane];
    float s = imp;
    #pragma unroll
    for (int o = 16; o; o >>= 1) s += __shfl_xor_sync(FULL, s, o);
    float mean = s / 32.f;
    float d = imp - mean;
    float ss = d * d;
    #pragma unroll
    for (int o = 16; o; o >>= 1) ss += __shfl_xor_sync(FULL, ss, o);
    float var = ss / 31.f;
    if (lane == 0 && out_size > NTOK * DMODEL)
        out[NTOK * DMODEL] = var / (mean * mean + 1e-9f);
}

// ================= kernel: scatter =================
__global__ void __launch_bounds__(256) scatter_kernel() {
    __shared__ int lcnt[NEXP];
    __shared__ int gbase[NEXP];
    __shared__ int lcur[NEXP];

    const int tid = threadIdx.x;
    const int n = blockIdx.x * 256 + tid;
    if (tid < NEXP) lcnt[tid] = 0;
    __syncthreads();

    int e0 = g_top_e[2 * n];     float v0 = g_top_v[2 * n];
    int e1 = g_top_e[2 * n + 1]; float v1 = g_top_v[2 * n + 1];
    atomicAdd(&lcnt[e0], 1);
    atomicAdd(&lcnt[e1], 1);
    __syncthreads();

    if (tid < NEXP) { gbase[tid] = atomicAdd(&g_cursor[tid], lcnt[tid]); lcur[tid] = 0; }
    __syncthreads();

    int p0 = gbase[e0] + atomicAdd(&lcur[e0], 1);
    g_bucket_tok[p0] = n; g_bucket_w[p0] = v0; g_tok_slot[2 * n] = p0;
    int p1 = gbase[e1] + atomicAdd(&lcur[e1], 1);
    g_bucket_tok[p1] = n; g_bucket_w[p1] = v1; g_tok_slot[2 * n + 1] = p1;
}

// ================= kernel: grouped expert GEMM (HMMA split-bf16) =================
// padded bf16 tiles: stride 136 elements (272 B) -> conflict-free ldmatrix
#define SX   136
#define ROWB (SX * 2)
#define O_XH 0
#define O_XL (128 * ROWB)
#define O_BH (2 * 128 * ROWB)
#define O_BL (3 * 128 * ROWB)
#define O_CH (4 * 128 * ROWB)
#define O_CL (5 * 128 * ROWB)
#define O_TOK (6 * 128 * ROWB)            // 208896
#define O_WSM (O_TOK + 512)
#define O_B1  (O_TOK + 1024)
#define O_B2  (O_TOK + 2048)
#define SMEM_DYN (O_TOK + 2560)           // 211456 bytes

__global__ void __launch_bounds__(256, 1) expert_mma_kernel(
    const float* __restrict__ x, const float* __restrict__ b1,
    const float* __restrict__ b2)
{
    const int t = blockIdx.x;
    if (t >= g_total_tiles) return;

    extern __shared__ char smp[];
    const uint32_t sbase = smem_to_u32(smp);
    int*   toks_s = (int*)(smp + O_TOK);
    float* wsm_s  = (float*)(smp + O_WSM);
    float* b1s    = (float*)(smp + O_B1);
    float* b2s    = (float*)(smp + O_B2);

    const int tid = threadIdx.x;
    const int wid = tid >> 5;
    const int lane = tid & 31;

    // locate expert / tile
    int e = 0;
    #pragma unroll 1
    while (t >= g_tile_off[e + 1]) ++e;
    const int mtile = t - g_tile_off[e];
    const int off   = g_offsets[e];
    const int cnt   = g_counts[e];
    const int m0g   = mtile * TM;
    const int valid = min(TM, cnt - m0g);

    if (tid < 128) {
        if (tid < valid) {
            toks_s[tid] = g_bucket_tok[off + m0g + tid];
            wsm_s[tid]  = g_bucket_w[off + m0g + tid];
        } else { toks_s[tid] = 0; wsm_s[tid] = 0.f; }
        b2s[tid] = b2[e * DMODEL + tid];
    }
    b1s[tid] = b1[e * HDIM + tid];
    __syncthreads();

    // gather X rows -> split bf16 hi/lo into smem
    #pragma unroll 2
    for (int i = tid; i < 2048; i += 256) {
        int r = i >> 4, ch = i & 15;
        uint4 vh, vl;
        if (r < valid) {
            const float* src = x + (size_t)toks_s[r] * DMODEL + ch * 8;
            float4 a = *reinterpret_cast<const float4*>(src);
            float4 b = *reinterpret_cast<const float4*>(src + 4);
            float f[8] = {a.x, a.y, a.z, a.w, b.x, b.y, b.z, b.w};
            __nv_bfloat16 hi[8], lo[8];
            #pragma unroll
            for (int q = 0; q < 8; ++q) split2(f[q], hi[q], lo[q]);
            vh = make_uint4(packbf(hi[0],hi[1]), packbf(hi[2],hi[3]),
                            packbf(hi[4],hi[5]), packbf(hi[6],hi[7]));
            vl = make_uint4(packbf(lo[0],lo[1]), packbf(lo[2],lo[3]),
                            packbf(lo[4],lo[5]), packbf(lo[6],lo[7]));
        } else { vh = make_uint4(0,0,0,0); vl = vh; }
        int dst = r * ROWB + ch * 16;
        *reinterpret_cast<uint4*>(smp + O_XH + dst) = vh;
        *reinterpret_cast<uint4*>(smp + O_XL + dst) = vl;
    }

    const int m0 = wid * 16;
    const size_t w1base = (size_t)e * HDIM * DMODEL;
    const size_t w2base = (size_t)e * DMODEL * HDIM;

    // ldmatrix lane address components
    const uint32_t arow  = m0 + (lane & 15);
    const uint32_t acolb = ((lane >> 4) & 1) * 16;           // byte offset within k16 step
    const uint32_t brow  = ((lane >> 4) & 1) * 8 + (lane & 7);
    const uint32_t bcolb = ((lane >> 3) & 1) * 16;

    float acc2[16][4];
    #pragma unroll
    for (int j = 0; j < 16; ++j)
        #pragma unroll
        for (int q = 0; q < 4; ++q) acc2[j][q] = 0.f;

    #pragma unroll 1
    for (int c = 0; c < 2; ++c) {
        __syncthreads();   // X gather done (c=0) / bufB+bufC free (c=1)

        // load W1T chunk [128 h][128 d] hi/lo -> bufB
        #pragma unroll 2
        for (int i = tid; i < 2048; i += 256) {
            int r = i >> 4, ch = i & 15;
            int dst = r * ROWB + ch * 16;
            size_t src = w1base + (size_t)(c * 128 + r) * DMODEL + ch * 8;
            *reinterpret_cast<uint4*>(smp + O_BH + dst) =
                *reinterpret_cast<const uint4*>(g_w1hi + src);
            *reinterpret_cast<uint4*>(smp + O_BL + dst) =
                *reinterpret_cast<const uint4*>(g_w1lo + src);
        }
        __syncthreads();

        // ---- FC1: acc1[16 jt][4] = X[m0..m0+15][:] @ W1chunk^T ----
        float acc1[16][4];
        #pragma unroll
        for (int j = 0; j < 16; ++j)
            #pragma unroll
            for (int q = 0; q < 4; ++q) acc1[j][q] = 0.f;

        #pragma unroll 1
        for (int k = 0; k < 8; ++k) {
            uint32_t aaddr = sbase + O_XH + arow * ROWB + k * 32 + acolb;
            uint32_t ah0, ah1, ah2, ah3, al0, al1, al2, al3;
            ldsm4(ah0, ah1, ah2, ah3, aaddr);
            ldsm4(al0, al1, al2, al3, aaddr + (O_XL - O_XH));
            #pragma unroll
            for (int jp = 0; jp < 8; ++jp) {
                uint32_t baddr = sbase + O_BH + (jp * 16 + brow) * ROWB + k * 32 + bcolb;
                uint32_t bh0, bh1, bh2, bh3, bl0, bl1, bl2, bl3;
                ldsm4(bh0, bh1, bh2, bh3, baddr);
                ldsm4(bl0, bl1, bl2, bl3, baddr + (O_BL - O_BH));
                mma16816(acc1[2*jp],   ah0, ah1, ah2, ah3, bh0, bh1);
                mma16816(acc1[2*jp],   ah0, ah1, ah2, ah3, bl0, bl1);
                mma16816(acc1[2*jp],   al0, al1, al2, al3, bh0, bh1);
                mma16816(acc1[2*jp+1], ah0, ah1, ah2, ah3, bh2, bh3);
                mma16816(acc1[2*jp+1], ah0, ah1, ah2, ah3, bl2, bl3);
                mma16816(acc1[2*jp+1], al0, al1, al2, al3, bh2, bh3);
            }
        }

        // ---- epilogue 1: relu(acc1 + b1) -> split hi/lo into bufC ----
        {
            const int r0 = m0 + (lane >> 2);
            const int cb = (lane & 3) * 2;
            #pragma unroll
            for (int jt = 0; jt < 16; ++jt) {
                int colg = c * 128 + jt * 8 + cb;
                int coll = jt * 8 + cb;
                float bb0 = b1s[colg], bb1 = b1s[colg + 1];
                float f0 = fmaxf(acc1[jt][0] + bb0, 0.f);
                float f1 = fmaxf(acc1[jt][1] + bb1, 0.f);
                float f2 = fmaxf(acc1[jt][2] + bb0, 0.f);
                float f3 = fmaxf(acc1[jt][3] + bb1, 0.f);
                __nv_bfloat16 h0,l0,h1,l1,h2,l2,h3,l3;
                split2(f0,h0,l0); split2(f1,h1,l1); split2(f2,h2,l2); split2(f3,h3,l3);
                int d0 = r0 * ROWB + coll * 2;
                int d1 = (r0 + 8) * ROWB + coll * 2;
                *reinterpret_cast<uint32_t*>(smp + O_CH + d0) = packbf(h0, h1);
                *reinterpret_cast<uint32_t*>(smp + O_CL + d0) = packbf(l0, l1);
                *reinterpret_cast<uint32_t*>(smp + O_CH + d1) = packbf(h2, h3);
                *reinterpret_cast<uint32_t*>(smp + O_CL + d1) = packbf(l2, l3);
            }
        }
        __syncthreads();   // FC1 done reading bufB; h writes visible

        // load W2T chunk [128 d][128 h-slice] hi/lo -> bufB
        #pragma unroll 2
        for (int i = tid; i < 2048; i += 256) {
            int r = i >> 4, ch = i & 15;
            int dst = r * ROWB + ch * 16;
            size_t src = w2base + (size_t)r * HDIM + c * 128 + ch * 8;
            *reinterpret_cast<uint4*>(smp + O_BH + dst) =
                *reinterpret_cast<const uint4*>(g_w2hi + src);
            *reinterpret_cast<uint4*>(smp + O_BL + dst) =
                *reinterpret_cast<const uint4*>(g_w2lo + src);
        }
        __syncthreads();

        // ---- FC2: acc2 += h[m0..][kchunk] @ W2chunk^T ----
        #pragma unroll 1
        for (int k = 0; k < 8; ++k) {
            uint32_t aaddr = sbase + O_CH + arow * ROWB + k * 32 + acolb;
            uint32_t ah0, ah1, ah2, ah3, al0, al1, al2, al3;
            ldsm4(ah0, ah1, ah2, ah3, aaddr);
            ldsm4(al0, al1, al2, al3, aaddr + (O_CL - O_CH));
            #pragma unroll
            for (int jp = 0; jp < 8; ++jp) {
                uint32_t baddr = sbase + O_BH + (jp * 16 + brow) * ROWB + k * 32 + bcolb;
                uint32_t bh0, bh1, bh2, bh3, bl0, bl1, bl2, bl3;
                ldsm4(bh0, bh1, bh2, bh3, baddr);
                ldsm4(bl0, bl1, bl2, bl3, baddr + (O_BL - O_BH));
                mma16816(acc2[2*jp],   ah0, ah1, ah2, ah3, bh0, bh1);
                mma16816(acc2[2*jp],   ah0, ah1, ah2, ah3, bl0, bl1);
                mma16816(acc2[2*jp],   al0, al1, al2, al3, bh0, bh1);
                mma16816(acc2[2*jp+1], ah0, ah1, ah2, ah3, bh2, bh3);
                mma16816(acc2[2*jp+1], ah0, ah1, ah2, ah3, bl2, bl3);
                mma16816(acc2[2*jp+1], al0, al1, al2, al3, bh2, bh3);
            }
        }
    }

    // ---- epilogue 2: w * (acc2 + b2) -> g_partial ----
    {
        const int r0 = m0 + (lane >> 2);
        const int r1 = r0 + 8;
        const int cb = (lane & 3) * 2;
        const float w0 = (r0 < valid) ? wsm_s[r0] : 0.f;
        const float w1 = (r1 < valid) ? wsm_s[r1] : 0.f;
        const size_t s0 = (size_t)(off + m0g + r0) * DMODEL;
        const size_t s1 = (size_t)(off + m0g + r1) * DMODEL;
        #pragma unroll
        for (int jt = 0; jt < 16; ++jt) {
            int col = jt * 8 + cb;
            float bb0 = b2s[col], bb1 = b2s[col + 1];
            if (r0 < valid) {
                float2 o;
                o.x = w0 * (acc2[jt][0] + bb0);
                o.y = w0 * (acc2[jt][1] + bb1);
                *reinterpret_cast<float2*>(&g_partial[s0 + col]) = o;
            }
            if (r1 < valid) {
                float2 o;
                o.x = w1 * (acc2[jt][2] + bb0);
                o.y = w1 * (acc2[jt][3] + bb1);
                *reinterpret_cast<float2*>(&g_partial[s1 + col]) = o;
            }
        }
    }
}

// ================= kernel: combine =================
__global__ void __launch_bounds__(256) combine_kernel(float* __restrict__ out) {
    int gid = blockIdx.x * 256 + threadIdx.x;
    int n = gid >> 5;
    int q = gid & 31;
    int s0 = g_tok_slot[2 * n];
    int s1 = g_tok_slot[2 * n + 1];
    const float4* P = reinterpret_cast<const float4*>(g_partial);
    float4 p0 = P[(size_t)s0 * 32 + q];
    float4 p1 = P[(size_t)s1 * 32 + q];
    float4 o;
    o.x = p0.x + p1.x; o.y = p0.y + p1.y;
    o.z = p0.z + p1.z; o.w = p0.w + p1.w;
    reinterpret_cast<float4*>(out)[(size_t)n * 32 + q] = o;
}

// ================= launch =================
extern "C" void kernel_launch(void* const* d_in, const int* in_sizes, int n_in,
                              void* d_out, int out_size) {
    const float* x  = (const float*)d_in[0];
    const float* W1 = (const float*)d_in[1];
    const float* b1 = (const float*)d_in[2];
    const float* W2 = (const float*)d_in[3];
    const float* b2 = (const float*)d_in[4];
    const float* Wr = (const float*)d_in[5];
    const float* br = (const float*)d_in[6];
    float* out = (float*)d_out;

    cudaFuncSetAttribute(expert_mma_kernel,
                         cudaFuncAttributeMaxDynamicSharedMemorySize, SMEM_DYN);

    init_kernel<<<1, 64>>>();
    convert_w_kernel<<<NEXP * HDIM * DMODEL / 256, 256>>>(W1, W2);
    router_kernel<<<256, 256>>>(x, Wr, br);
    scan_loss_kernel<<<1, 32>>>(out, out_size);
    scatter_kernel<<<NTOK / 256, 256>>>();
    // max tiles = 2N/TM + NEXP = 1024 + 32
    expert_mma_kernel<<<1056, 256, SMEM_DYN>>>(x, b1, b2);
    combine_kernel<<<(NTOK * 32) / 256, 256>>>(out);
}

// round 4
// speedup vs baseline: 2.1822x; 1.1084x over previous
#include <cuda_runtime.h>
#include <cuda_bf16.h>
#include <math.h>
#include <stdint.h>

#define NTOK   65536
#define DMODEL 128
#define HDIM   256
#define NEXP   32
#define TM     128

// ================= helpers =================
__device__ __forceinline__ uint32_t smem_to_u32(const void* p) {
    uint32_t a;
    asm("{ .reg .u64 t; cvta.to.shared.u64 t, %1; cvt.u32.u64 %0, t; }" : "=r"(a) : "l"(p));
    return a;
}
__device__ __forceinline__ void ldsm4(uint32_t& r0, uint32_t& r1, uint32_t& r2, uint32_t& r3,
                                      uint32_t addr) {
    asm volatile("ldmatrix.sync.aligned.m8n8.x4.shared.b16 {%0,%1,%2,%3}, [%4];"
                 : "=r"(r0), "=r"(r1), "=r"(r2), "=r"(r3) : "r"(addr));
}
__device__ __forceinline__ void mma16816(float* c, uint32_t a0, uint32_t a1, uint32_t a2,
                                         uint32_t a3, uint32_t b0, uint32_t b1) {
    asm volatile("mma.sync.aligned.m16n8k16.row.col.f32.bf16.bf16.f32 "
                 "{%0,%1,%2,%3}, {%4,%5,%6,%7}, {%8,%9}, {%0,%1,%2,%3};"
                 : "+f"(c[0]), "+f"(c[1]), "+f"(c[2]), "+f"(c[3])
                 : "r"(a0), "r"(a1), "r"(a2), "r"(a3), "r"(b0), "r"(b1));
}
__device__ __forceinline__ void cp16(uint32_t dst, const void* src) {
    asm volatile("cp.async.cg.shared.global [%0], [%1], 16;" :: "r"(dst), "l"(src) : "memory");
}
#define CP_COMMIT() asm volatile("cp.async.commit_group;" ::: "memory")
#define CP_WAIT0()  asm volatile("cp.async.wait_group 0;" ::: "memory")

__device__ __forceinline__ void split2(float v, __nv_bfloat16& hi, __nv_bfloat16& lo) {
    hi = __float2bfloat16(v);
    lo = __float2bfloat16(v - __bfloat162float(hi));
}
__device__ __forceinline__ uint32_t packbf(__nv_bfloat16 a, __nv_bfloat16 b) {
    __nv_bfloat162 t(a, b);
    return *reinterpret_cast<uint32_t*>(&t);
}

// ================= device scratch =================
__device__ float g_top_v[2 * NTOK];
__device__ int   g_top_e[2 * NTOK];
__device__ float g_importance[NEXP];
__device__ int   g_counts[NEXP];
__device__ int   g_offsets[NEXP + 1];
__device__ int   g_cursor[NEXP];
__device__ int   g_tile_off[NEXP + 1];
__device__ int   g_total_tiles;
__device__ int   g_bucket_tok[2 * NTOK];
__device__ float g_bucket_w[2 * NTOK];
__device__ int   g_tok_slot[2 * NTOK];
__device__ float g_partial[(size_t)2 * NTOK * DMODEL];

__device__ __align__(16) __nv_bfloat16 g_xhi[NTOK * DMODEL];
__device__ __align__(16) __nv_bfloat16 g_xlo[NTOK * DMODEL];
__device__ __align__(16) __nv_bfloat16 g_w1hi[NEXP * HDIM * DMODEL];   // [E,H,D]
__device__ __align__(16) __nv_bfloat16 g_w1lo[NEXP * HDIM * DMODEL];
__device__ __align__(16) __nv_bfloat16 g_w2hi[NEXP * DMODEL * HDIM];   // [E,D,H]
__device__ __align__(16) __nv_bfloat16 g_w2lo[NEXP * DMODEL * HDIM];

// ================= kernel: init =================
__global__ void init_kernel() {
    int t = threadIdx.x;
    if (t < NEXP) { g_counts[t] = 0; g_importance[t] = 0.f; }
}

// ================= kernel: convert x -> bf16 hi/lo =================
__global__ void __launch_bounds__(256) convert_x_kernel(const float* __restrict__ x) {
    size_t i = ((size_t)blockIdx.x * 256 + threadIdx.x) * 8;
    float4 a = *reinterpret_cast<const float4*>(x + i);
    float4 b = *reinterpret_cast<const float4*>(x + i + 4);
    float v[8] = {a.x, a.y, a.z, a.w, b.x, b.y, b.z, b.w};
    __nv_bfloat16 hi[8], lo[8];
    #pragma unroll
    for (int q = 0; q < 8; ++q) split2(v[q], hi[q], lo[q]);
    uint4 ph, pl;
    ph.x = packbf(hi[0], hi[1]); ph.y = packbf(hi[2], hi[3]);
    ph.z = packbf(hi[4], hi[5]); ph.w = packbf(hi[6], hi[7]);
    pl.x = packbf(lo[0], lo[1]); pl.y = packbf(lo[2], lo[3]);
    pl.z = packbf(lo[4], lo[5]); pl.w = packbf(lo[6], lo[7]);
    *reinterpret_cast<uint4*>(g_xhi + i) = ph;
    *reinterpret_cast<uint4*>(g_xlo + i) = pl;
}

// ================= kernel: convert + transpose weights =================
__global__ void __launch_bounds__(256) convert_w_kernel(const float* __restrict__ W1,
                                                        const float* __restrict__ W2) {
    int idx = blockIdx.x * 256 + threadIdx.x;
    {   // W1T[e][h][d] = W1[e][d][h]
        int d = idx & 127, h = (idx >> 7) & 255, e = idx >> 15;
        float v = W1[((size_t)e * 128 + d) * 256 + h];
        __nv_bfloat16 hi, lo; split2(v, hi, lo);
        g_w1hi[idx] = hi; g_w1lo[idx] = lo;
    }
    {   // W2T[e][d][h] = W2[e][h][d]
        int h = idx & 255, d = (idx >> 8) & 127, e = idx >> 15;
        float v = W2[((size_t)e * 256 + h) * 128 + d];
        __nv_bfloat16 hi, lo; split2(v, hi, lo);
        g_w2hi[idx] = hi; g_w2lo[idx] = lo;
    }
}

// ================= kernel: router (warp per token) =================
__global__ void __launch_bounds__(256) router_kernel(
    const float* __restrict__ x, const float* __restrict__ Wr,
    const float* __restrict__ br)
{
    __shared__ float wr_s[DMODEL * NEXP];
    __shared__ float imp_s[NEXP];
    __shared__ int   cnt_s[NEXP];

    const int tid = threadIdx.x;
    if (tid < NEXP) { imp_s[tid] = 0.f; cnt_s[tid] = 0; }
    for (int i = tid; i < DMODEL * NEXP; i += 256) wr_s[i] = Wr[i];
    __syncthreads();

    const int lane = tid & 31;
    const int warp = tid >> 5;
    const unsigned FULL = 0xffffffffu;
    const float brv = br[lane];

    for (int n = blockIdx.x * 8 + warp; n < NTOK; n += gridDim.x * 8) {
        float xr[4];
        #pragma unroll
        for (int q = 0; q < 4; ++q) xr[q] = x[(size_t)n * DMODEL + q * 32 + lane];

        float acc = brv;
        #pragma unroll
        for (int d = 0; d < DMODEL; ++d) {
            float xv = __shfl_sync(FULL, xr[d >> 5], d & 31);
            acc = fmaf(xv, wr_s[d * NEXP + lane], acc);
        }
        float mx = acc;
        #pragma unroll
        for (int o = 16; o; o >>= 1) mx = fmaxf(mx, __shfl_xor_sync(FULL, mx, o));
        float p = expf(acc - mx);
        float s = p;
        #pragma unroll
        for (int o = 16; o; o >>= 1) s += __shfl_xor_sync(FULL, s, o);
        float prob = p / s;

        float v = prob; int idx = lane;
        #pragma unroll
        for (int o = 16; o; o >>= 1) {
            float ov = __shfl_xor_sync(FULL, v, o);
            int   oi = __shfl_xor_sync(FULL, idx, o);
            if (ov > v || (ov == v && oi < idx)) { v = ov; idx = oi; }
        }
        int i1 = idx; float v1 = v;

        float v2c = (lane == i1) ? -1e30f : prob;
        v = v2c; idx = lane;
        #pragma unroll
        for (int o = 16; o; o >>= 1) {
            float ov = __shfl_xor_sync(FULL, v, o);
            int   oi = __shfl_xor_sync(FULL, idx, o);
            if (ov > v || (ov == v && oi < idx)) { v = ov; idx = oi; }
        }
        int i2 = idx; float v2 = v;

        if (lane == 0) {
            g_top_e[2 * n]     = i1;  g_top_v[2 * n]     = v1;
            g_top_e[2 * n + 1] = i2;  g_top_v[2 * n + 1] = v2;
            atomicAdd(&imp_s[i1], v1);
            atomicAdd(&imp_s[i2], v2);
            atomicAdd(&cnt_s[i1], 1);
            atomicAdd(&cnt_s[i2], 1);
        }
    }
    __syncthreads();
    if (tid < NEXP) {
        atomicAdd(&g_importance[tid], imp_s[tid]);
        atomicAdd(&g_counts[tid], cnt_s[tid]);
    }
}

// ================= kernel: scan + loss =================
__global__ void scan_loss_kernel(float* __restrict__ out, int out_size) {
    const int lane = threadIdx.x;
    const unsigned FULL = 0xffffffffu;

    int c = g_counts[lane];
    int sc = c;
    #pragma unroll
    for (int o = 1; o < 32; o <<= 1) {
        int v = __shfl_up_sync(FULL, sc, o);
        if (lane >= o) sc += v;
    }
    g_offsets[lane] = sc - c;
    g_cursor[lane]  = sc - c;
    if (lane == 31) g_offsets[NEXP] = sc;

    int nt = (c + TM - 1) / TM;
    int st = nt;
    #pragma unroll
    for (int o = 1; o < 32; o <<= 1) {
        int v = __shfl_up_sync(FULL, st, o);
        if (lane >= o) st += v;
    }
    g_tile_off[lane] = st - nt;
    if (lane == 31) { g_tile_off[NEXP] = st; g_total_tiles = st; }

    float imp = g_importance[lane];
    float s = imp;
    #pragma unroll
    for (int o = 16; o; o >>= 1) s += __shfl_xor_sync(FULL, s, o);
    float mean = s / 32.f;
    float d = imp - mean;
    float ss = d * d;
    #pragma unroll
    for (int o = 16; o; o >>= 1) ss += __shfl_xor_sync(FULL, ss, o);
    float var = ss / 31.f;
    if (lane == 0 && out_size > NTOK * DMODEL)
        out[NTOK * DMODEL] = var / (mean * mean + 1e-9f);
}

// ================= kernel: scatter =================
__global__ void __launch_bounds__(256) scatter_kernel() {
    __shared__ int lcnt[NEXP];
    __shared__ int gbase[NEXP];
    __shared__ int lcur[NEXP];

    const int tid = threadIdx.x;
    const int n = blockIdx.x * 256 + tid;
    if (tid < NEXP) lcnt[tid] = 0;
    __syncthreads();

    int e0 = g_top_e[2 * n];     float v0 = g_top_v[2 * n];
    int e1 = g_top_e[2 * n + 1]; float v1 = g_top_v[2 * n + 1];
    atomicAdd(&lcnt[e0], 1);
    atomicAdd(&lcnt[e1], 1);
    __syncthreads();

    if (tid < NEXP) { gbase[tid] = atomicAdd(&g_cursor[tid], lcnt[tid]); lcur[tid] = 0; }
    __syncthreads();

    int p0 = gbase[e0] + atomicAdd(&lcur[e0], 1);
    g_bucket_tok[p0] = n; g_bucket_w[p0] = v0; g_tok_slot[2 * n] = p0;
    int p1 = gbase[e1] + atomicAdd(&lcur[e1], 1);
    g_bucket_tok[p1] = n; g_bucket_w[p1] = v1; g_tok_slot[2 * n + 1] = p1;
}

// ================= kernel: grouped expert GEMM (HMMA split-bf16, 512 thr, cp.async) =================
#define SX   136
#define ROWB (SX * 2)
#define O_XH 0
#define O_XL (128 * ROWB)
#define O_BH (2 * 128 * ROWB)
#define O_BL (3 * 128 * ROWB)
#define O_CH (4 * 128 * ROWB)
#define O_CL (5 * 128 * ROWB)
#define O_TOK (6 * 128 * ROWB)            // 208896
#define O_WSM (O_TOK + 512)
#define O_B1  (O_TOK + 1024)
#define O_B2  (O_TOK + 2048)
#define SMEM_DYN (O_TOK + 2560)           // 211456 bytes

#define NTHR 512

__global__ void __launch_bounds__(NTHR, 1) expert_mma_kernel(
    const float* __restrict__ b1, const float* __restrict__ b2)
{
    const int t = blockIdx.x;
    if (t >= g_total_tiles) return;

    extern __shared__ char smp[];
    const uint32_t sbase = smem_to_u32(smp);
    int*   toks_s = (int*)(smp + O_TOK);
    float* wsm_s  = (float*)(smp + O_WSM);
    float* b1s    = (float*)(smp + O_B1);
    float* b2s    = (float*)(smp + O_B2);

    const int tid = threadIdx.x;
    const int wid = tid >> 5;
    const int lane = tid & 31;

    // locate expert / tile
    int e = 0;
    #pragma unroll 1
    while (t >= g_tile_off[e + 1]) ++e;
    const int mtile = t - g_tile_off[e];
    const int off   = g_offsets[e];
    const int cnt   = g_counts[e];
    const int m0g   = mtile * TM;
    const int valid = min(TM, cnt - m0g);

    if (tid < 128) {
        if (tid < valid) {
            toks_s[tid] = g_bucket_tok[off + m0g + tid];
            wsm_s[tid]  = g_bucket_w[off + m0g + tid];
        } else { toks_s[tid] = 0; wsm_s[tid] = 0.f; }
        b2s[tid] = b2[e * DMODEL + tid];
    }
    if (tid < 256) b1s[tid] = b1[e * HDIM + tid];
    __syncthreads();   // toks visible for gather

    // ---- async gather X rows (bf16 hi/lo) ----
    #pragma unroll
    for (int i = tid; i < 2048; i += NTHR) {
        int r = i >> 4, ch = i & 15;
        const size_t src = (size_t)toks_s[r] * DMODEL + ch * 8;
        uint32_t dst = sbase + r * ROWB + ch * 16;
        cp16(dst + O_XH, g_xhi + src);
        cp16(dst + O_XL, g_xlo + src);
    }
    CP_COMMIT();

    const size_t w1base = (size_t)e * HDIM * DMODEL;
    const size_t w2base = (size_t)e * DMODEL * HDIM;

    // ---- async load W1 chunk 0 ----
    #pragma unroll
    for (int i = tid; i < 2048; i += NTHR) {
        int r = i >> 4, ch = i & 15;
        size_t src = w1base + (size_t)r * DMODEL + ch * 8;
        uint32_t dst = sbase + r * ROWB + ch * 16;
        cp16(dst + O_BH, g_w1hi + src);
        cp16(dst + O_BL, g_w1lo + src);
    }
    CP_COMMIT();
    CP_WAIT0();
    __syncthreads();

    // warp tiling: 8 m-warps x 2 n-warps
    const int m0 = (wid >> 1) * 16;
    const int nw = wid & 1;
    const uint32_t arow  = m0 + (lane & 15);
    const uint32_t acolb = ((lane >> 4) & 1) * 16;
    const uint32_t brow0 = nw * 64 + ((lane >> 4) & 1) * 8 + (lane & 7);
    const uint32_t bcolb = ((lane >> 3) & 1) * 16;

    float acc2[8][4];
    #pragma unroll
    for (int j = 0; j < 8; ++j)
        #pragma unroll
        for (int q = 0; q < 4; ++q) acc2[j][q] = 0.f;

    #pragma unroll 1
    for (int c = 0; c < 2; ++c) {
        // ---- FC1: acc1 = X @ W1chunk^T (m16 x n64 per warp) ----
        float acc1[8][4];
        #pragma unroll
        for (int j = 0; j < 8; ++j)
            #pragma unroll
            for (int q = 0; q < 4; ++q) acc1[j][q] = 0.f;

        #pragma unroll 1
        for (int k = 0; k < 8; ++k) {
            uint32_t aaddr = sbase + O_XH + arow * ROWB + k * 32 + acolb;
            uint32_t ah0, ah1, ah2, ah3, al0, al1, al2, al3;
            ldsm4(ah0, ah1, ah2, ah3, aaddr);
            ldsm4(al0, al1, al2, al3, aaddr + (O_XL - O_XH));
            #pragma unroll
            for (int jp = 0; jp < 4; ++jp) {
                uint32_t baddr = sbase + O_BH + (brow0 + jp * 16) * ROWB + k * 32 + bcolb;
                uint32_t bh0, bh1, bh2, bh3, bl0, bl1, bl2, bl3;
                ldsm4(bh0, bh1, bh2, bh3, baddr);
                ldsm4(bl0, bl1, bl2, bl3, baddr + (O_BL - O_BH));
                mma16816(acc1[2*jp],   ah0, ah1, ah2, ah3, bh0, bh1);
                mma16816(acc1[2*jp],   ah0, ah1, ah2, ah3, bl0, bl1);
                mma16816(acc1[2*jp],   al0, al1, al2, al3, bh0, bh1);
                mma16816(acc1[2*jp+1], ah0, ah1, ah2, ah3, bh2, bh3);
                mma16816(acc1[2*jp+1], ah0, ah1, ah2, ah3, bl2, bl3);
                mma16816(acc1[2*jp+1], al0, al1, al2, al3, bh2, bh3);
            }
        }
        __syncthreads();   // all warps done reading B (W1 chunk)

        // ---- prefetch W2 chunk c into B (overlaps epilogue 1) ----
        #pragma unroll
        for (int i = tid; i < 2048; i += NTHR) {
            int r = i >> 4, ch = i & 15;
            size_t src = w2base + (size_t)r * HDIM + c * 128 + ch * 8;
            uint32_t dst = sbase + r * ROWB + ch * 16;
            cp16(dst + O_BH, g_w2hi + src);
            cp16(dst + O_BL, g_w2lo + src);
        }
        CP_COMMIT();

        // ---- epilogue 1: relu(acc1 + b1) -> split hi/lo into C ----
        {
            const int r0 = m0 + (lane >> 2);
            const int cb = (lane & 3) * 2;
            #pragma unroll
            for (int jt = 0; jt < 8; ++jt) {
                int coll = (nw * 8 + jt) * 8 + cb;
                int colg = c * 128 + coll;
                float bb0 = b1s[colg], bb1 = b1s[colg + 1];
                float f0 = fmaxf(acc1[jt][0] + bb0, 0.f);
                float f1 = fmaxf(acc1[jt][1] + bb1, 0.f);
                float f2 = fmaxf(acc1[jt][2] + bb0, 0.f);
                float f3 = fmaxf(acc1[jt][3] + bb1, 0.f);
                __nv_bfloat16 h0,l0,h1,l1,h2,l2,h3,l3;
                split2(f0,h0,l0); split2(f1,h1,l1); split2(f2,h2,l2); split2(f3,h3,l3);
                int d0 = r0 * ROWB + coll * 2;
                int d1 = (r0 + 8) * ROWB + coll * 2;
                *reinterpret_cast<uint32_t*>(smp + O_CH + d0) = packbf(h0, h1);
                *reinterpret_cast<uint32_t*>(smp + O_CL + d0) = packbf(l0, l1);
                *reinterpret_cast<uint32_t*>(smp + O_CH + d1) = packbf(h2, h3);
                *reinterpret_cast<uint32_t*>(smp + O_CL + d1) = packbf(l2, l3);
            }
        }
        CP_WAIT0();
        __syncthreads();   // W2 chunk ready, h visible

        // ---- FC2: acc2 += h_chunk @ W2chunk^T ----
        #pragma unroll 1
        for (int k = 0; k < 8; ++k) {
            uint32_t aaddr = sbase + O_CH + arow * ROWB + k * 32 + acolb;
            uint32_t ah0, ah1, ah2, ah3, al0, al1, al2, al3;
            ldsm4(ah0, ah1, ah2, ah3, aaddr);
            ldsm4(al0, al1, al2, al3, aaddr + (O_CL - O_CH));
            #pragma unroll
            for (int jp = 0; jp < 4; ++jp) {
                uint32_t baddr = sbase + O_BH + (brow0 + jp * 16) * ROWB + k * 32 + bcolb;
                uint32_t bh0, bh1, bh2, bh3, bl0, bl1, bl2, bl3;
                ldsm4(bh0, bh1, bh2, bh3, baddr);
                ldsm4(bl0, bl1, bl2, bl3, baddr + (O_BL - O_BH));
                mma16816(acc2[2*jp],   ah0, ah1, ah2, ah3, bh0, bh1);
                mma16816(acc2[2*jp],   ah0, ah1, ah2, ah3, bl0, bl1);
                mma16816(acc2[2*jp],   al0, al1, al2, al3, bh0, bh1);
                mma16816(acc2[2*jp+1], ah0, ah1, ah2, ah3, bh2, bh3);
                mma16816(acc2[2*jp+1], ah0, ah1, ah2, ah3, bl2, bl3);
                mma16816(acc2[2*jp+1], al0, al1, al2, al3, bh2, bh3);
            }
        }
        __syncthreads();   // done reading B & C

        // ---- prefetch W1 chunk 1 into B ----
        if (c == 0) {
            #pragma unroll
            for (int i = tid; i < 2048; i += NTHR) {
                int r = i >> 4, ch = i & 15;
                size_t src = w1base + (size_t)(128 + r) * DMODEL + ch * 8;
                uint32_t dst = sbase + r * ROWB + ch * 16;
                cp16(dst + O_BH, g_w1hi + src);
                cp16(dst + O_BL, g_w1lo + src);
            }
            CP_COMMIT();
            CP_WAIT0();
            __syncthreads();
        }
    }

    // ---- epilogue 2: w * (acc2 + b2) -> g_partial ----
    {
        const int r0 = m0 + (lane >> 2);
        const int r1 = r0 + 8;
        const int cb = (lane & 3) * 2;
        const float w0 = (r0 < valid) ? wsm_s[r0] : 0.f;
        const float w1 = (r1 < valid) ? wsm_s[r1] : 0.f;
        const size_t s0 = (size_t)(off + m0g + r0) * DMODEL;
        const size_t s1 = (size_t)(off + m0g + r1) * DMODEL;
        #pragma unroll
        for (int jt = 0; jt < 8; ++jt) {
            int col = (nw * 8 + jt) * 8 + cb;
            float bb0 = b2s[col], bb1 = b2s[col + 1];
            if (r0 < valid) {
                float2 o;
                o.x = w0 * (acc2[jt][0] + bb0);
                o.y = w0 * (acc2[jt][1] + bb1);
                *reinterpret_cast<float2*>(&g_partial[s0 + col]) = o;
            }
            if (r1 < valid) {
                float2 o;
                o.x = w1 * (acc2[jt][2] + bb0);
                o.y = w1 * (acc2[jt][3] + bb1);
                *reinterpret_cast<float2*>(&g_partial[s1 + col]) = o;
            }
        }
    }
}

// ================= kernel: combine =================
__global__ void __launch_bounds__(256) combine_kernel(float* __restrict__ out) {
    int gid = blockIdx.x * 256 + threadIdx.x;
    int n = gid >> 5;
    int q = gid & 31;
    int s0 = g_tok_slot[2 * n];
    int s1 = g_tok_slot[2 * n + 1];
    const float4* P = reinterpret_cast<const float4*>(g_partial);
    float4 p0 = P[(size_t)s0 * 32 + q];
    float4 p1 = P[(size_t)s1 * 32 + q];
    float4 o;
    o.x = p0.x + p1.x; o.y = p0.y + p1.y;
    o.z = p0.z + p1.z; o.w = p0.w + p1.w;
    reinterpret_cast<float4*>(out)[(size_t)n * 32 + q] = o;
}

// ================= launch =================
extern "C" void kernel_launch(void* const* d_in, const int* in_sizes, int n_in,
                              void* d_out, int out_size) {
    const float* x  = (const float*)d_in[0];
    const float* W1 = (const float*)d_in[1];
    const float* b1 = (const float*)d_in[2];
    const float* W2 = (const float*)d_in[3];
    const float* b2 = (const float*)d_in[4];
    const float* Wr = (const float*)d_in[5];
    const float* br = (const float*)d_in[6];
    float* out = (float*)d_out;

    cudaFuncSetAttribute(expert_mma_kernel,
                         cudaFuncAttributeMaxDynamicSharedMemorySize, SMEM_DYN);

    init_kernel<<<1, 64>>>();
    convert_x_kernel<<<NTOK * DMODEL / (256 * 8), 256>>>(x);
    convert_w_kernel<<<NEXP * HDIM * DMODEL / 256, 256>>>(W1, W2);
    router_kernel<<<256, 256>>>(x, Wr, br);
    scan_loss_kernel<<<1, 32>>>(out, out_size);
    scatter_kernel<<<NTOK / 256, 256>>>();
    expert_mma_kernel<<<1056, NTHR, SMEM_DYN>>>(b1, b2);
    combine_kernel<<<(NTOK * 32) / 256, 256>>>(out);
}

// round 5
// speedup vs baseline: 2.7518x; 1.2610x over previous
#include <cuda_runtime.h>
#include <cuda_bf16.h>
#include <math.h>
#include <stdint.h>

#define NTOK   65536
#define DMODEL 128
#define HDIM   256
#define NEXP   32
#define TM     128

// ================= helpers =================
__device__ __forceinline__ uint32_t smem_to_u32(const void* p) {
    uint32_t a;
    asm("{ .reg .u64 t; cvta.to.shared.u64 t, %1; cvt.u32.u64 %0, t; }" : "=r"(a) : "l"(p));
    return a;
}
__device__ __forceinline__ void ldsm4(uint32_t& r0, uint32_t& r1, uint32_t& r2, uint32_t& r3,
                                      uint32_t addr) {
    asm volatile("ldmatrix.sync.aligned.m8n8.x4.shared.b16 {%0,%1,%2,%3}, [%4];"
                 : "=r"(r0), "=r"(r1), "=r"(r2), "=r"(r3) : "r"(addr));
}
__device__ __forceinline__ void mma16816(float* c, uint32_t a0, uint32_t a1, uint32_t a2,
                                         uint32_t a3, uint32_t b0, uint32_t b1) {
    asm volatile("mma.sync.aligned.m16n8k16.row.col.f32.bf16.bf16.f32 "
                 "{%0,%1,%2,%3}, {%4,%5,%6,%7}, {%8,%9}, {%0,%1,%2,%3};"
                 : "+f"(c[0]), "+f"(c[1]), "+f"(c[2]), "+f"(c[3])
                 : "r"(a0), "r"(a1), "r"(a2), "r"(a3), "r"(b0), "r"(b1));
}
__device__ __forceinline__ void cp16(uint32_t dst, const void* src) {
    asm volatile("cp.async.cg.shared.global [%0], [%1], 16;" :: "r"(dst), "l"(src) : "memory");
}
#define CP_COMMIT() asm volatile("cp.async.commit_group;" ::: "memory")
#define CP_WAIT0()  asm volatile("cp.async.wait_group 0;" ::: "memory")

__device__ __forceinline__ void split2(float v, __nv_bfloat16& hi, __nv_bfloat16& lo) {
    hi = __float2bfloat16(v);
    lo = __float2bfloat16(v - __bfloat162float(hi));
}
__device__ __forceinline__ uint32_t packbf(__nv_bfloat16 a, __nv_bfloat16 b) {
    __nv_bfloat162 t(a, b);
    return *reinterpret_cast<uint32_t*>(&t);
}

// ================= device scratch =================
__device__ float g_top_v[2 * NTOK];
__device__ int   g_top_e[2 * NTOK];
__device__ float g_importance[NEXP];
__device__ int   g_counts[NEXP];
__device__ int   g_offsets[NEXP + 1];
__device__ int   g_cursor[NEXP];
__device__ int   g_tile_off[NEXP + 1];
__device__ int   g_total_tiles;
__device__ int   g_bucket_tok[2 * NTOK];
__device__ float g_bucket_w[2 * NTOK];
__device__ int   g_tok_slot[2 * NTOK];
__device__ float g_partial[(size_t)2 * NTOK * DMODEL];

__device__ __align__(16) __nv_bfloat16 g_xhi[NTOK * DMODEL];
__device__ __align__(16) __nv_bfloat16 g_xlo[NTOK * DMODEL];
__device__ __align__(16) __nv_bfloat16 g_w1hi[NEXP * HDIM * DMODEL];   // [E,H,D]
__device__ __align__(16) __nv_bfloat16 g_w1lo[NEXP * HDIM * DMODEL];
__device__ __align__(16) __nv_bfloat16 g_w2hi[NEXP * DMODEL * HDIM];   // [E,D,H]
__device__ __align__(16) __nv_bfloat16 g_w2lo[NEXP * DMODEL * HDIM];

// ================= kernel: convert x -> bf16 hi/lo (+ init in block 0) =================
__global__ void __launch_bounds__(256) convert_x_kernel(const float* __restrict__ x) {
    if (blockIdx.x == 0 && threadIdx.x < NEXP) {
        g_counts[threadIdx.x] = 0;
        g_importance[threadIdx.x] = 0.f;
    }
    size_t i = ((size_t)blockIdx.x * 256 + threadIdx.x) * 8;
    float4 a = *reinterpret_cast<const float4*>(x + i);
    float4 b = *reinterpret_cast<const float4*>(x + i + 4);
    float v[8] = {a.x, a.y, a.z, a.w, b.x, b.y, b.z, b.w};
    __nv_bfloat16 hi[8], lo[8];
    #pragma unroll
    for (int q = 0; q < 8; ++q) split2(v[q], hi[q], lo[q]);
    uint4 ph, pl;
    ph.x = packbf(hi[0], hi[1]); ph.y = packbf(hi[2], hi[3]);
    ph.z = packbf(hi[4], hi[5]); ph.w = packbf(hi[6], hi[7]);
    pl.x = packbf(lo[0], lo[1]); pl.y = packbf(lo[2], lo[3]);
    pl.z = packbf(lo[4], lo[5]); pl.w = packbf(lo[6], lo[7]);
    *reinterpret_cast<uint4*>(g_xhi + i) = ph;
    *reinterpret_cast<uint4*>(g_xlo + i) = pl;
}

// ================= kernel: convert + transpose weights =================
__global__ void __launch_bounds__(256) convert_w_kernel(const float* __restrict__ W1,
                                                        const float* __restrict__ W2) {
    int idx = blockIdx.x * 256 + threadIdx.x;
    {   // W1T[e][h][d] = W1[e][d][h]
        int d = idx & 127, h = (idx >> 7) & 255, e = idx >> 15;
        float v = W1[((size_t)e * 128 + d) * 256 + h];
        __nv_bfloat16 hi, lo; split2(v, hi, lo);
        g_w1hi[idx] = hi; g_w1lo[idx] = lo;
    }
    {   // W2T[e][d][h] = W2[e][h][d]
        int h = idx & 255, d = (idx >> 8) & 127, e = idx >> 15;
        float v = W2[((size_t)e * 256 + h) * 128 + d];
        __nv_bfloat16 hi, lo; split2(v, hi, lo);
        g_w2hi[idx] = hi; g_w2lo[idx] = lo;
    }
}

// ================= kernel: router (thread per token, shuffle-free) =================
__global__ void __launch_bounds__(256) router_kernel(
    const float* __restrict__ x, const float* __restrict__ Wr,
    const float* __restrict__ br)
{
    __shared__ float wr_s[DMODEL * NEXP];   // [d][e] — same layout as Wr
    __shared__ float br_s[NEXP];
    __shared__ float imp_s[NEXP];
    __shared__ int   cnt_s[NEXP];

    const int tid = threadIdx.x;
    if (tid < NEXP) { imp_s[tid] = 0.f; cnt_s[tid] = 0; br_s[tid] = br[tid]; }
    #pragma unroll
    for (int i = tid; i < DMODEL * NEXP; i += 256) wr_s[i] = Wr[i];
    __syncthreads();

    const int n = blockIdx.x * 256 + tid;     // grid covers NTOK exactly

    float acc[NEXP];
    #pragma unroll
    for (int e = 0; e < NEXP; ++e) acc[e] = br_s[e];

    const float4* xrow = reinterpret_cast<const float4*>(x + (size_t)n * DMODEL);
    float4 xv = xrow[0];
    #pragma unroll 4
    for (int ch = 0; ch < 32; ++ch) {
        float4 xn;
        if (ch < 31) xn = xrow[ch + 1];
        float xd[4] = {xv.x, xv.y, xv.z, xv.w};
        #pragma unroll
        for (int dd = 0; dd < 4; ++dd) {
            const float4* wrow = reinterpret_cast<const float4*>(&wr_s[(ch * 4 + dd) * NEXP]);
            #pragma unroll
            for (int e4 = 0; e4 < 8; ++e4) {
                float4 w = wrow[e4];   // broadcast LDS.128
                acc[e4 * 4 + 0] = fmaf(xd[dd], w.x, acc[e4 * 4 + 0]);
                acc[e4 * 4 + 1] = fmaf(xd[dd], w.y, acc[e4 * 4 + 1]);
                acc[e4 * 4 + 2] = fmaf(xd[dd], w.z, acc[e4 * 4 + 2]);
                acc[e4 * 4 + 3] = fmaf(xd[dd], w.w, acc[e4 * 4 + 3]);
            }
        }
        xv = xn;
    }

    // softmax over 32 register values
    float mx = acc[0];
    #pragma unroll
    for (int e = 1; e < NEXP; ++e) mx = fmaxf(mx, acc[e]);
    float s = 0.f;
    #pragma unroll
    for (int e = 0; e < NEXP; ++e) { acc[e] = expf(acc[e] - mx); s += acc[e]; }
    float inv = 1.f / s;
    #pragma unroll
    for (int e = 0; e < NEXP; ++e) acc[e] *= inv;

    // top-1 then top-2 (strict > keeps lowest index on ties, matching top_k)
    float v1 = acc[0]; int i1 = 0;
    #pragma unroll
    for (int e = 1; e < NEXP; ++e) if (acc[e] > v1) { v1 = acc[e]; i1 = e; }
    float v2 = -1.f; int i2 = 0;
    #pragma unroll
    for (int e = 0; e < NEXP; ++e) {
        bool ok = (e != i1) && (acc[e] > v2);
        if (ok) { v2 = acc[e]; i2 = e; }
    }

    g_top_e[2 * n]     = i1;  g_top_v[2 * n]     = v1;
    g_top_e[2 * n + 1] = i2;  g_top_v[2 * n + 1] = v2;
    atomicAdd(&imp_s[i1], v1);
    atomicAdd(&imp_s[i2], v2);
    atomicAdd(&cnt_s[i1], 1);
    atomicAdd(&cnt_s[i2], 1);

    __syncthreads();
    if (tid < NEXP) {
        atomicAdd(&g_importance[tid], imp_s[tid]);
        atomicAdd(&g_counts[tid], cnt_s[tid]);
    }
}

// ================= kernel: scan + loss =================
__global__ void scan_loss_kernel(float* __restrict__ out, int out_size) {
    const int lane = threadIdx.x;
    const unsigned FULL = 0xffffffffu;

    int c = g_counts[lane];
    int sc = c;
    #pragma unroll
    for (int o = 1; o < 32; o <<= 1) {
        int v = __shfl_up_sync(FULL, sc, o);
        if (lane >= o) sc += v;
    }
    g_offsets[lane] = sc - c;
    g_cursor[lane]  = sc - c;
    if (lane == 31) g_offsets[NEXP] = sc;

    int nt = (c + TM - 1) / TM;
    int st = nt;
    #pragma unroll
    for (int o = 1; o < 32; o <<= 1) {
        int v = __shfl_up_sync(FULL, st, o);
        if (lane >= o) st += v;
    }
    g_tile_off[lane] = st - nt;
    if (lane == 31) { g_tile_off[NEXP] = st; g_total_tiles = st; }

    float imp = g_importance[lane];
    float s = imp;
    #pragma unroll
    for (int o = 16; o; o >>= 1) s += __shfl_xor_sync(FULL, s, o);
    float mean = s / 32.f;
    float d = imp - mean;
    float ss = d * d;
    #pragma unroll
    for (int o = 16; o; o >>= 1) ss += __shfl_xor_sync(FULL, ss, o);
    float var = ss / 31.f;
    if (lane == 0 && out_size > NTOK * DMODEL)
        out[NTOK * DMODEL] = var / (mean * mean + 1e-9f);
}

// ================= kernel: scatter =================
__global__ void __launch_bounds__(256) scatter_kernel() {
    __shared__ int lcnt[NEXP];
    __shared__ int gbase[NEXP];
    __shared__ int lcur[NEXP];

    const int tid = threadIdx.x;
    const int n = blockIdx.x * 256 + tid;
    if (tid < NEXP) lcnt[tid] = 0;
    __syncthreads();

    int e0 = g_top_e[2 * n];     float v0 = g_top_v[2 * n];
    int e1 = g_top_e[2 * n + 1]; float v1 = g_top_v[2 * n + 1];
    atomicAdd(&lcnt[e0], 1);
    atomicAdd(&lcnt[e1], 1);
    __syncthreads();

    if (tid < NEXP) { gbase[tid] = atomicAdd(&g_cursor[tid], lcnt[tid]); lcur[tid] = 0; }
    __syncthreads();

    int p0 = gbase[e0] + atomicAdd(&lcur[e0], 1);
    g_bucket_tok[p0] = n; g_bucket_w[p0] = v0; g_tok_slot[2 * n] = p0;
    int p1 = gbase[e1] + atomicAdd(&lcur[e1], 1);
    g_bucket_tok[p1] = n; g_bucket_w[p1] = v1; g_tok_slot[2 * n + 1] = p1;
}

// ================= kernel: grouped expert GEMM (HMMA split-bf16, 512 thr, cp.async) =================
#define SX   136
#define ROWB (SX * 2)
#define O_XH 0
#define O_XL (128 * ROWB)
#define O_BH (2 * 128 * ROWB)
#define O_BL (3 * 128 * ROWB)
#define O_CH (4 * 128 * ROWB)
#define O_CL (5 * 128 * ROWB)
#define O_TOK (6 * 128 * ROWB)            // 208896
#define O_WSM (O_TOK + 512)
#define O_B1  (O_TOK + 1024)
#define O_B2  (O_TOK + 2048)
#define SMEM_DYN (O_TOK + 2560)           // 211456 bytes

#define NTHR 512

__global__ void __launch_bounds__(NTHR, 1) expert_mma_kernel(
    const float* __restrict__ b1, const float* __restrict__ b2)
{
    const int t = blockIdx.x;
    if (t >= g_total_tiles) return;

    extern __shared__ char smp[];
    const uint32_t sbase = smem_to_u32(smp);
    int*   toks_s = (int*)(smp + O_TOK);
    float* wsm_s  = (float*)(smp + O_WSM);
    float* b1s    = (float*)(smp + O_B1);
    float* b2s    = (float*)(smp + O_B2);

    const int tid = threadIdx.x;
    const int wid = tid >> 5;
    const int lane = tid & 31;

    // locate expert / tile
    int e = 0;
    #pragma unroll 1
    while (t >= g_tile_off[e + 1]) ++e;
    const int mtile = t - g_tile_off[e];
    const int off   = g_offsets[e];
    const int cnt   = g_counts[e];
    const int m0g   = mtile * TM;
    const int valid = min(TM, cnt - m0g);

    if (tid < 128) {
        if (tid < valid) {
            toks_s[tid] = g_bucket_tok[off + m0g + tid];
            wsm_s[tid]  = g_bucket_w[off + m0g + tid];
        } else { toks_s[tid] = 0; wsm_s[tid] = 0.f; }
        b2s[tid] = b2[e * DMODEL + tid];
    }
    if (tid < 256) b1s[tid] = b1[e * HDIM + tid];
    __syncthreads();   // toks visible for gather

    // ---- async gather X rows (bf16 hi/lo) ----
    #pragma unroll
    for (int i = tid; i < 2048; i += NTHR) {
        int r = i >> 4, ch = i & 15;
        const size_t src = (size_t)toks_s[r] * DMODEL + ch * 8;
        uint32_t dst = sbase + r * ROWB + ch * 16;
        cp16(dst + O_XH, g_xhi + src);
        cp16(dst + O_XL, g_xlo + src);
    }
    CP_COMMIT();

    const size_t w1base = (size_t)e * HDIM * DMODEL;
    const size_t w2base = (size_t)e * DMODEL * HDIM;

    // ---- async load W1 chunk 0 ----
    #pragma unroll
    for (int i = tid; i < 2048; i += NTHR) {
        int r = i >> 4, ch = i & 15;
        size_t src = w1base + (size_t)r * DMODEL + ch * 8;
        uint32_t dst = sbase + r * ROWB + ch * 16;
        cp16(dst + O_BH, g_w1hi + src);
        cp16(dst + O_BL, g_w1lo + src);
    }
    CP_COMMIT();
    CP_WAIT0();
    __syncthreads();

    // warp tiling: 8 m-warps x 2 n-warps
    const int m0 = (wid >> 1) * 16;
    const int nw = wid & 1;
    const uint32_t arow  = m0 + (lane & 15);
    const uint32_t acolb = ((lane >> 4) & 1) * 16;
    const uint32_t brow0 = nw * 64 + ((lane >> 4) & 1) * 8 + (lane & 7);
    const uint32_t bcolb = ((lane >> 3) & 1) * 16;

    float acc2[8][4];
    #pragma unroll
    for (int j = 0; j < 8; ++j)
        #pragma unroll
        for (int q = 0; q < 4; ++q) acc2[j][q] = 0.f;

    #pragma unroll 1
    for (int c = 0; c < 2; ++c) {
        // ---- FC1: acc1 = X @ W1chunk^T (m16 x n64 per warp) ----
        float acc1[8][4];
        #pragma unroll
        for (int j = 0; j < 8; ++j)
            #pragma unroll
            for (int q = 0; q < 4; ++q) acc1[j][q] = 0.f;

        #pragma unroll 1
        for (int k = 0; k < 8; ++k) {
            uint32_t aaddr = sbase + O_XH + arow * ROWB + k * 32 + acolb;
            uint32_t ah0, ah1, ah2, ah3, al0, al1, al2, al3;
            ldsm4(ah0, ah1, ah2, ah3, aaddr);
            ldsm4(al0, al1, al2, al3, aaddr + (O_XL - O_XH));
            #pragma unroll
            for (int jp = 0; jp < 4; ++jp) {
                uint32_t baddr = sbase + O_BH + (brow0 + jp * 16) * ROWB + k * 32 + bcolb;
                uint32_t bh0, bh1, bh2, bh3, bl0, bl1, bl2, bl3;
                ldsm4(bh0, bh1, bh2, bh3, baddr);
                ldsm4(bl0, bl1, bl2, bl3, baddr + (O_BL - O_BH));
                mma16816(acc1[2*jp],   ah0, ah1, ah2, ah3, bh0, bh1);
                mma16816(acc1[2*jp],   ah0, ah1, ah2, ah3, bl0, bl1);
                mma16816(acc1[2*jp],   al0, al1, al2, al3, bh0, bh1);
                mma16816(acc1[2*jp+1], ah0, ah1, ah2, ah3, bh2, bh3);
                mma16816(acc1[2*jp+1], ah0, ah1, ah2, ah3, bl2, bl3);
                mma16816(acc1[2*jp+1], al0, al1, al2, al3, bh2, bh3);
            }
        }
        __syncthreads();   // all warps done reading B (W1 chunk)

        // ---- prefetch W2 chunk c into B (overlaps epilogue 1) ----
        #pragma unroll
        for (int i = tid; i < 2048; i += NTHR) {
            int r = i >> 4, ch = i & 15;
            size_t src = w2base + (size_t)r * HDIM + c * 128 + ch * 8;
            uint32_t dst = sbase + r * ROWB + ch * 16;
            cp16(dst + O_BH, g_w2hi + src);
            cp16(dst + O_BL, g_w2lo + src);
        }
        CP_COMMIT();

        // ---- epilogue 1: relu(acc1 + b1) -> split hi/lo into C ----
        {
            const int r0 = m0 + (lane >> 2);
            const int cb = (lane & 3) * 2;
            #pragma unroll
            for (int jt = 0; jt < 8; ++jt) {
                int coll = (nw * 8 + jt) * 8 + cb;
                int colg = c * 128 + coll;
                float bb0 = b1s[colg], bb1 = b1s[colg + 1];
                float f0 = fmaxf(acc1[jt][0] + bb0, 0.f);
                float f1 = fmaxf(acc1[jt][1] + bb1, 0.f);
                float f2 = fmaxf(acc1[jt][2] + bb0, 0.f);
                float f3 = fmaxf(acc1[jt][3] + bb1, 0.f);
                __nv_bfloat16 h0,l0,h1,l1,h2,l2,h3,l3;
                split2(f0,h0,l0); split2(f1,h1,l1); split2(f2,h2,l2); split2(f3,h3,l3);
                int d0 = r0 * ROWB + coll * 2;
                int d1 = (r0 + 8) * ROWB + coll * 2;
                *reinterpret_cast<uint32_t*>(smp + O_CH + d0) = packbf(h0, h1);
                *reinterpret_cast<uint32_t*>(smp + O_CL + d0) = packbf(l0, l1);
                *reinterpret_cast<uint32_t*>(smp + O_CH + d1) = packbf(h2, h3);
                *reinterpret_cast<uint32_t*>(smp + O_CL + d1) = packbf(l2, l3);
            }
        }
        CP_WAIT0();
        __syncthreads();   // W2 chunk ready, h visible

        // ---- FC2: acc2 += h_chunk @ W2chunk^T ----
        #pragma unroll 1
        for (int k = 0; k < 8; ++k) {
            uint32_t aaddr = sbase + O_CH + arow * ROWB + k * 32 + acolb;
            uint32_t ah0, ah1, ah2, ah3, al0, al1, al2, al3;
            ldsm4(ah0, ah1, ah2, ah3, aaddr);
            ldsm4(al0, al1, al2, al3, aaddr + (O_CL - O_CH));
            #pragma unroll
            for (int jp = 0; jp < 4; ++jp) {
                uint32_t baddr = sbase + O_BH + (brow0 + jp * 16) * ROWB + k * 32 + bcolb;
                uint32_t bh0, bh1, bh2, bh3, bl0, bl1, bl2, bl3;
                ldsm4(bh0, bh1, bh2, bh3, baddr);
                ldsm4(bl0, bl1, bl2, bl3, baddr + (O_BL - O_BH));
                mma16816(acc2[2*jp],   ah0, ah1, ah2, ah3, bh0, bh1);
                mma16816(acc2[2*jp],   ah0, ah1, ah2, ah3, bl0, bl1);
                mma16816(acc2[2*jp],   al0, al1, al2, al3, bh0, bh1);
                mma16816(acc2[2*jp+1], ah0, ah1, ah2, ah3, bh2, bh3);
                mma16816(acc2[2*jp+1], ah0, ah1, ah2, ah3, bl2, bl3);
                mma16816(acc2[2*jp+1], al0, al1, al2, al3, bh2, bh3);
            }
        }
        __syncthreads();   // done reading B & C

        // ---- prefetch W1 chunk 1 into B ----
        if (c == 0) {
            #pragma unroll
            for (int i = tid; i < 2048; i += NTHR) {
                int r = i >> 4, ch = i & 15;
                size_t src = w1base + (size_t)(128 + r) * DMODEL + ch * 8;
                uint32_t dst = sbase + r * ROWB + ch * 16;
                cp16(dst + O_BH, g_w1hi + src);
                cp16(dst + O_BL, g_w1lo + src);
            }
            CP_COMMIT();
            CP_WAIT0();
            __syncthreads();
        }
    }

    // ---- epilogue 2: w * (acc2 + b2) -> g_partial ----
    {
        const int r0 = m0 + (lane >> 2);
        const int r1 = r0 + 8;
        const int cb = (lane & 3) * 2;
        const float w0 = (r0 < valid) ? wsm_s[r0] : 0.f;
        const float w1 = (r1 < valid) ? wsm_s[r1] : 0.f;
        const size_t s0 = (size_t)(off + m0g + r0) * DMODEL;
        const size_t s1 = (size_t)(off + m0g + r1) * DMODEL;
        #pragma unroll
        for (int jt = 0; jt < 8; ++jt) {
            int col = (nw * 8 + jt) * 8 + cb;
            float bb0 = b2s[col], bb1 = b2s[col + 1];
            if (r0 < valid) {
                float2 o;
                o.x = w0 * (acc2[jt][0] + bb0);
                o.y = w0 * (acc2[jt][1] + bb1);
                *reinterpret_cast<float2*>(&g_partial[s0 + col]) = o;
            }
            if (r1 < valid) {
                float2 o;
                o.x = w1 * (acc2[jt][2] + bb0);
                o.y = w1 * (acc2[jt][3] + bb1);
                *reinterpret_cast<float2*>(&g_partial[s1 + col]) = o;
            }
        }
    }
}

// ================= kernel: combine =================
__global__ void __launch_bounds__(256) combine_kernel(float* __restrict__ out) {
    int gid = blockIdx.x * 256 + threadIdx.x;
    int n = gid >> 5;
    int q = gid & 31;
    int s0 = g_tok_slot[2 * n];
    int s1 = g_tok_slot[2 * n + 1];
    const float4* P = reinterpret_cast<const float4*>(g_partial);
    float4 p0 = P[(size_t)s0 * 32 + q];
    float4 p1 = P[(size_t)s1 * 32 + q];
    float4 o;
    o.x = p0.x + p1.x; o.y = p0.y + p1.y;
    o.z = p0.z + p1.z; o.w = p0.w + p1.w;
    reinterpret_cast<float4*>(out)[(size_t)n * 32 + q] = o;
}

// ================= launch =================
extern "C" void kernel_launch(void* const* d_in, const int* in_sizes, int n_in,
                              void* d_out, int out_size) {
    const float* x  = (const float*)d_in[0];
    const float* W1 = (const float*)d_in[1];
    const float* b1 = (const float*)d_in[2];
    const float* W2 = (const float*)d_in[3];
    const float* b2 = (const float*)d_in[4];
    const float* Wr = (const float*)d_in[5];
    const float* br = (const float*)d_in[6];
    float* out = (float*)d_out;

    cudaFuncSetAttribute(expert_mma_kernel,
                         cudaFuncAttributeMaxDynamicSharedMemorySize, SMEM_DYN);

    convert_x_kernel<<<NTOK * DMODEL / (256 * 8), 256>>>(x);
    convert_w_kernel<<<NEXP * HDIM * DMODEL / 256, 256>>>(W1, W2);
    router_kernel<<<NTOK / 256, 256>>>(x, Wr, br);
    scan_loss_kernel<<<1, 32>>>(out, out_size);
    scatter_kernel<<<NTOK / 256, 256>>>();
    expert_mma_kernel<<<1056, NTHR, SMEM_DYN>>>(b1, b2);
    combine_kernel<<<(NTOK * 32) / 256, 256>>>(out);
}

// round 6
// speedup vs baseline: 2.7566x; 1.0017x over previous
#include <cuda_runtime.h>
#include <cuda_bf16.h>
#include <math.h>
#include <stdint.h>

#define NTOK   65536
#define DMODEL 128
#define HDIM   256
#define NEXP   32
#define TM     128

// ================= helpers =================
__device__ __forceinline__ uint32_t smem_to_u32(const void* p) {
    uint32_t a;
    asm("{ .reg .u64 t; cvta.to.shared.u64 t, %1; cvt.u32.u64 %0, t; }" : "=r"(a) : "l"(p));
    return a;
}
__device__ __forceinline__ void ldsm4(uint32_t& r0, uint32_t& r1, uint32_t& r2, uint32_t& r3,
                                      uint32_t addr) {
    asm volatile("ldmatrix.sync.aligned.m8n8.x4.shared.b16 {%0,%1,%2,%3}, [%4];"
                 : "=r"(r0), "=r"(r1), "=r"(r2), "=r"(r3) : "r"(addr));
}
__device__ __forceinline__ void mma16816(float* c, uint32_t a0, uint32_t a1, uint32_t a2,
                                         uint32_t a3, uint32_t b0, uint32_t b1) {
    asm volatile("mma.sync.aligned.m16n8k16.row.col.f32.bf16.bf16.f32 "
                 "{%0,%1,%2,%3}, {%4,%5,%6,%7}, {%8,%9}, {%0,%1,%2,%3};"
                 : "+f"(c[0]), "+f"(c[1]), "+f"(c[2]), "+f"(c[3])
                 : "r"(a0), "r"(a1), "r"(a2), "r"(a3), "r"(b0), "r"(b1));
}
__device__ __forceinline__ void cp16(uint32_t dst, const void* src) {
    asm volatile("cp.async.cg.shared.global [%0], [%1], 16;" :: "r"(dst), "l"(src) : "memory");
}
#define CP_COMMIT() asm volatile("cp.async.commit_group;" ::: "memory")
#define CP_WAIT0()  asm volatile("cp.async.wait_group 0;" ::: "memory")

__device__ __forceinline__ void split2(float v, __nv_bfloat16& hi, __nv_bfloat16& lo) {
    hi = __float2bfloat16(v);
    lo = __float2bfloat16(v - __bfloat162float(hi));
}
__device__ __forceinline__ uint32_t packbf(__nv_bfloat16 a, __nv_bfloat16 b) {
    __nv_bfloat162 t(a, b);
    return *reinterpret_cast<uint32_t*>(&t);
}

// ================= device scratch =================
__device__ float g_top_v[2 * NTOK];
__device__ int   g_top_e[2 * NTOK];
__device__ float g_importance[NEXP];
__device__ int   g_counts[NEXP];
__device__ int   g_offsets[NEXP + 1];
__device__ int   g_cursor[NEXP];
__device__ int   g_tile_off[NEXP + 1];
__device__ int   g_total_tiles;
__device__ int   g_bucket_tok[2 * NTOK];
__device__ float g_bucket_w[2 * NTOK];
__device__ int   g_tok_slot[2 * NTOK];
__device__ float g_partial[(size_t)2 * NTOK * DMODEL];

__device__ __align__(16) __nv_bfloat16 g_xhi[NTOK * DMODEL];
__device__ __align__(16) __nv_bfloat16 g_xlo[NTOK * DMODEL];
__device__ __align__(16) __nv_bfloat16 g_w1hi[NEXP * HDIM * DMODEL];   // [E,H,D]
__device__ __align__(16) __nv_bfloat16 g_w1lo[NEXP * HDIM * DMODEL];
__device__ __align__(16) __nv_bfloat16 g_w2hi[NEXP * DMODEL * HDIM];   // [E,D,H]
__device__ __align__(16) __nv_bfloat16 g_w2lo[NEXP * DMODEL * HDIM];

// ================= kernel: convert x -> bf16 hi/lo (+ init in block 0) =================
__global__ void __launch_bounds__(256) convert_x_kernel(const float* __restrict__ x) {
    if (blockIdx.x == 0 && threadIdx.x < NEXP) {
        g_counts[threadIdx.x] = 0;
        g_importance[threadIdx.x] = 0.f;
    }
    size_t i = ((size_t)blockIdx.x * 256 + threadIdx.x) * 8;
    float4 a = *reinterpret_cast<const float4*>(x + i);
    float4 b = *reinterpret_cast<const float4*>(x + i + 4);
    float v[8] = {a.x, a.y, a.z, a.w, b.x, b.y, b.z, b.w};
    __nv_bfloat16 hi[8], lo[8];
    #pragma unroll
    for (int q = 0; q < 8; ++q) split2(v[q], hi[q], lo[q]);
    uint4 ph, pl;
    ph.x = packbf(hi[0], hi[1]); ph.y = packbf(hi[2], hi[3]);
    ph.z = packbf(hi[4], hi[5]); ph.w = packbf(hi[6], hi[7]);
    pl.x = packbf(lo[0], lo[1]); pl.y = packbf(lo[2], lo[3]);
    pl.z = packbf(lo[4], lo[5]); pl.w = packbf(lo[6], lo[7]);
    *reinterpret_cast<uint4*>(g_xhi + i) = ph;
    *reinterpret_cast<uint4*>(g_xlo + i) = pl;
}

// ================= kernel: convert + transpose weights =================
__global__ void __launch_bounds__(256) convert_w_kernel(const float* __restrict__ W1,
                                                        const float* __restrict__ W2) {
    int idx = blockIdx.x * 256 + threadIdx.x;
    {   // W1T[e][h][d] = W1[e][d][h]
        int d = idx & 127, h = (idx >> 7) & 255, e = idx >> 15;
        float v = W1[((size_t)e * 128 + d) * 256 + h];
        __nv_bfloat16 hi, lo; split2(v, hi, lo);
        g_w1hi[idx] = hi; g_w1lo[idx] = lo;
    }
    {   // W2T[e][d][h] = W2[e][h][d]
        int h = idx & 255, d = (idx >> 8) & 127, e = idx >> 15;
        float v = W2[((size_t)e * 256 + h) * 128 + d];
        __nv_bfloat16 hi, lo; split2(v, hi, lo);
        g_w2hi[idx] = hi; g_w2lo[idx] = lo;
    }
}

// ================= kernel: router (thread per token, shuffle-free) =================
__global__ void __launch_bounds__(256) router_kernel(
    const float* __restrict__ x, const float* __restrict__ Wr,
    const float* __restrict__ br)
{
    __shared__ float wr_s[DMODEL * NEXP];   // [d][e]
    __shared__ float br_s[NEXP];
    __shared__ float imp_s[NEXP];
    __shared__ int   cnt_s[NEXP];

    const int tid = threadIdx.x;
    if (tid < NEXP) { imp_s[tid] = 0.f; cnt_s[tid] = 0; br_s[tid] = br[tid]; }
    #pragma unroll
    for (int i = tid; i < DMODEL * NEXP; i += 256) wr_s[i] = Wr[i];
    __syncthreads();

    const int n = blockIdx.x * 256 + tid;

    float acc[NEXP];
    #pragma unroll
    for (int e = 0; e < NEXP; ++e) acc[e] = br_s[e];

    const float4* xrow = reinterpret_cast<const float4*>(x + (size_t)n * DMODEL);
    float4 xv = xrow[0];
    #pragma unroll 4
    for (int ch = 0; ch < 32; ++ch) {
        float4 xn;
        if (ch < 31) xn = xrow[ch + 1];
        float xd[4] = {xv.x, xv.y, xv.z, xv.w};
        #pragma unroll
        for (int dd = 0; dd < 4; ++dd) {
            const float4* wrow = reinterpret_cast<const float4*>(&wr_s[(ch * 4 + dd) * NEXP]);
            #pragma unroll
            for (int e4 = 0; e4 < 8; ++e4) {
                float4 w = wrow[e4];
                acc[e4 * 4 + 0] = fmaf(xd[dd], w.x, acc[e4 * 4 + 0]);
                acc[e4 * 4 + 1] = fmaf(xd[dd], w.y, acc[e4 * 4 + 1]);
                acc[e4 * 4 + 2] = fmaf(xd[dd], w.z, acc[e4 * 4 + 2]);
                acc[e4 * 4 + 3] = fmaf(xd[dd], w.w, acc[e4 * 4 + 3]);
            }
        }
        xv = xn;
    }

    float mx = acc[0];
    #pragma unroll
    for (int e = 1; e < NEXP; ++e) mx = fmaxf(mx, acc[e]);
    float s = 0.f;
    #pragma unroll
    for (int e = 0; e < NEXP; ++e) { acc[e] = expf(acc[e] - mx); s += acc[e]; }
    float inv = 1.f / s;
    #pragma unroll
    for (int e = 0; e < NEXP; ++e) acc[e] *= inv;

    float v1 = acc[0]; int i1 = 0;
    #pragma unroll
    for (int e = 1; e < NEXP; ++e) if (acc[e] > v1) { v1 = acc[e]; i1 = e; }
    float v2 = -1.f; int i2 = 0;
    #pragma unroll
    for (int e = 0; e < NEXP; ++e) {
        bool ok = (e != i1) && (acc[e] > v2);
        if (ok) { v2 = acc[e]; i2 = e; }
    }

    g_top_e[2 * n]     = i1;  g_top_v[2 * n]     = v1;
    g_top_e[2 * n + 1] = i2;  g_top_v[2 * n + 1] = v2;
    atomicAdd(&imp_s[i1], v1);
    atomicAdd(&imp_s[i2], v2);
    atomicAdd(&cnt_s[i1], 1);
    atomicAdd(&cnt_s[i2], 1);

    __syncthreads();
    if (tid < NEXP) {
        atomicAdd(&g_importance[tid], imp_s[tid]);
        atomicAdd(&g_counts[tid], cnt_s[tid]);
    }
}

// ================= kernel: scan + loss =================
__global__ void scan_loss_kernel(float* __restrict__ out, int out_size) {
    const int lane = threadIdx.x;
    const unsigned FULL = 0xffffffffu;

    int c = g_counts[lane];
    int sc = c;
    #pragma unroll
    for (int o = 1; o < 32; o <<= 1) {
        int v = __shfl_up_sync(FULL, sc, o);
        if (lane >= o) sc += v;
    }
    g_offsets[lane] = sc - c;
    g_cursor[lane]  = sc - c;
    if (lane == 31) g_offsets[NEXP] = sc;

    int nt = (c + TM - 1) / TM;
    int st = nt;
    #pragma unroll
    for (int o = 1; o < 32; o <<= 1) {
        int v = __shfl_up_sync(FULL, st, o);
        if (lane >= o) st += v;
    }
    g_tile_off[lane] = st - nt;
    if (lane == 31) { g_tile_off[NEXP] = st; g_total_tiles = st; }

    float imp = g_importance[lane];
    float s = imp;
    #pragma unroll
    for (int o = 16; o; o >>= 1) s += __shfl_xor_sync(FULL, s, o);
    float mean = s / 32.f;
    float d = imp - mean;
    float ss = d * d;
    #pragma unroll
    for (int o = 16; o; o >>= 1) ss += __shfl_xor_sync(FULL, ss, o);
    float var = ss / 31.f;
    if (lane == 0 && out_size > NTOK * DMODEL)
        out[NTOK * DMODEL] = var / (mean * mean + 1e-9f);
}

// ================= kernel: scatter =================
__global__ void __launch_bounds__(256) scatter_kernel() {
    __shared__ int lcnt[NEXP];
    __shared__ int gbase[NEXP];
    __shared__ int lcur[NEXP];

    const int tid = threadIdx.x;
    const int n = blockIdx.x * 256 + tid;
    if (tid < NEXP) lcnt[tid] = 0;
    __syncthreads();

    int e0 = g_top_e[2 * n];     float v0 = g_top_v[2 * n];
    int e1 = g_top_e[2 * n + 1]; float v1 = g_top_v[2 * n + 1];
    atomicAdd(&lcnt[e0], 1);
    atomicAdd(&lcnt[e1], 1);
    __syncthreads();

    if (tid < NEXP) { gbase[tid] = atomicAdd(&g_cursor[tid], lcnt[tid]); lcur[tid] = 0; }
    __syncthreads();

    int p0 = gbase[e0] + atomicAdd(&lcur[e0], 1);
    g_bucket_tok[p0] = n; g_bucket_w[p0] = v0; g_tok_slot[2 * n] = p0;
    int p1 = gbase[e1] + atomicAdd(&lcur[e1], 1);
    g_bucket_tok[p1] = n; g_bucket_w[p1] = v1; g_tok_slot[2 * n + 1] = p1;
}

// ================= kernel: grouped expert GEMM (HMMA split-bf16, 8 warps m32n64) =================
#define SX   136
#define ROWB (SX * 2)
#define O_XH 0
#define O_XL (128 * ROWB)
#define O_BH (2 * 128 * ROWB)
#define O_BL (3 * 128 * ROWB)
#define O_CH (4 * 128 * ROWB)
#define O_CL (5 * 128 * ROWB)
#define O_TOK (6 * 128 * ROWB)            // 208896
#define O_WSM (O_TOK + 512)
#define O_B1  (O_TOK + 1024)
#define O_B2  (O_TOK + 2048)
#define SMEM_DYN (O_TOK + 2560)           // 211456 bytes

#define NTHR 256

__global__ void __launch_bounds__(NTHR, 1) expert_mma_kernel(
    const float* __restrict__ b1, const float* __restrict__ b2)
{
    const int t = blockIdx.x;
    if (t >= g_total_tiles) return;

    extern __shared__ char smp[];
    const uint32_t sbase = smem_to_u32(smp);
    int*   toks_s = (int*)(smp + O_TOK);
    float* wsm_s  = (float*)(smp + O_WSM);
    float* b1s    = (float*)(smp + O_B1);
    float* b2s    = (float*)(smp + O_B2);

    const int tid = threadIdx.x;
    const int wid = tid >> 5;
    const int lane = tid & 31;

    int e = 0;
    #pragma unroll 1
    while (t >= g_tile_off[e + 1]) ++e;
    const int mtile = t - g_tile_off[e];
    const int off   = g_offsets[e];
    const int cnt   = g_counts[e];
    const int m0g   = mtile * TM;
    const int valid = min(TM, cnt - m0g);

    if (tid < 128) {
        if (tid < valid) {
            toks_s[tid] = g_bucket_tok[off + m0g + tid];
            wsm_s[tid]  = g_bucket_w[off + m0g + tid];
        } else { toks_s[tid] = 0; wsm_s[tid] = 0.f; }
        b2s[tid] = b2[e * DMODEL + tid];
    }
    b1s[tid] = b1[e * HDIM + tid];
    __syncthreads();

    // ---- async gather X rows (bf16 hi/lo) ----
    #pragma unroll
    for (int i = tid; i < 2048; i += NTHR) {
        int r = i >> 4, ch = i & 15;
        const size_t src = (size_t)toks_s[r] * DMODEL + ch * 8;
        uint32_t dst = sbase + r * ROWB + ch * 16;
        cp16(dst + O_XH, g_xhi + src);
        cp16(dst + O_XL, g_xlo + src);
    }
    CP_COMMIT();

    const size_t w1base = (size_t)e * HDIM * DMODEL;
    const size_t w2base = (size_t)e * DMODEL * HDIM;

    // ---- async load W1 chunk 0 ----
    #pragma unroll
    for (int i = tid; i < 2048; i += NTHR) {
        int r = i >> 4, ch = i & 15;
        size_t src = w1base + (size_t)r * DMODEL + ch * 8;
        uint32_t dst = sbase + r * ROWB + ch * 16;
        cp16(dst + O_BH, g_w1hi + src);
        cp16(dst + O_BL, g_w1lo + src);
    }
    CP_COMMIT();
    CP_WAIT0();
    __syncthreads();

    // warp tiling: 4 m-warps x 2 n-warps, warp tile m32 x n64
    const int m0 = (wid >> 1) * 32;
    const int nw = wid & 1;
    const uint32_t arow  = m0 + (lane & 15);
    const uint32_t acolb = ((lane >> 4) & 1) * 16;
    const uint32_t brow0 = nw * 64 + ((lane >> 4) & 1) * 8 + (lane & 7);
    const uint32_t bcolb = ((lane >> 3) & 1) * 16;

    // acc layout: [msub*8 + jn][4], msub in {0,1} (rows m0+16*msub), jn n-sub of 8 cols
    float acc2[16][4];
    #pragma unroll
    for (int j = 0; j < 16; ++j)
        #pragma unroll
        for (int q = 0; q < 4; ++q) acc2[j][q] = 0.f;

    #pragma unroll 1
    for (int c = 0; c < 2; ++c) {
        // ---- FC1: acc1 = X @ W1chunk^T (m32 x n64 per warp) ----
        float acc1[16][4];
        #pragma unroll
        for (int j = 0; j < 16; ++j)
            #pragma unroll
            for (int q = 0; q < 4; ++q) acc1[j][q] = 0.f;

        #pragma unroll 1
        for (int k = 0; k < 8; ++k) {
            uint32_t aaddr0 = sbase + O_XH + arow * ROWB + k * 32 + acolb;
            uint32_t aaddr1 = aaddr0 + 16 * ROWB;
            uint32_t ah[8], al[8];
            ldsm4(ah[0], ah[1], ah[2], ah[3], aaddr0);
            ldsm4(ah[4], ah[5], ah[6], ah[7], aaddr1);
            ldsm4(al[0], al[1], al[2], al[3], aaddr0 + (O_XL - O_XH));
            ldsm4(al[4], al[5], al[6], al[7], aaddr1 + (O_XL - O_XH));
            #pragma unroll
            for (int jp = 0; jp < 4; ++jp) {
                uint32_t baddr = sbase + O_BH + (brow0 + jp * 16) * ROWB + k * 32 + bcolb;
                uint32_t bh0, bh1, bh2, bh3, bl0, bl1, bl2, bl3;
                ldsm4(bh0, bh1, bh2, bh3, baddr);
                ldsm4(bl0, bl1, bl2, bl3, baddr + (O_BL - O_BH));
                #pragma unroll
                for (int ms = 0; ms < 2; ++ms) {
                    float* c0 = acc1[ms * 8 + 2 * jp];
                    float* c1 = acc1[ms * 8 + 2 * jp + 1];
                    const uint32_t* A = ah + ms * 4;
                    const uint32_t* L = al + ms * 4;
                    mma16816(c0, A[0], A[1], A[2], A[3], bh0, bh1);
                    mma16816(c0, A[0], A[1], A[2], A[3], bl0, bl1);
                    mma16816(c0, L[0], L[1], L[2], L[3], bh0, bh1);
                    mma16816(c1, A[0], A[1], A[2], A[3], bh2, bh3);
                    mma16816(c1, A[0], A[1], A[2], A[3], bl2, bl3);
                    mma16816(c1, L[0], L[1], L[2], L[3], bh2, bh3);
                }
            }
        }
        __syncthreads();   // all warps done reading B (W1 chunk)

        // ---- prefetch W2 chunk c into B (overlaps epilogue 1) ----
        #pragma unroll
        for (int i = tid; i < 2048; i += NTHR) {
            int r = i >> 4, ch = i & 15;
            size_t src = w2base + (size_t)r * HDIM + c * 128 + ch * 8;
            uint32_t dst = sbase + r * ROWB + ch * 16;
            cp16(dst + O_BH, g_w2hi + src);
            cp16(dst + O_BL, g_w2lo + src);
        }
        CP_COMMIT();

        // ---- epilogue 1: relu(acc1 + b1) -> split hi/lo into C ----
        {
            const int cb = (lane & 3) * 2;
            #pragma unroll
            for (int ms = 0; ms < 2; ++ms) {
                const int r0 = m0 + ms * 16 + (lane >> 2);
                #pragma unroll
                for (int jn = 0; jn < 8; ++jn) {
                    const float* a = acc1[ms * 8 + jn];
                    int coll = nw * 64 + jn * 8 + cb;
                    int colg = c * 128 + coll;
                    float bb0 = b1s[colg], bb1 = b1s[colg + 1];
                    float f0 = fmaxf(a[0] + bb0, 0.f);
                    float f1 = fmaxf(a[1] + bb1, 0.f);
                    float f2 = fmaxf(a[2] + bb0, 0.f);
                    float f3 = fmaxf(a[3] + bb1, 0.f);
                    __nv_bfloat16 h0,l0,h1,l1,h2,l2,h3,l3;
                    split2(f0,h0,l0); split2(f1,h1,l1); split2(f2,h2,l2); split2(f3,h3,l3);
                    int d0 = r0 * ROWB + coll * 2;
                    int d1 = (r0 + 8) * ROWB + coll * 2;
                    *reinterpret_cast<uint32_t*>(smp + O_CH + d0) = packbf(h0, h1);
                    *reinterpret_cast<uint32_t*>(smp + O_CL + d0) = packbf(l0, l1);
                    *reinterpret_cast<uint32_t*>(smp + O_CH + d1) = packbf(h2, h3);
                    *reinterpret_cast<uint32_t*>(smp + O_CL + d1) = packbf(l2, l3);
                }
            }
        }
        CP_WAIT0();
        __syncthreads();   // W2 chunk ready, h visible

        // ---- FC2: acc2 += h_chunk @ W2chunk^T ----
        #pragma unroll 1
        for (int k = 0; k < 8; ++k) {
            uint32_t aaddr0 = sbase + O_CH + arow * ROWB + k * 32 + acolb;
            uint32_t aaddr1 = aaddr0 + 16 * ROWB;
            uint32_t ah[8], al[8];
            ldsm4(ah[0], ah[1], ah[2], ah[3], aaddr0);
            ldsm4(ah[4], ah[5], ah[6], ah[7], aaddr1);
            ldsm4(al[0], al[1], al[2], al[3], aaddr0 + (O_CL - O_CH));
            ldsm4(al[4], al[5], al[6], al[7], aaddr1 + (O_CL - O_CH));
            #pragma unroll
            for (int jp = 0; jp < 4; ++jp) {
                uint32_t baddr = sbase + O_BH + (brow0 + jp * 16) * ROWB + k * 32 + bcolb;
                uint32_t bh0, bh1, bh2, bh3, bl0, bl1, bl2, bl3;
                ldsm4(bh0, bh1, bh2, bh3, baddr);
                ldsm4(bl0, bl1, bl2, bl3, baddr + (O_BL - O_BH));
                #pragma unroll
                for (int ms = 0; ms < 2; ++ms) {
                    float* c0 = acc2[ms * 8 + 2 * jp];
                    float* c1 = acc2[ms * 8 + 2 * jp + 1];
                    const uint32_t* A = ah + ms * 4;
                    const uint32_t* L = al + ms * 4;
                    mma16816(c0, A[0], A[1], A[2], A[3], bh0, bh1);
                    mma16816(c0, A[0], A[1], A[2], A[3], bl0, bl1);
                    mma16816(c0, L[0], L[1], L[2], L[3], bh0, bh1);
                    mma16816(c1, A[0], A[1], A[2], A[3], bh2, bh3);
                    mma16816(c1, A[0], A[1], A[2], A[3], bl2, bl3);
                    mma16816(c1, L[0], L[1], L[2], L[3], bh2, bh3);
                }
            }
        }
        __syncthreads();   // done reading B & C

        // ---- prefetch W1 chunk 1 into B ----
        if (c == 0) {
            #pragma unroll
            for (int i = tid; i < 2048; i += NTHR) {
                int r = i >> 4, ch = i & 15;
                size_t src = w1base + (size_t)(128 + r) * DMODEL + ch * 8;
                uint32_t dst = sbase + r * ROWB + ch * 16;
                cp16(dst + O_BH, g_w1hi + src);
                cp16(dst + O_BL, g_w1lo + src);
            }
            CP_COMMIT();
            CP_WAIT0();
            __syncthreads();
        }
    }

    // ---- epilogue 2: w * (acc2 + b2) -> g_partial ----
    {
        const int cb = (lane & 3) * 2;
        #pragma unroll
        for (int ms = 0; ms < 2; ++ms) {
            const int r0 = m0 + ms * 16 + (lane >> 2);
            const int r1 = r0 + 8;
            const float w0 = (r0 < valid) ? wsm_s[r0] : 0.f;
            const float w1 = (r1 < valid) ? wsm_s[r1] : 0.f;
            const size_t s0 = (size_t)(off + m0g + r0) * DMODEL;
            const size_t s1 = (size_t)(off + m0g + r1) * DMODEL;
            #pragma unroll
            for (int jn = 0; jn < 8; ++jn) {
                const float* a = acc2[ms * 8 + jn];
                int col = nw * 64 + jn * 8 + cb;
                float bb0 = b2s[col], bb1 = b2s[col + 1];
                if (r0 < valid) {
                    float2 o;
                    o.x = w0 * (a[0] + bb0);
                    o.y = w0 * (a[1] + bb1);
                    *reinterpret_cast<float2*>(&g_partial[s0 + col]) = o;
                }
                if (r1 < valid) {
                    float2 o;
                    o.x = w1 * (a[2] + bb0);
                    o.y = w1 * (a[3] + bb1);
                    *reinterpret_cast<float2*>(&g_partial[s1 + col]) = o;
                }
            }
        }
    }
}

// ================= kernel: combine =================
__global__ void __launch_bounds__(256) combine_kernel(float* __restrict__ out) {
    int gid = blockIdx.x * 256 + threadIdx.x;
    int n = gid >> 5;
    int q = gid & 31;
    int s0 = g_tok_slot[2 * n];
    int s1 = g_tok_slot[2 * n + 1];
    const float4* P = reinterpret_cast<const float4*>(g_partial);
    float4 p0 = P[(size_t)s0 * 32 + q];
    float4 p1 = P[(size_t)s1 * 32 + q];
    float4 o;
    o.x = p0.x + p1.x; o.y = p0.y + p1.y;
    o.z = p0.z + p1.z; o.w = p0.w + p1.w;
    reinterpret_cast<float4*>(out)[(size_t)n * 32 + q] = o;
}

// ================= launch =================
extern "C" void kernel_launch(void* const* d_in, const int* in_sizes, int n_in,
                              void* d_out, int out_size) {
    const float* x  = (const float*)d_in[0];
    const float* W1 = (const float*)d_in[1];
    const float* b1 = (const float*)d_in[2];
    const float* W2 = (const float*)d_in[3];
    const float* b2 = (const float*)d_in[4];
    const float* Wr = (const float*)d_in[5];
    const float* br = (const float*)d_in[6];
    float* out = (float*)d_out;

    cudaFuncSetAttribute(expert_mma_kernel,
                         cudaFuncAttributeMaxDynamicSharedMemorySize, SMEM_DYN);

    convert_x_kernel<<<NTOK * DMODEL / (256 * 8), 256>>>(x);
    convert_w_kernel<<<NEXP * HDIM * DMODEL / 256, 256>>>(W1, W2);
    router_kernel<<<NTOK / 256, 256>>>(x, Wr, br);
    scan_loss_kernel<<<1, 32>>>(out, out_size);
    scatter_kernel<<<NTOK / 256, 256>>>();
    expert_mma_kernel<<<1056, NTHR, SMEM_DYN>>>(b1, b2);
    combine_kernel<<<(NTOK * 32) / 256, 256>>>(out);
}

// round 7
// speedup vs baseline: 2.7992x; 1.0155x over previous
#include <cuda_runtime.h>
#include <cuda_bf16.h>
#include <math.h>
#include <stdint.h>

#define NTOK   65536
#define DMODEL 128
#define HDIM   256
#define NEXP   32
#define TM     64

// ================= helpers =================
__device__ __forceinline__ uint32_t smem_to_u32(const void* p) {
    uint32_t a;
    asm("{ .reg .u64 t; cvta.to.shared.u64 t, %1; cvt.u32.u64 %0, t; }" : "=r"(a) : "l"(p));
    return a;
}
__device__ __forceinline__ void ldsm4(uint32_t& r0, uint32_t& r1, uint32_t& r2, uint32_t& r3,
                                      uint32_t addr) {
    asm volatile("ldmatrix.sync.aligned.m8n8.x4.shared.b16 {%0,%1,%2,%3}, [%4];"
                 : "=r"(r0), "=r"(r1), "=r"(r2), "=r"(r3) : "r"(addr));
}
__device__ __forceinline__ void mma16816(float* c, uint32_t a0, uint32_t a1, uint32_t a2,
                                         uint32_t a3, uint32_t b0, uint32_t b1) {
    asm volatile("mma.sync.aligned.m16n8k16.row.col.f32.bf16.bf16.f32 "
                 "{%0,%1,%2,%3}, {%4,%5,%6,%7}, {%8,%9}, {%0,%1,%2,%3};"
                 : "+f"(c[0]), "+f"(c[1]), "+f"(c[2]), "+f"(c[3])
                 : "r"(a0), "r"(a1), "r"(a2), "r"(a3), "r"(b0), "r"(b1));
}
__device__ __forceinline__ void cp16(uint32_t dst, const void* src) {
    asm volatile("cp.async.cg.shared.global [%0], [%1], 16;" :: "r"(dst), "l"(src) : "memory");
}
#define CP_COMMIT() asm volatile("cp.async.commit_group;" ::: "memory")
#define CP_WAIT0()  asm volatile("cp.async.wait_group 0;" ::: "memory")

__device__ __forceinline__ void split2(float v, __nv_bfloat16& hi, __nv_bfloat16& lo) {
    hi = __float2bfloat16(v);
    lo = __float2bfloat16(v - __bfloat162float(hi));
}
__device__ __forceinline__ uint32_t packbf(__nv_bfloat16 a, __nv_bfloat16 b) {
    __nv_bfloat162 t(a, b);
    return *reinterpret_cast<uint32_t*>(&t);
}

// ================= device scratch =================
__device__ float g_top_v[2 * NTOK];
__device__ int   g_top_e[2 * NTOK];
__device__ float g_importance[NEXP];
__device__ int   g_counts[NEXP];
__device__ int   g_offsets[NEXP + 1];
__device__ int   g_cursor[NEXP];
__device__ int   g_tile_off[NEXP + 1];
__device__ int   g_total_tiles;
__device__ int   g_bucket_tok[2 * NTOK];
__device__ float g_bucket_w[2 * NTOK];
__device__ int   g_tok_slot[2 * NTOK];
__device__ float g_partial[(size_t)2 * NTOK * DMODEL];

__device__ __align__(16) __nv_bfloat16 g_xhi[NTOK * DMODEL];
__device__ __align__(16) __nv_bfloat16 g_xlo[NTOK * DMODEL];
__device__ __align__(16) __nv_bfloat16 g_w1hi[NEXP * HDIM * DMODEL];   // [E,H,D]
__device__ __align__(16) __nv_bfloat16 g_w1lo[NEXP * HDIM * DMODEL];
__device__ __align__(16) __nv_bfloat16 g_w2hi[NEXP * DMODEL * HDIM];   // [E,D,H]
__device__ __align__(16) __nv_bfloat16 g_w2lo[NEXP * DMODEL * HDIM];

// ================= kernel: convert x -> bf16 hi/lo (+ init in block 0) =================
__global__ void __launch_bounds__(256) convert_x_kernel(const float* __restrict__ x) {
    if (blockIdx.x == 0 && threadIdx.x < NEXP) {
        g_counts[threadIdx.x] = 0;
        g_importance[threadIdx.x] = 0.f;
    }
    size_t i = ((size_t)blockIdx.x * 256 + threadIdx.x) * 8;
    float4 a = *reinterpret_cast<const float4*>(x + i);
    float4 b = *reinterpret_cast<const float4*>(x + i + 4);
    float v[8] = {a.x, a.y, a.z, a.w, b.x, b.y, b.z, b.w};
    __nv_bfloat16 hi[8], lo[8];
    #pragma unroll
    for (int q = 0; q < 8; ++q) split2(v[q], hi[q], lo[q]);
    uint4 ph, pl;
    ph.x = packbf(hi[0], hi[1]); ph.y = packbf(hi[2], hi[3]);
    ph.z = packbf(hi[4], hi[5]); ph.w = packbf(hi[6], hi[7]);
    pl.x = packbf(lo[0], lo[1]); pl.y = packbf(lo[2], lo[3]);
    pl.z = packbf(lo[4], lo[5]); pl.w = packbf(lo[6], lo[7]);
    *reinterpret_cast<uint4*>(g_xhi + i) = ph;
    *reinterpret_cast<uint4*>(g_xlo + i) = pl;
}

// ================= kernel: convert + transpose weights =================
__global__ void __launch_bounds__(256) convert_w_kernel(const float* __restrict__ W1,
                                                        const float* __restrict__ W2) {
    int idx = blockIdx.x * 256 + threadIdx.x;
    {   // W1T[e][h][d] = W1[e][d][h]
        int d = idx & 127, h = (idx >> 7) & 255, e = idx >> 15;
        float v = W1[((size_t)e * 128 + d) * 256 + h];
        __nv_bfloat16 hi, lo; split2(v, hi, lo);
        g_w1hi[idx] = hi; g_w1lo[idx] = lo;
    }
    {   // W2T[e][d][h] = W2[e][h][d]
        int h = idx & 255, d = (idx >> 8) & 127, e = idx >> 15;
        float v = W2[((size_t)e * 256 + h) * 128 + d];
        __nv_bfloat16 hi, lo; split2(v, hi, lo);
        g_w2hi[idx] = hi; g_w2lo[idx] = lo;
    }
}

// ================= kernel: router (thread per token, shuffle-free) =================
__global__ void __launch_bounds__(256) router_kernel(
    const float* __restrict__ x, const float* __restrict__ Wr,
    const float* __restrict__ br)
{
    __shared__ float wr_s[DMODEL * NEXP];
    __shared__ float br_s[NEXP];
    __shared__ float imp_s[NEXP];
    __shared__ int   cnt_s[NEXP];

    const int tid = threadIdx.x;
    if (tid < NEXP) { imp_s[tid] = 0.f; cnt_s[tid] = 0; br_s[tid] = br[tid]; }
    #pragma unroll
    for (int i = tid; i < DMODEL * NEXP; i += 256) wr_s[i] = Wr[i];
    __syncthreads();

    const int n = blockIdx.x * 256 + tid;

    float acc[NEXP];
    #pragma unroll
    for (int e = 0; e < NEXP; ++e) acc[e] = br_s[e];

    const float4* xrow = reinterpret_cast<const float4*>(x + (size_t)n * DMODEL);
    float4 xv = xrow[0];
    #pragma unroll 4
    for (int ch = 0; ch < 32; ++ch) {
        float4 xn;
        if (ch < 31) xn = xrow[ch + 1];
        float xd[4] = {xv.x, xv.y, xv.z, xv.w};
        #pragma unroll
        for (int dd = 0; dd < 4; ++dd) {
            const float4* wrow = reinterpret_cast<const float4*>(&wr_s[(ch * 4 + dd) * NEXP]);
            #pragma unroll
            for (int e4 = 0; e4 < 8; ++e4) {
                float4 w = wrow[e4];
                acc[e4 * 4 + 0] = fmaf(xd[dd], w.x, acc[e4 * 4 + 0]);
                acc[e4 * 4 + 1] = fmaf(xd[dd], w.y, acc[e4 * 4 + 1]);
                acc[e4 * 4 + 2] = fmaf(xd[dd], w.z, acc[e4 * 4 + 2]);
                acc[e4 * 4 + 3] = fmaf(xd[dd], w.w, acc[e4 * 4 + 3]);
            }
        }
        xv = xn;
    }

    float mx = acc[0];
    #pragma unroll
    for (int e = 1; e < NEXP; ++e) mx = fmaxf(mx, acc[e]);
    float s = 0.f;
    #pragma unroll
    for (int e = 0; e < NEXP; ++e) { acc[e] = expf(acc[e] - mx); s += acc[e]; }
    float inv = 1.f / s;
    #pragma unroll
    for (int e = 0; e < NEXP; ++e) acc[e] *= inv;

    float v1 = acc[0]; int i1 = 0;
    #pragma unroll
    for (int e = 1; e < NEXP; ++e) if (acc[e] > v1) { v1 = acc[e]; i1 = e; }
    float v2 = -1.f; int i2 = 0;
    #pragma unroll
    for (int e = 0; e < NEXP; ++e) {
        bool ok = (e != i1) && (acc[e] > v2);
        if (ok) { v2 = acc[e]; i2 = e; }
    }

    g_top_e[2 * n]     = i1;  g_top_v[2 * n]     = v1;
    g_top_e[2 * n + 1] = i2;  g_top_v[2 * n + 1] = v2;
    atomicAdd(&imp_s[i1], v1);
    atomicAdd(&imp_s[i2], v2);
    atomicAdd(&cnt_s[i1], 1);
    atomicAdd(&cnt_s[i2], 1);

    __syncthreads();
    if (tid < NEXP) {
        atomicAdd(&g_importance[tid], imp_s[tid]);
        atomicAdd(&g_counts[tid], cnt_s[tid]);
    }
}

// ================= kernel: scan + loss =================
__global__ void scan_loss_kernel(float* __restrict__ out, int out_size) {
    const int lane = threadIdx.x;
    const unsigned FULL = 0xffffffffu;

    int c = g_counts[lane];
    int sc = c;
    #pragma unroll
    for (int o = 1; o < 32; o <<= 1) {
        int v = __shfl_up_sync(FULL, sc, o);
        if (lane >= o) sc += v;
    }
    g_offsets[lane] = sc - c;
    g_cursor[lane]  = sc - c;
    if (lane == 31) g_offsets[NEXP] = sc;

    int nt = (c + TM - 1) / TM;
    int st = nt;
    #pragma unroll
    for (int o = 1; o < 32; o <<= 1) {
        int v = __shfl_up_sync(FULL, st, o);
        if (lane >= o) st += v;
    }
    g_tile_off[lane] = st - nt;
    if (lane == 31) { g_tile_off[NEXP] = st; g_total_tiles = st; }

    float imp = g_importance[lane];
    float s = imp;
    #pragma unroll
    for (int o = 16; o; o >>= 1) s += __shfl_xor_sync(FULL, s, o);
    float mean = s / 32.f;
    float d = imp - mean;
    float ss = d * d;
    #pragma unroll
    for (int o = 16; o; o >>= 1) ss += __shfl_xor_sync(FULL, ss, o);
    float var = ss / 31.f;
    if (lane == 0 && out_size > NTOK * DMODEL)
        out[NTOK * DMODEL] = var / (mean * mean + 1e-9f);
}

// ================= kernel: scatter =================
__global__ void __launch_bounds__(256) scatter_kernel() {
    __shared__ int lcnt[NEXP];
    __shared__ int gbase[NEXP];
    __shared__ int lcur[NEXP];

    const int tid = threadIdx.x;
    const int n = blockIdx.x * 256 + tid;
    if (tid < NEXP) lcnt[tid] = 0;
    __syncthreads();

    int e0 = g_top_e[2 * n];     float v0 = g_top_v[2 * n];
    int e1 = g_top_e[2 * n + 1]; float v1 = g_top_v[2 * n + 1];
    atomicAdd(&lcnt[e0], 1);
    atomicAdd(&lcnt[e1], 1);
    __syncthreads();

    if (tid < NEXP) { gbase[tid] = atomicAdd(&g_cursor[tid], lcnt[tid]); lcur[tid] = 0; }
    __syncthreads();

    int p0 = gbase[e0] + atomicAdd(&lcur[e0], 1);
    g_bucket_tok[p0] = n; g_bucket_w[p0] = v0; g_tok_slot[2 * n] = p0;
    int p1 = gbase[e1] + atomicAdd(&lcur[e1], 1);
    g_bucket_tok[p1] = n; g_bucket_w[p1] = v1; g_tok_slot[2 * n + 1] = p1;
}

// ================= kernel: grouped expert GEMM (TM=64, 2 CTAs/SM) =================
// X   : [64, 128] bf16 hi/lo, row stride 272B
// Wbuf: FC1 chunk [64h, 128d] stride 272 (17408/comp) OR FC2 chunk [128d, 64h] stride 144 (18432/comp)
// Cbuf: h chunk [64, 64] stride 144 (9216/comp)
#define RW128 272
#define RW64  144
#define O_XH  0
#define O_XL  17408
#define O_BH  34816
#define O_BL  (34816 + 18432)     // 53248
#define O_CH  71680
#define O_CL  (71680 + 9216)      // 80896
#define O_TOK 90112
#define O_WSM (O_TOK + 256)
#define O_B1  (O_TOK + 512)
#define O_B2  (O_TOK + 1536)
#define SMEM_DYN (O_TOK + 2048)   // 92160

#define NTHR 256

__global__ void __launch_bounds__(NTHR, 2) expert_mma_kernel(
    const float* __restrict__ b1, const float* __restrict__ b2)
{
    const int t = blockIdx.x;
    if (t >= g_total_tiles) return;

    extern __shared__ char smp[];
    const uint32_t sbase = smem_to_u32(smp);
    int*   toks_s = (int*)(smp + O_TOK);
    float* wsm_s  = (float*)(smp + O_WSM);
    float* b1s    = (float*)(smp + O_B1);
    float* b2s    = (float*)(smp + O_B2);

    const int tid = threadIdx.x;
    const int wid = tid >> 5;
    const int lane = tid & 31;

    int e = 0;
    #pragma unroll 1
    while (t >= g_tile_off[e + 1]) ++e;
    const int mtile = t - g_tile_off[e];
    const int off   = g_offsets[e];
    const int cnt   = g_counts[e];
    const int m0g   = mtile * TM;
    const int valid = min(TM, cnt - m0g);

    if (tid < 64) {
        if (tid < valid) {
            toks_s[tid] = g_bucket_tok[off + m0g + tid];
            wsm_s[tid]  = g_bucket_w[off + m0g + tid];
        } else { toks_s[tid] = 0; wsm_s[tid] = 0.f; }
    }
    if (tid < 128) b2s[tid] = b2[e * DMODEL + tid];
    b1s[tid] = b1[e * HDIM + tid];
    __syncthreads();

    // ---- async gather X rows [64,128] hi/lo ----
    #pragma unroll
    for (int i = tid; i < 1024; i += NTHR) {
        int r = i >> 4, ch = i & 15;
        const size_t src = (size_t)toks_s[r] * DMODEL + ch * 8;
        uint32_t dst = sbase + r * RW128 + ch * 16;
        cp16(dst + O_XH, g_xhi + src);
        cp16(dst + O_XL, g_xlo + src);
    }

    const size_t w1base = (size_t)e * HDIM * DMODEL;
    const size_t w2base = (size_t)e * DMODEL * HDIM;

    // ---- async load W1 chunk 0: [64h, 128d] ----
    #pragma unroll
    for (int i = tid; i < 1024; i += NTHR) {
        int r = i >> 4, ch = i & 15;
        size_t src = w1base + (size_t)r * DMODEL + ch * 8;
        uint32_t dst = sbase + r * RW128 + ch * 16;
        cp16(dst + O_BH, g_w1hi + src);
        cp16(dst + O_BL, g_w1lo + src);
    }
    CP_COMMIT();
    CP_WAIT0();
    __syncthreads();

    // warp tiling: 4 m-warps (16 rows) x 2 n-warps
    const int m0 = (wid >> 1) * 16;
    const int nw = wid & 1;
    const uint32_t arow  = m0 + (lane & 15);
    const uint32_t acolb = ((lane >> 4) & 1) * 16;
    const uint32_t brsub = ((lane >> 4) & 1) * 8 + (lane & 7);
    const uint32_t bcolb = ((lane >> 3) & 1) * 16;

    float acc2[8][4];                       // FC2: n64 per warp
    #pragma unroll
    for (int j = 0; j < 8; ++j)
        #pragma unroll
        for (int q = 0; q < 4; ++q) acc2[j][q] = 0.f;

    #pragma unroll 1
    for (int c = 0; c < 4; ++c) {
        // ---- FC1: h_c[64,64] = X[64,128] @ W1c[64,128]^T ; warp: m16 x n32 ----
        float acc1[4][4];
        #pragma unroll
        for (int j = 0; j < 4; ++j)
            #pragma unroll
            for (int q = 0; q < 4; ++q) acc1[j][q] = 0.f;

        #pragma unroll 1
        for (int k = 0; k < 8; ++k) {
            uint32_t aaddr = sbase + O_XH + arow * RW128 + k * 32 + acolb;
            uint32_t ah0, ah1, ah2, ah3, al0, al1, al2, al3;
            ldsm4(ah0, ah1, ah2, ah3, aaddr);
            ldsm4(al0, al1, al2, al3, aaddr + (O_XL - O_XH));
            #pragma unroll
            for (int jp = 0; jp < 2; ++jp) {
                uint32_t brow = nw * 32 + jp * 16 + brsub;
                uint32_t baddr = sbase + O_BH + brow * RW128 + k * 32 + bcolb;
                uint32_t bh0, bh1, bh2, bh3, bl0, bl1, bl2, bl3;
                ldsm4(bh0, bh1, bh2, bh3, baddr);
                ldsm4(bl0, bl1, bl2, bl3, baddr + (O_BL - O_BH));
                float* c0 = acc1[2 * jp];
                float* c1 = acc1[2 * jp + 1];
                mma16816(c0, ah0, ah1, ah2, ah3, bh0, bh1);
                mma16816(c0, ah0, ah1, ah2, ah3, bl0, bl1);
                mma16816(c0, al0, al1, al2, al3, bh0, bh1);
                mma16816(c1, ah0, ah1, ah2, ah3, bh2, bh3);
                mma16816(c1, ah0, ah1, ah2, ah3, bl2, bl3);
                mma16816(c1, al0, al1, al2, al3, bh2, bh3);
            }
        }
        __syncthreads();   // W1c consumed

        // ---- prefetch W2 chunk c: [128d, 64h] into B (overlaps epilogue) ----
        #pragma unroll
        for (int i = tid; i < 1024; i += NTHR) {
            int r = i >> 3, ch = i & 7;
            size_t src = w2base + (size_t)r * HDIM + c * 64 + ch * 8;
            uint32_t dst = sbase + r * RW64 + ch * 16;
            cp16(dst + O_BH, g_w2hi + src);
            cp16(dst + O_BL, g_w2lo + src);
        }
        CP_COMMIT();

        // ---- epilogue 1: relu(acc1 + b1) -> split into C [64,64] ----
        {
            const int r0 = m0 + (lane >> 2);
            const int cb = (lane & 3) * 2;
            #pragma unroll
            for (int jn = 0; jn < 4; ++jn) {
                const float* a = acc1[jn];
                int coll = nw * 32 + jn * 8 + cb;          // local col 0..63
                int colg = c * 64 + coll;                   // global h col
                float bb0 = b1s[colg], bb1 = b1s[colg + 1];
                float f0 = fmaxf(a[0] + bb0, 0.f);
                float f1 = fmaxf(a[1] + bb1, 0.f);
                float f2 = fmaxf(a[2] + bb0, 0.f);
                float f3 = fmaxf(a[3] + bb1, 0.f);
                __nv_bfloat16 h0,l0,h1,l1,h2,l2,h3,l3;
                split2(f0,h0,l0); split2(f1,h1,l1); split2(f2,h2,l2); split2(f3,h3,l3);
                int d0 = r0 * RW64 + coll * 2;
                int d1 = (r0 + 8) * RW64 + coll * 2;
                *reinterpret_cast<uint32_t*>(smp + O_CH + d0) = packbf(h0, h1);
                *reinterpret_cast<uint32_t*>(smp + O_CL + d0) = packbf(l0, l1);
                *reinterpret_cast<uint32_t*>(smp + O_CH + d1) = packbf(h2, h3);
                *reinterpret_cast<uint32_t*>(smp + O_CL + d1) = packbf(l2, l3);
            }
        }
        CP_WAIT0();
        __syncthreads();   // W2c ready, h visible

        // ---- FC2: acc2 += h_c[64,64] @ W2c[128,64]^T ; warp: m16 x n64 ----
        #pragma unroll 1
        for (int k = 0; k < 4; ++k) {
            uint32_t aaddr = sbase + O_CH + arow * RW64 + k * 32 + acolb;
            uint32_t ah0, ah1, ah2, ah3, al0, al1, al2, al3;
            ldsm4(ah0, ah1, ah2, ah3, aaddr);
            ldsm4(al0, al1, al2, al3, aaddr + (O_CL - O_CH));
            #pragma unroll
            for (int jp = 0; jp < 4; ++jp) {
                uint32_t brow = nw * 64 + jp * 16 + brsub;
                uint32_t baddr = sbase + O_BH + brow * RW64 + k * 32 + bcolb;
                uint32_t bh0, bh1, bh2, bh3, bl0, bl1, bl2, bl3;
                ldsm4(bh0, bh1, bh2, bh3, baddr);
                ldsm4(bl0, bl1, bl2, bl3, baddr + (O_BL - O_BH));
                float* c0 = acc2[2 * jp];
                float* c1 = acc2[2 * jp + 1];
                mma16816(c0, ah0, ah1, ah2, ah3, bh0, bh1);
                mma16816(c0, ah0, ah1, ah2, ah3, bl0, bl1);
                mma16816(c0, al0, al1, al2, al3, bh0, bh1);
                mma16816(c1, ah0, ah1, ah2, ah3, bh2, bh3);
                mma16816(c1, ah0, ah1, ah2, ah3, bl2, bl3);
                mma16816(c1, al0, al1, al2, al3, bh2, bh3);
            }
        }
        __syncthreads();   // W2c + C consumed

        // ---- prefetch W1 chunk c+1 ----
        if (c < 3) {
            #pragma unroll
            for (int i = tid; i < 1024; i += NTHR) {
                int r = i >> 4, ch = i & 15;
                size_t src = w1base + (size_t)((c + 1) * 64 + r) * DMODEL + ch * 8;
                uint32_t dst = sbase + r * RW128 + ch * 16;
                cp16(dst + O_BH, g_w1hi + src);
                cp16(dst + O_BL, g_w1lo + src);
            }
            CP_COMMIT();
            CP_WAIT0();
            __syncthreads();
        }
    }

    // ---- epilogue 2: w * (acc2 + b2) -> g_partial ----
    {
        const int cb = (lane & 3) * 2;
        const int r0 = m0 + (lane >> 2);
        const int r1 = r0 + 8;
        const float w0 = (r0 < valid) ? wsm_s[r0] : 0.f;
        const float w1 = (r1 < valid) ? wsm_s[r1] : 0.f;
        const size_t s0 = (size_t)(off + m0g + r0) * DMODEL;
        const size_t s1 = (size_t)(off + m0g + r1) * DMODEL;
        #pragma unroll
        for (int jn = 0; jn < 8; ++jn) {
            const float* a = acc2[jn];
            int col = nw * 64 + jn * 8 + cb;
            float bb0 = b2s[col], bb1 = b2s[col + 1];
            if (r0 < valid) {
                float2 o;
                o.x = w0 * (a[0] + bb0);
                o.y = w0 * (a[1] + bb1);
                *reinterpret_cast<float2*>(&g_partial[s0 + col]) = o;
            }
            if (r1 < valid) {
                float2 o;
                o.x = w1 * (a[2] + bb0);
                o.y = w1 * (a[3] + bb1);
                *reinterpret_cast<float2*>(&g_partial[s1 + col]) = o;
            }
        }
    }
}

// ================= kernel: combine =================
__global__ void __launch_bounds__(256) combine_kernel(float* __restrict__ out) {
    int gid = blockIdx.x * 256 + threadIdx.x;
    int n = gid >> 5;
    int q = gid & 31;
    int s0 = g_tok_slot[2 * n];
    int s1 = g_tok_slot[2 * n + 1];
    const float4* P = reinterpret_cast<const float4*>(g_partial);
    float4 p0 = P[(size_t)s0 * 32 + q];
    float4 p1 = P[(size_t)s1 * 32 + q];
    float4 o;
    o.x = p0.x + p1.x; o.y = p0.y + p1.y;
    o.z = p0.z + p1.z; o.w = p0.w + p1.w;
    reinterpret_cast<float4*>(out)[(size_t)n * 32 + q] = o;
}

// ================= launch =================
extern "C" void kernel_launch(void* const* d_in, const int* in_sizes, int n_in,
                              void* d_out, int out_size) {
    const float* x  = (const float*)d_in[0];
    const float* W1 = (const float*)d_in[1];
    const float* b1 = (const float*)d_in[2];
    const float* W2 = (const float*)d_in[3];
    const float* b2 = (const float*)d_in[4];
    const float* Wr = (const float*)d_in[5];
    const float* br = (const float*)d_in[6];
    float* out = (float*)d_out;

    cudaFuncSetAttribute(expert_mma_kernel,
                         cudaFuncAttributeMaxDynamicSharedMemorySize, SMEM_DYN);

    convert_x_kernel<<<NTOK * DMODEL / (256 * 8), 256>>>(x);
    convert_w_kernel<<<NEXP * HDIM * DMODEL / 256, 256>>>(W1, W2);
    router_kernel<<<NTOK / 256, 256>>>(x, Wr, br);
    scan_loss_kernel<<<1, 32>>>(out, out_size);
    scatter_kernel<<<NTOK / 256, 256>>>();
    // max tiles = 2N/64 + NEXP = 2048 + 32
    expert_mma_kernel<<<2080, NTHR, SMEM_DYN>>>(b1, b2);
    combine_kernel<<<(NTOK * 32) / 256, 256>>>(out);
}

// round 8
// speedup vs baseline: 3.4607x; 1.2363x over previous
#include <cuda_runtime.h>
#include <cuda_fp16.h>
#include <math.h>
#include <stdint.h>

#define NTOK   65536
#define DMODEL 128
#define HDIM   256
#define NEXP   32
#define TM     64

// ================= helpers =================
__device__ __forceinline__ uint32_t smem_to_u32(const void* p) {
    uint32_t a;
    asm("{ .reg .u64 t; cvta.to.shared.u64 t, %1; cvt.u32.u64 %0, t; }" : "=r"(a) : "l"(p));
    return a;
}
__device__ __forceinline__ void ldsm4(uint32_t& r0, uint32_t& r1, uint32_t& r2, uint32_t& r3,
                                      uint32_t addr) {
    asm volatile("ldmatrix.sync.aligned.m8n8.x4.shared.b16 {%0,%1,%2,%3}, [%4];"
                 : "=r"(r0), "=r"(r1), "=r"(r2), "=r"(r3) : "r"(addr));
}
__device__ __forceinline__ void mma16816(float* c, uint32_t a0, uint32_t a1, uint32_t a2,
                                         uint32_t a3, uint32_t b0, uint32_t b1) {
    asm volatile("mma.sync.aligned.m16n8k16.row.col.f32.f16.f16.f32 "
                 "{%0,%1,%2,%3}, {%4,%5,%6,%7}, {%8,%9}, {%0,%1,%2,%3};"
                 : "+f"(c[0]), "+f"(c[1]), "+f"(c[2]), "+f"(c[3])
                 : "r"(a0), "r"(a1), "r"(a2), "r"(a3), "r"(b0), "r"(b1));
}
__device__ __forceinline__ void cp16(uint32_t dst, const void* src) {
    asm volatile("cp.async.cg.shared.global [%0], [%1], 16;" :: "r"(dst), "l"(src) : "memory");
}
#define CP_COMMIT() asm volatile("cp.async.commit_group;" ::: "memory")
#define CP_WAIT0()  asm volatile("cp.async.wait_group 0;" ::: "memory")

__device__ __forceinline__ void split2h(float v, __half& hi, __half& lo) {
    hi = __float2half_rn(v);
    lo = __float2half_rn(v - __half2float(hi));
}
__device__ __forceinline__ uint32_t packh(__half a, __half b) {
    __half2 t(a, b);
    return *reinterpret_cast<uint32_t*>(&t);
}

// ================= device scratch =================
__device__ float g_top_v[2 * NTOK];
__device__ int   g_top_e[2 * NTOK];
__device__ float g_importance[NEXP];
__device__ int   g_counts[NEXP];
__device__ int   g_offsets[NEXP + 1];
__device__ int   g_cursor[NEXP];
__device__ int   g_tile_off[NEXP + 1];
__device__ int   g_total_tiles;
__device__ int   g_bucket_tok[2 * NTOK];
__device__ float g_bucket_w[2 * NTOK];
__device__ int   g_tok_slot[2 * NTOK];
__device__ float g_partial[(size_t)2 * NTOK * DMODEL];

__device__ __align__(16) __half g_xhi[NTOK * DMODEL];
__device__ __align__(16) __half g_xlo[NTOK * DMODEL];
__device__ __align__(16) __half g_w1h[NEXP * HDIM * DMODEL];   // [E,H,D] (transposed)
__device__ __align__(16) __half g_w2h[NEXP * DMODEL * HDIM];   // [E,D,H] (transposed)

// ================= kernel: convert x -> fp16 hi/lo (+ init in block 0) =================
__global__ void __launch_bounds__(256) convert_x_kernel(const float* __restrict__ x) {
    if (blockIdx.x == 0 && threadIdx.x < NEXP) {
        g_counts[threadIdx.x] = 0;
        g_importance[threadIdx.x] = 0.f;
    }
    size_t i = ((size_t)blockIdx.x * 256 + threadIdx.x) * 8;
    float4 a = *reinterpret_cast<const float4*>(x + i);
    float4 b = *reinterpret_cast<const float4*>(x + i + 4);
    float v[8] = {a.x, a.y, a.z, a.w, b.x, b.y, b.z, b.w};
    __half hi[8], lo[8];
    #pragma unroll
    for (int q = 0; q < 8; ++q) split2h(v[q], hi[q], lo[q]);
    uint4 ph, pl;
    ph.x = packh(hi[0], hi[1]); ph.y = packh(hi[2], hi[3]);
    ph.z = packh(hi[4], hi[5]); ph.w = packh(hi[6], hi[7]);
    pl.x = packh(lo[0], lo[1]); pl.y = packh(lo[2], lo[3]);
    pl.z = packh(lo[4], lo[5]); pl.w = packh(lo[6], lo[7]);
    *reinterpret_cast<uint4*>(g_xhi + i) = ph;
    *reinterpret_cast<uint4*>(g_xlo + i) = pl;
}

// ================= kernel: convert + transpose weights (single fp16) =================
__global__ void __launch_bounds__(256) convert_w_kernel(const float* __restrict__ W1,
                                                        const float* __restrict__ W2) {
    int idx = blockIdx.x * 256 + threadIdx.x;
    {   // W1T[e][h][d] = W1[e][d][h]
        int d = idx & 127, h = (idx >> 7) & 255, e = idx >> 15;
        g_w1h[idx] = __float2half_rn(W1[((size_t)e * 128 + d) * 256 + h]);
    }
    {   // W2T[e][d][h] = W2[e][h][d]
        int h = idx & 255, d = (idx >> 8) & 127, e = idx >> 15;
        g_w2h[idx] = __float2half_rn(W2[((size_t)e * 256 + h) * 128 + d]);
    }
}

// ================= kernel: router (thread per token, shuffle-free) =================
__global__ void __launch_bounds__(256) router_kernel(
    const float* __restrict__ x, const float* __restrict__ Wr,
    const float* __restrict__ br)
{
    __shared__ float wr_s[DMODEL * NEXP];
    __shared__ float br_s[NEXP];
    __shared__ float imp_s[NEXP];
    __shared__ int   cnt_s[NEXP];

    const int tid = threadIdx.x;
    if (tid < NEXP) { imp_s[tid] = 0.f; cnt_s[tid] = 0; br_s[tid] = br[tid]; }
    #pragma unroll
    for (int i = tid; i < DMODEL * NEXP; i += 256) wr_s[i] = Wr[i];
    __syncthreads();

    const int n = blockIdx.x * 256 + tid;

    float acc[NEXP];
    #pragma unroll
    for (int e = 0; e < NEXP; ++e) acc[e] = br_s[e];

    const float4* xrow = reinterpret_cast<const float4*>(x + (size_t)n * DMODEL);
    float4 xv = xrow[0];
    #pragma unroll 4
    for (int ch = 0; ch < 32; ++ch) {
        float4 xn;
        if (ch < 31) xn = xrow[ch + 1];
        float xd[4] = {xv.x, xv.y, xv.z, xv.w};
        #pragma unroll
        for (int dd = 0; dd < 4; ++dd) {
            const float4* wrow = reinterpret_cast<const float4*>(&wr_s[(ch * 4 + dd) * NEXP]);
            #pragma unroll
            for (int e4 = 0; e4 < 8; ++e4) {
                float4 w = wrow[e4];
                acc[e4 * 4 + 0] = fmaf(xd[dd], w.x, acc[e4 * 4 + 0]);
                acc[e4 * 4 + 1] = fmaf(xd[dd], w.y, acc[e4 * 4 + 1]);
                acc[e4 * 4 + 2] = fmaf(xd[dd], w.z, acc[e4 * 4 + 2]);
                acc[e4 * 4 + 3] = fmaf(xd[dd], w.w, acc[e4 * 4 + 3]);
            }
        }
        xv = xn;
    }

    float mx = acc[0];
    #pragma unroll
    for (int e = 1; e < NEXP; ++e) mx = fmaxf(mx, acc[e]);
    float s = 0.f;
    #pragma unroll
    for (int e = 0; e < NEXP; ++e) { acc[e] = expf(acc[e] - mx); s += acc[e]; }
    float inv = 1.f / s;
    #pragma unroll
    for (int e = 0; e < NEXP; ++e) acc[e] *= inv;

    float v1 = acc[0]; int i1 = 0;
    #pragma unroll
    for (int e = 1; e < NEXP; ++e) if (acc[e] > v1) { v1 = acc[e]; i1 = e; }
    float v2 = -1.f; int i2 = 0;
    #pragma unroll
    for (int e = 0; e < NEXP; ++e) {
        bool ok = (e != i1) && (acc[e] > v2);
        if (ok) { v2 = acc[e]; i2 = e; }
    }

    g_top_e[2 * n]     = i1;  g_top_v[2 * n]     = v1;
    g_top_e[2 * n + 1] = i2;  g_top_v[2 * n + 1] = v2;
    atomicAdd(&imp_s[i1], v1);
    atomicAdd(&imp_s[i2], v2);
    atomicAdd(&cnt_s[i1], 1);
    atomicAdd(&cnt_s[i2], 1);

    __syncthreads();
    if (tid < NEXP) {
        atomicAdd(&g_importance[tid], imp_s[tid]);
        atomicAdd(&g_counts[tid], cnt_s[tid]);
    }
}

// ================= kernel: scan + loss =================
__global__ void scan_loss_kernel(float* __restrict__ out, int out_size) {
    const int lane = threadIdx.x;
    const unsigned FULL = 0xffffffffu;

    int c = g_counts[lane];
    int sc = c;
    #pragma unroll
    for (int o = 1; o < 32; o <<= 1) {
        int v = __shfl_up_sync(FULL, sc, o);
        if (lane >= o) sc += v;
    }
    g_offsets[lane] = sc - c;
    g_cursor[lane]  = sc - c;
    if (lane == 31) g_offsets[NEXP] = sc;

    int nt = (c + TM - 1) / TM;
    int st = nt;
    #pragma unroll
    for (int o = 1; o < 32; o <<= 1) {
        int v = __shfl_up_sync(FULL, st, o);
        if (lane >= o) st += v;
    }
    g_tile_off[lane] = st - nt;
    if (lane == 31) { g_tile_off[NEXP] = st; g_total_tiles = st; }

    float imp = g_importance[lane];
    float s = imp;
    #pragma unroll
    for (int o = 16; o; o >>= 1) s += __shfl_xor_sync(FULL, s, o);
    float mean = s / 32.f;
    float d = imp - mean;
    float ss = d * d;
    #pragma unroll
    for (int o = 16; o; o >>= 1) ss += __shfl_xor_sync(FULL, ss, o);
    float var = ss / 31.f;
    if (lane == 0 && out_size > NTOK * DMODEL)
        out[NTOK * DMODEL] = var / (mean * mean + 1e-9f);
}

// ================= kernel: scatter =================
__global__ void __launch_bounds__(256) scatter_kernel() {
    __shared__ int lcnt[NEXP];
    __shared__ int gbase[NEXP];
    __shared__ int lcur[NEXP];

    const int tid = threadIdx.x;
    const int n = blockIdx.x * 256 + tid;
    if (tid < NEXP) lcnt[tid] = 0;
    __syncthreads();

    int e0 = g_top_e[2 * n];     float v0 = g_top_v[2 * n];
    int e1 = g_top_e[2 * n + 1]; float v1 = g_top_v[2 * n + 1];
    atomicAdd(&lcnt[e0], 1);
    atomicAdd(&lcnt[e1], 1);
    __syncthreads();

    if (tid < NEXP) { gbase[tid] = atomicAdd(&g_cursor[tid], lcnt[tid]); lcur[tid] = 0; }
    __syncthreads();

    int p0 = gbase[e0] + atomicAdd(&lcur[e0], 1);
    g_bucket_tok[p0] = n; g_bucket_w[p0] = v0; g_tok_slot[2 * n] = p0;
    int p1 = gbase[e1] + atomicAdd(&lcur[e1], 1);
    g_bucket_tok[p1] = n; g_bucket_w[p1] = v1; g_tok_slot[2 * n + 1] = p1;
}

// ================= kernel: grouped expert GEMM (fp16 2-term, TM=64, 2 CTA/SM) =================
// X   : [64,128] fp16 hi/lo, row stride 272B (17408 B each)
// Wbuf: FC1 chunk [64h,128d] fp16 (17408) OR FC2 chunk [128d,64h] stride 144 (18432)
// Cbuf: h chunk [64,64] fp16 hi/lo, stride 144 (9216 each)
#define RW128 272
#define RW64  144
#define O_XH  0
#define O_XL  17408
#define O_BH  34816
#define O_CH  53248
#define O_CL  62464
#define O_TOK 71680
#define O_WSM (O_TOK + 256)
#define O_B1  (O_TOK + 512)
#define O_B2  (O_TOK + 1536)
#define SMEM_DYN (O_TOK + 2048)   // 73728

#define NTHR 256

__global__ void __launch_bounds__(NTHR, 2) expert_mma_kernel(
    const float* __restrict__ b1, const float* __restrict__ b2)
{
    const int t = blockIdx.x;
    if (t >= g_total_tiles) return;

    extern __shared__ char smp[];
    const uint32_t sbase = smem_to_u32(smp);
    int*   toks_s = (int*)(smp + O_TOK);
    float* wsm_s  = (float*)(smp + O_WSM);
    float* b1s    = (float*)(smp + O_B1);
    float* b2s    = (float*)(smp + O_B2);

    const int tid = threadIdx.x;
    const int wid = tid >> 5;
    const int lane = tid & 31;

    int e = 0;
    #pragma unroll 1
    while (t >= g_tile_off[e + 1]) ++e;
    const int mtile = t - g_tile_off[e];
    const int off   = g_offsets[e];
    const int cnt   = g_counts[e];
    const int m0g   = mtile * TM;
    const int valid = min(TM, cnt - m0g);

    if (tid < 64) {
        if (tid < valid) {
            toks_s[tid] = g_bucket_tok[off + m0g + tid];
            wsm_s[tid]  = g_bucket_w[off + m0g + tid];
        } else { toks_s[tid] = 0; wsm_s[tid] = 0.f; }
    }
    if (tid < 128) b2s[tid] = b2[e * DMODEL + tid];
    b1s[tid] = b1[e * HDIM + tid];
    __syncthreads();

    // ---- async gather X rows [64,128] hi/lo ----
    #pragma unroll
    for (int i = tid; i < 1024; i += NTHR) {
        int r = i >> 4, ch = i & 15;
        const size_t src = (size_t)toks_s[r] * DMODEL + ch * 8;
        uint32_t dst = sbase + r * RW128 + ch * 16;
        cp16(dst + O_XH, g_xhi + src);
        cp16(dst + O_XL, g_xlo + src);
    }

    const size_t w1base = (size_t)e * HDIM * DMODEL;
    const size_t w2base = (size_t)e * DMODEL * HDIM;

    // ---- async load W1 chunk 0: [64h, 128d] fp16 ----
    #pragma unroll
    for (int i = tid; i < 1024; i += NTHR) {
        int r = i >> 4, ch = i & 15;
        size_t src = w1base + (size_t)r * DMODEL + ch * 8;
        cp16(sbase + O_BH + r * RW128 + ch * 16, g_w1h + src);
    }
    CP_COMMIT();
    CP_WAIT0();
    __syncthreads();

    // warp tiling: 4 m-warps (16 rows) x 2 n-warps
    const int m0 = (wid >> 1) * 16;
    const int nw = wid & 1;
    const uint32_t arow  = m0 + (lane & 15);
    const uint32_t acolb = ((lane >> 4) & 1) * 16;
    const uint32_t brsub = ((lane >> 4) & 1) * 8 + (lane & 7);
    const uint32_t bcolb = ((lane >> 3) & 1) * 16;

    float acc2[8][4];                       // FC2: n64 per warp
    #pragma unroll
    for (int j = 0; j < 8; ++j)
        #pragma unroll
        for (int q = 0; q < 4; ++q) acc2[j][q] = 0.f;

    #pragma unroll 1
    for (int c = 0; c < 4; ++c) {
        // ---- FC1: h_c[64,64] = X[64,128] @ W1c[64,128]^T ; warp m16 x n32 ----
        float acc1[4][4];
        #pragma unroll
        for (int j = 0; j < 4; ++j)
            #pragma unroll
            for (int q = 0; q < 4; ++q) acc1[j][q] = 0.f;

        #pragma unroll 1
        for (int k = 0; k < 8; ++k) {
            uint32_t aaddr = sbase + O_XH + arow * RW128 + k * 32 + acolb;
            uint32_t ah0, ah1, ah2, ah3, al0, al1, al2, al3;
            ldsm4(ah0, ah1, ah2, ah3, aaddr);
            ldsm4(al0, al1, al2, al3, aaddr + (O_XL - O_XH));
            #pragma unroll
            for (int jp = 0; jp < 2; ++jp) {
                uint32_t brow = nw * 32 + jp * 16 + brsub;
                uint32_t baddr = sbase + O_BH + brow * RW128 + k * 32 + bcolb;
                uint32_t bh0, bh1, bh2, bh3;
                ldsm4(bh0, bh1, bh2, bh3, baddr);
                float* c0 = acc1[2 * jp];
                float* c1 = acc1[2 * jp + 1];
                mma16816(c0, ah0, ah1, ah2, ah3, bh0, bh1);
                mma16816(c0, al0, al1, al2, al3, bh0, bh1);
                mma16816(c1, ah0, ah1, ah2, ah3, bh2, bh3);
                mma16816(c1, al0, al1, al2, al3, bh2, bh3);
            }
        }
        __syncthreads();   // W1c consumed

        // ---- prefetch W2 chunk c: [128d, 64h] (overlaps epilogue) ----
        #pragma unroll
        for (int i = tid; i < 1024; i += NTHR) {
            int r = i >> 3, ch = i & 7;
            size_t src = w2base + (size_t)r * HDIM + c * 64 + ch * 8;
            cp16(sbase + O_BH + r * RW64 + ch * 16, g_w2h + src);
        }
        CP_COMMIT();

        // ---- epilogue 1: relu(acc1 + b1) -> split fp16 hi/lo into C [64,64] ----
        {
            const int r0 = m0 + (lane >> 2);
            const int cb = (lane & 3) * 2;
            #pragma unroll
            for (int jn = 0; jn < 4; ++jn) {
                const float* a = acc1[jn];
                int coll = nw * 32 + jn * 8 + cb;
                int colg = c * 64 + coll;
                float bb0 = b1s[colg], bb1 = b1s[colg + 1];
                float f0 = fmaxf(a[0] + bb0, 0.f);
                float f1 = fmaxf(a[1] + bb1, 0.f);
                float f2 = fmaxf(a[2] + bb0, 0.f);
                float f3 = fmaxf(a[3] + bb1, 0.f);
                __half h0,l0,h1,l1,h2,l2,h3,l3;
                split2h(f0,h0,l0); split2h(f1,h1,l1); split2h(f2,h2,l2); split2h(f3,h3,l3);
                int d0 = r0 * RW64 + coll * 2;
                int d1 = (r0 + 8) * RW64 + coll * 2;
                *reinterpret_cast<uint32_t*>(smp + O_CH + d0) = packh(h0, h1);
                *reinterpret_cast<uint32_t*>(smp + O_CL + d0) = packh(l0, l1);
                *reinterpret_cast<uint32_t*>(smp + O_CH + d1) = packh(h2, h3);
                *reinterpret_cast<uint32_t*>(smp + O_CL + d1) = packh(l2, l3);
            }
        }
        CP_WAIT0();
        __syncthreads();   // W2c ready, h visible

        // ---- FC2: acc2 += h_c[64,64] @ W2c[128,64]^T ; warp m16 x n64 ----
        #pragma unroll 1
        for (int k = 0; k < 4; ++k) {
            uint32_t aaddr = sbase + O_CH + arow * RW64 + k * 32 + acolb;
            uint32_t ah0, ah1, ah2, ah3, al0, al1, al2, al3;
            ldsm4(ah0, ah1, ah2, ah3, aaddr);
            ldsm4(al0, al1, al2, al3, aaddr + (O_CL - O_CH));
            #pragma unroll
            for (int jp = 0; jp < 4; ++jp) {
                uint32_t brow = nw * 64 + jp * 16 + brsub;
                uint32_t baddr = sbase + O_BH + brow * RW64 + k * 32 + bcolb;
                uint32_t bh0, bh1, bh2, bh3;
                ldsm4(bh0, bh1, bh2, bh3, baddr);
                float* c0 = acc2[2 * jp];
                float* c1 = acc2[2 * jp + 1];
                mma16816(c0, ah0, ah1, ah2, ah3, bh0, bh1);
                mma16816(c0, al0, al1, al2, al3, bh0, bh1);
                mma16816(c1, ah0, ah1, ah2, ah3, bh2, bh3);
                mma16816(c1, al0, al1, al2, al3, bh2, bh3);
            }
        }
        __syncthreads();   // W2c + C consumed

        // ---- prefetch W1 chunk c+1 ----
        if (c < 3) {
            #pragma unroll
            for (int i = tid; i < 1024; i += NTHR) {
                int r = i >> 4, ch = i & 15;
                size_t src = w1base + (size_t)((c + 1) * 64 + r) * DMODEL + ch * 8;
                cp16(sbase + O_BH + r * RW128 + ch * 16, g_w1h + src);
            }
            CP_COMMIT();
            CP_WAIT0();
            __syncthreads();
        }
    }

    // ---- epilogue 2: w * (acc2 + b2) -> g_partial ----
    {
        const int cb = (lane & 3) * 2;
        const int r0 = m0 + (lane >> 2);
        const int r1 = r0 + 8;
        const float w0 = (r0 < valid) ? wsm_s[r0] : 0.f;
        const float w1 = (r1 < valid) ? wsm_s[r1] : 0.f;
        const size_t s0 = (size_t)(off + m0g + r0) * DMODEL;
        const size_t s1 = (size_t)(off + m0g + r1) * DMODEL;
        #pragma unroll
        for (int jn = 0; jn < 8; ++jn) {
            const float* a = acc2[jn];
            int col = nw * 64 + jn * 8 + cb;
            float bb0 = b2s[col], bb1 = b2s[col + 1];
            if (r0 < valid) {
                float2 o;
                o.x = w0 * (a[0] + bb0);
                o.y = w0 * (a[1] + bb1);
                *reinterpret_cast<float2*>(&g_partial[s0 + col]) = o;
            }
            if (r1 < valid) {
                float2 o;
                o.x = w1 * (a[2] + bb0);
                o.y = w1 * (a[3] + bb1);
                *reinterpret_cast<float2*>(&g_partial[s1 + col]) = o;
            }
        }
    }
}

// ================= kernel: combine =================
__global__ void __launch_bounds__(256) combine_kernel(float* __restrict__ out) {
    int gid = blockIdx.x * 256 + threadIdx.x;
    int n = gid >> 5;
    int q = gid & 31;
    int s0 = g_tok_slot[2 * n];
    int s1 = g_tok_slot[2 * n + 1];
    const float4* P = reinterpret_cast<const float4*>(g_partial);
    float4 p0 = P[(size_t)s0 * 32 + q];
    float4 p1 = P[(size_t)s1 * 32 + q];
    float4 o;
    o.x = p0.x + p1.x; o.y = p0.y + p1.y;
    o.z = p0.z + p1.z; o.w = p0.w + p1.w;
    reinterpret_cast<float4*>(out)[(size_t)n * 32 + q] = o;
}

// ================= launch =================
extern "C" void kernel_launch(void* const* d_in, const int* in_sizes, int n_in,
                              void* d_out, int out_size) {
    const float* x  = (const float*)d_in[0];
    const float* W1 = (const float*)d_in[1];
    const float* b1 = (const float*)d_in[2];
    const float* W2 = (const float*)d_in[3];
    const float* b2 = (const float*)d_in[4];
    const float* Wr = (const float*)d_in[5];
    const float* br = (const float*)d_in[6];
    float* out = (float*)d_out;

    cudaFuncSetAttribute(expert_mma_kernel,
                         cudaFuncAttributeMaxDynamicSharedMemorySize, SMEM_DYN);

    convert_x_kernel<<<NTOK * DMODEL / (256 * 8), 256>>>(x);
    convert_w_kernel<<<NEXP * HDIM * DMODEL / 256, 256>>>(W1, W2);
    router_kernel<<<NTOK / 256, 256>>>(x, Wr, br);
    scan_loss_kernel<<<1, 32>>>(out, out_size);
    scatter_kernel<<<NTOK / 256, 256>>>();
    // max tiles = 2N/64 + NEXP = 2048 + 32
    expert_mma_kernel<<<2080, NTHR, SMEM_DYN>>>(b1, b2);
    combine_kernel<<<(NTOK * 32) / 256, 256>>>(out);
}

// round 9
// speedup vs baseline: 4.2793x; 1.2365x over previous
#include <cuda_runtime.h>
#include <cuda_fp16.h>
#include <math.h>
#include <stdint.h>

#define NTOK   65536
#define DMODEL 128
#define HDIM   256
#define NEXP   32
#define TM     64

// ================= helpers =================
__device__ __forceinline__ uint32_t smem_to_u32(const void* p) {
    uint32_t a;
    asm("{ .reg .u64 t; cvta.to.shared.u64 t, %1; cvt.u32.u64 %0, t; }" : "=r"(a) : "l"(p));
    return a;
}
__device__ __forceinline__ void ldsm4(uint32_t& r0, uint32_t& r1, uint32_t& r2, uint32_t& r3,
                                      uint32_t addr) {
    asm volatile("ldmatrix.sync.aligned.m8n8.x4.shared.b16 {%0,%1,%2,%3}, [%4];"
                 : "=r"(r0), "=r"(r1), "=r"(r2), "=r"(r3) : "r"(addr));
}
__device__ __forceinline__ void mma16816(float* c, uint32_t a0, uint32_t a1, uint32_t a2,
                                         uint32_t a3, uint32_t b0, uint32_t b1) {
    asm volatile("mma.sync.aligned.m16n8k16.row.col.f32.f16.f16.f32 "
                 "{%0,%1,%2,%3}, {%4,%5,%6,%7}, {%8,%9}, {%0,%1,%2,%3};"
                 : "+f"(c[0]), "+f"(c[1]), "+f"(c[2]), "+f"(c[3])
                 : "r"(a0), "r"(a1), "r"(a2), "r"(a3), "r"(b0), "r"(b1));
}
__device__ __forceinline__ void cp16(uint32_t dst, const void* src) {
    asm volatile("cp.async.cg.shared.global [%0], [%1], 16;" :: "r"(dst), "l"(src) : "memory");
}
#define CP_COMMIT() asm volatile("cp.async.commit_group;" ::: "memory")
#define CP_WAIT0()  asm volatile("cp.async.wait_group 0;" ::: "memory")

__device__ __forceinline__ uint32_t packh(__half a, __half b) {
    __half2 t(a, b);
    return *reinterpret_cast<uint32_t*>(&t);
}

// ================= device scratch =================
__device__ float g_top_v[2 * NTOK];
__device__ int   g_top_e[2 * NTOK];
__device__ float g_importance[NEXP];
__device__ int   g_counts[NEXP];
__device__ int   g_offsets[NEXP + 1];
__device__ int   g_cursor[NEXP];
__device__ int   g_tile_off[NEXP + 1];
__device__ int   g_total_tiles;
__device__ int   g_bucket_tok[2 * NTOK];
__device__ float g_bucket_w[2 * NTOK];
__device__ int   g_tok_slot[2 * NTOK];
__device__ float g_partial[(size_t)2 * NTOK * DMODEL];

__device__ __align__(16) __half g_xh[NTOK * DMODEL];
__device__ __align__(16) __half g_w1h[NEXP * HDIM * DMODEL];   // [E,H,D] (transposed)
__device__ __align__(16) __half g_w2h[NEXP * DMODEL * HDIM];   // [E,D,H] (transposed)

// ================= kernel: convert x -> fp16 (+ init in block 0) =================
__global__ void __launch_bounds__(256) convert_x_kernel(const float* __restrict__ x) {
    if (blockIdx.x == 0 && threadIdx.x < NEXP) {
        g_counts[threadIdx.x] = 0;
        g_importance[threadIdx.x] = 0.f;
    }
    size_t i = ((size_t)blockIdx.x * 256 + threadIdx.x) * 8;
    float4 a = *reinterpret_cast<const float4*>(x + i);
    float4 b = *reinterpret_cast<const float4*>(x + i + 4);
    uint4 ph;
    ph.x = packh(__float2half_rn(a.x), __float2half_rn(a.y));
    ph.y = packh(__float2half_rn(a.z), __float2half_rn(a.w));
    ph.z = packh(__float2half_rn(b.x), __float2half_rn(b.y));
    ph.w = packh(__float2half_rn(b.z), __float2half_rn(b.w));
    *reinterpret_cast<uint4*>(g_xh + i) = ph;
}

// ================= kernel: convert + transpose weights (single fp16) =================
__global__ void __launch_bounds__(256) convert_w_kernel(const float* __restrict__ W1,
                                                        const float* __restrict__ W2) {
    int idx = blockIdx.x * 256 + threadIdx.x;
    {   // W1T[e][h][d] = W1[e][d][h]
        int d = idx & 127, h = (idx >> 7) & 255, e = idx >> 15;
        g_w1h[idx] = __float2half_rn(W1[((size_t)e * 128 + d) * 256 + h]);
    }
    {   // W2T[e][d][h] = W2[e][h][d]
        int h = idx & 255, d = (idx >> 8) & 127, e = idx >> 15;
        g_w2h[idx] = __float2half_rn(W2[((size_t)e * 256 + h) * 128 + d]);
    }
}

// ================= kernel: router (thread per token, shuffle-free) =================
__global__ void __launch_bounds__(256) router_kernel(
    const float* __restrict__ x, const float* __restrict__ Wr,
    const float* __restrict__ br)
{
    __shared__ float wr_s[DMODEL * NEXP];
    __shared__ float br_s[NEXP];
    __shared__ float imp_s[NEXP];
    __shared__ int   cnt_s[NEXP];

    const int tid = threadIdx.x;
    if (tid < NEXP) { imp_s[tid] = 0.f; cnt_s[tid] = 0; br_s[tid] = br[tid]; }
    #pragma unroll
    for (int i = tid; i < DMODEL * NEXP; i += 256) wr_s[i] = Wr[i];
    __syncthreads();

    const int n = blockIdx.x * 256 + tid;

    float acc[NEXP];
    #pragma unroll
    for (int e = 0; e < NEXP; ++e) acc[e] = br_s[e];

    const float4* xrow = reinterpret_cast<const float4*>(x + (size_t)n * DMODEL);
    float4 xv = xrow[0];
    #pragma unroll 4
    for (int ch = 0; ch < 32; ++ch) {
        float4 xn;
        if (ch < 31) xn = xrow[ch + 1];
        float xd[4] = {xv.x, xv.y, xv.z, xv.w};
        #pragma unroll
        for (int dd = 0; dd < 4; ++dd) {
            const float4* wrow = reinterpret_cast<const float4*>(&wr_s[(ch * 4 + dd) * NEXP]);
            #pragma unroll
            for (int e4 = 0; e4 < 8; ++e4) {
                float4 w = wrow[e4];
                acc[e4 * 4 + 0] = fmaf(xd[dd], w.x, acc[e4 * 4 + 0]);
                acc[e4 * 4 + 1] = fmaf(xd[dd], w.y, acc[e4 * 4 + 1]);
                acc[e4 * 4 + 2] = fmaf(xd[dd], w.z, acc[e4 * 4 + 2]);
                acc[e4 * 4 + 3] = fmaf(xd[dd], w.w, acc[e4 * 4 + 3]);
            }
        }
        xv = xn;
    }

    float mx = acc[0];
    #pragma unroll
    for (int e = 1; e < NEXP; ++e) mx = fmaxf(mx, acc[e]);
    float s = 0.f;
    #pragma unroll
    for (int e = 0; e < NEXP; ++e) { acc[e] = expf(acc[e] - mx); s += acc[e]; }
    float inv = 1.f / s;
    #pragma unroll
    for (int e = 0; e < NEXP; ++e) acc[e] *= inv;

    float v1 = acc[0]; int i1 = 0;
    #pragma unroll
    for (int e = 1; e < NEXP; ++e) if (acc[e] > v1) { v1 = acc[e]; i1 = e; }
    float v2 = -1.f; int i2 = 0;
    #pragma unroll
    for (int e = 0; e < NEXP; ++e) {
        bool ok = (e != i1) && (acc[e] > v2);
        if (ok) { v2 = acc[e]; i2 = e; }
    }

    g_top_e[2 * n]     = i1;  g_top_v[2 * n]     = v1;
    g_top_e[2 * n + 1] = i2;  g_top_v[2 * n + 1] = v2;
    atomicAdd(&imp_s[i1], v1);
    atomicAdd(&imp_s[i2], v2);
    atomicAdd(&cnt_s[i1], 1);
    atomicAdd(&cnt_s[i2], 1);

    __syncthreads();
    if (tid < NEXP) {
        atomicAdd(&g_importance[tid], imp_s[tid]);
        atomicAdd(&g_counts[tid], cnt_s[tid]);
    }
}

// ================= kernel: scan + loss =================
__global__ void scan_loss_kernel(float* __restrict__ out, int out_size) {
    const int lane = threadIdx.x;
    const unsigned FULL = 0xffffffffu;

    int c = g_counts[lane];
    int sc = c;
    #pragma unroll
    for (int o = 1; o < 32; o <<= 1) {
        int v = __shfl_up_sync(FULL, sc, o);
        if (lane >= o) sc += v;
    }
    g_offsets[lane] = sc - c;
    g_cursor[lane]  = sc - c;
    if (lane == 31) g_offsets[NEXP] = sc;

    int nt = (c + TM - 1) / TM;
    int st = nt;
    #pragma unroll
    for (int o = 1; o < 32; o <<= 1) {
        int v = __shfl_up_sync(FULL, st, o);
        if (lane >= o) st += v;
    }
    g_tile_off[lane] = st - nt;
    if (lane == 31) { g_tile_off[NEXP] = st; g_total_tiles = st; }

    float imp = g_importance[lane];
    float s = imp;
    #pragma unroll
    for (int o = 16; o; o >>= 1) s += __shfl_xor_sync(FULL, s, o);
    float mean = s / 32.f;
    float d = imp - mean;
    float ss = d * d;
    #pragma unroll
    for (int o = 16; o; o >>= 1) ss += __shfl_xor_sync(FULL, ss, o);
    float var = ss / 31.f;
    if (lane == 0 && out_size > NTOK * DMODEL)
        out[NTOK * DMODEL] = var / (mean * mean + 1e-9f);
}

// ================= kernel: scatter =================
__global__ void __launch_bounds__(256) scatter_kernel() {
    __shared__ int lcnt[NEXP];
    __shared__ int gbase[NEXP];
    __shared__ int lcur[NEXP];

    const int tid = threadIdx.x;
    const int n = blockIdx.x * 256 + tid;
    if (tid < NEXP) lcnt[tid] = 0;
    __syncthreads();

    int e0 = g_top_e[2 * n];     float v0 = g_top_v[2 * n];
    int e1 = g_top_e[2 * n + 1]; float v1 = g_top_v[2 * n + 1];
    atomicAdd(&lcnt[e0], 1);
    atomicAdd(&lcnt[e1], 1);
    __syncthreads();

    if (tid < NEXP) { gbase[tid] = atomicAdd(&g_cursor[tid], lcnt[tid]); lcur[tid] = 0; }
    __syncthreads();

    int p0 = gbase[e0] + atomicAdd(&lcur[e0], 1);
    g_bucket_tok[p0] = n; g_bucket_w[p0] = v0; g_tok_slot[2 * n] = p0;
    int p1 = gbase[e1] + atomicAdd(&lcur[e1], 1);
    g_bucket_tok[p1] = n; g_bucket_w[p1] = v1; g_tok_slot[2 * n + 1] = p1;
}

// ================= kernel: grouped expert GEMM (pure fp16, TM=64, 4 CTA/SM) =================
// X   : [64,128] fp16, row stride 272B (17408 B)
// Wbuf: FC1 chunk [64h,128d] fp16 (17408) OR FC2 chunk [128d,64h] stride 144 (18432)
// Cbuf: h chunk [64,64] fp16, stride 144 (9216)
#define RW128 272
#define RW64  144
#define O_XH  0
#define O_BH  17408
#define O_CH  35840
#define O_TOK 45056
#define O_WSM (O_TOK + 256)
#define O_B1  (O_TOK + 512)
#define O_B2  (O_TOK + 1536)
#define SMEM_DYN (O_TOK + 2048)   // 47104

#define NTHR 256

__global__ void __launch_bounds__(NTHR, 4) expert_mma_kernel(
    const float* __restrict__ b1, const float* __restrict__ b2)
{
    const int t = blockIdx.x;
    if (t >= g_total_tiles) return;

    extern __shared__ char smp[];
    const uint32_t sbase = smem_to_u32(smp);
    int*   toks_s = (int*)(smp + O_TOK);
    float* wsm_s  = (float*)(smp + O_WSM);
    float* b1s    = (float*)(smp + O_B1);
    float* b2s    = (float*)(smp + O_B2);

    const int tid = threadIdx.x;
    const int wid = tid >> 5;
    const int lane = tid & 31;

    int e = 0;
    #pragma unroll 1
    while (t >= g_tile_off[e + 1]) ++e;
    const int mtile = t - g_tile_off[e];
    const int off   = g_offsets[e];
    const int cnt   = g_counts[e];
    const int m0g   = mtile * TM;
    const int valid = min(TM, cnt - m0g);

    if (tid < 64) {
        if (tid < valid) {
            toks_s[tid] = g_bucket_tok[off + m0g + tid];
            wsm_s[tid]  = g_bucket_w[off + m0g + tid];
        } else { toks_s[tid] = 0; wsm_s[tid] = 0.f; }
    }
    if (tid < 128) b2s[tid] = b2[e * DMODEL + tid];
    b1s[tid] = b1[e * HDIM + tid];
    __syncthreads();

    // ---- async gather X rows [64,128] fp16 ----
    #pragma unroll
    for (int i = tid; i < 1024; i += NTHR) {
        int r = i >> 4, ch = i & 15;
        const size_t src = (size_t)toks_s[r] * DMODEL + ch * 8;
        cp16(sbase + O_XH + r * RW128 + ch * 16, g_xh + src);
    }

    const size_t w1base = (size_t)e * HDIM * DMODEL;
    const size_t w2base = (size_t)e * DMODEL * HDIM;

    // ---- async load W1 chunk 0: [64h, 128d] fp16 ----
    #pragma unroll
    for (int i = tid; i < 1024; i += NTHR) {
        int r = i >> 4, ch = i & 15;
        size_t src = w1base + (size_t)r * DMODEL + ch * 8;
        cp16(sbase + O_BH + r * RW128 + ch * 16, g_w1h + src);
    }
    CP_COMMIT();
    CP_WAIT0();
    __syncthreads();

    // warp tiling: 4 m-warps (16 rows) x 2 n-warps
    const int m0 = (wid >> 1) * 16;
    const int nw = wid & 1;
    const uint32_t arow  = m0 + (lane & 15);
    const uint32_t acolb = ((lane >> 4) & 1) * 16;
    const uint32_t brsub = ((lane >> 4) & 1) * 8 + (lane & 7);
    const uint32_t bcolb = ((lane >> 3) & 1) * 16;

    float acc2[8][4];                       // FC2: n64 per warp
    #pragma unroll
    for (int j = 0; j < 8; ++j)
        #pragma unroll
        for (int q = 0; q < 4; ++q) acc2[j][q] = 0.f;

    #pragma unroll 1
    for (int c = 0; c < 4; ++c) {
        // ---- FC1: h_c[64,64] = X[64,128] @ W1c[64,128]^T ; warp m16 x n32 ----
        float acc1[4][4];
        #pragma unroll
        for (int j = 0; j < 4; ++j)
            #pragma unroll
            for (int q = 0; q < 4; ++q) acc1[j][q] = 0.f;

        #pragma unroll 1
        for (int k = 0; k < 8; ++k) {
            uint32_t aaddr = sbase + O_XH + arow * RW128 + k * 32 + acolb;
            uint32_t ah0, ah1, ah2, ah3;
            ldsm4(ah0, ah1, ah2, ah3, aaddr);
            #pragma unroll
            for (int jp = 0; jp < 2; ++jp) {
                uint32_t brow = nw * 32 + jp * 16 + brsub;
                uint32_t baddr = sbase + O_BH + brow * RW128 + k * 32 + bcolb;
                uint32_t bh0, bh1, bh2, bh3;
                ldsm4(bh0, bh1, bh2, bh3, baddr);
                mma16816(acc1[2 * jp],     ah0, ah1, ah2, ah3, bh0, bh1);
                mma16816(acc1[2 * jp + 1], ah0, ah1, ah2, ah3, bh2, bh3);
            }
        }
        __syncthreads();   // W1c consumed

        // ---- prefetch W2 chunk c: [128d, 64h] (overlaps epilogue) ----
        #pragma unroll
        for (int i = tid; i < 1024; i += NTHR) {
            int r = i >> 3, ch = i & 7;
            size_t src = w2base + (size_t)r * HDIM + c * 64 + ch * 8;
            cp16(sbase + O_BH + r * RW64 + ch * 16, g_w2h + src);
        }
        CP_COMMIT();

        // ---- epilogue 1: relu(acc1 + b1) -> fp16 into C [64,64] ----
        {
            const int r0 = m0 + (lane >> 2);
            const int cb = (lane & 3) * 2;
            #pragma unroll
            for (int jn = 0; jn < 4; ++jn) {
                const float* a = acc1[jn];
                int coll = nw * 32 + jn * 8 + cb;
                int colg = c * 64 + coll;
                float bb0 = b1s[colg], bb1 = b1s[colg + 1];
                __half h0 = __float2half_rn(fmaxf(a[0] + bb0, 0.f));
                __half h1 = __float2half_rn(fmaxf(a[1] + bb1, 0.f));
                __half h2 = __float2half_rn(fmaxf(a[2] + bb0, 0.f));
                __half h3 = __float2half_rn(fmaxf(a[3] + bb1, 0.f));
                *reinterpret_cast<uint32_t*>(smp + O_CH + r0 * RW64 + coll * 2) = packh(h0, h1);
                *reinterpret_cast<uint32_t*>(smp + O_CH + (r0 + 8) * RW64 + coll * 2) = packh(h2, h3);
            }
        }
        CP_WAIT0();
        __syncthreads();   // W2c ready, h visible

        // ---- FC2: acc2 += h_c[64,64] @ W2c[128,64]^T ; warp m16 x n64 ----
        #pragma unroll 1
        for (int k = 0; k < 4; ++k) {
            uint32_t aaddr = sbase + O_CH + arow * RW64 + k * 32 + acolb;
            uint32_t ah0, ah1, ah2, ah3;
            ldsm4(ah0, ah1, ah2, ah3, aaddr);
            #pragma unroll
            for (int jp = 0; jp < 4; ++jp) {
                uint32_t brow = nw * 64 + jp * 16 + brsub;
                uint32_t baddr = sbase + O_BH + brow * RW64 + k * 32 + bcolb;
                uint32_t bh0, bh1, bh2, bh3;
                ldsm4(bh0, bh1, bh2, bh3, baddr);
                mma16816(acc2[2 * jp],     ah0, ah1, ah2, ah3, bh0, bh1);
                mma16816(acc2[2 * jp + 1], ah0, ah1, ah2, ah3, bh2, bh3);
            }
        }
        __syncthreads();   // W2c + C consumed

        // ---- prefetch W1 chunk c+1 ----
        if (c < 3) {
            #pragma unroll
            for (int i = tid; i < 1024; i += NTHR) {
                int r = i >> 4, ch = i & 15;
                size_t src = w1base + (size_t)((c + 1) * 64 + r) * DMODEL + ch * 8;
                cp16(sbase + O_BH + r * RW128 + ch * 16, g_w1h + src);
            }
            CP_COMMIT();
            CP_WAIT0();
            __syncthreads();
        }
    }

    // ---- epilogue 2: w * (acc2 + b2) -> g_partial ----
    {
        const int cb = (lane & 3) * 2;
        const int r0 = m0 + (lane >> 2);
        const int r1 = r0 + 8;
        const float w0 = (r0 < valid) ? wsm_s[r0] : 0.f;
        const float w1 = (r1 < valid) ? wsm_s[r1] : 0.f;
        const size_t s0 = (size_t)(off + m0g + r0) * DMODEL;
        const size_t s1 = (size_t)(off + m0g + r1) * DMODEL;
        #pragma unroll
        for (int jn = 0; jn < 8; ++jn) {
            const float* a = acc2[jn];
            int col = nw * 64 + jn * 8 + cb;
            float bb0 = b2s[col], bb1 = b2s[col + 1];
            if (r0 < valid) {
                float2 o;
                o.x = w0 * (a[0] + bb0);
                o.y = w0 * (a[1] + bb1);
                *reinterpret_cast<float2*>(&g_partial[s0 + col]) = o;
            }
            if (r1 < valid) {
                float2 o;
                o.x = w1 * (a[2] + bb0);
                o.y = w1 * (a[3] + bb1);
                *reinterpret_cast<float2*>(&g_partial[s1 + col]) = o;
            }
        }
    }
}

// ================= kernel: combine =================
__global__ void __launch_bounds__(256) combine_kernel(float* __restrict__ out) {
    int gid = blockIdx.x * 256 + threadIdx.x;
    int n = gid >> 5;
    int q = gid & 31;
    int s0 = g_tok_slot[2 * n];
    int s1 = g_tok_slot[2 * n + 1];
    const float4* P = reinterpret_cast<const float4*>(g_partial);
    float4 p0 = P[(size_t)s0 * 32 + q];
    float4 p1 = P[(size_t)s1 * 32 + q];
    float4 o;
    o.x = p0.x + p1.x; o.y = p0.y + p1.y;
    o.z = p0.z + p1.z; o.w = p0.w + p1.w;
    reinterpret_cast<float4*>(out)[(size_t)n * 32 + q] = o;
}

// ================= launch =================
extern "C" void kernel_launch(void* const* d_in, const int* in_sizes, int n_in,
                              void* d_out, int out_size) {
    const float* x  = (const float*)d_in[0];
    const float* W1 = (const float*)d_in[1];
    const float* b1 = (const float*)d_in[2];
    const float* W2 = (const float*)d_in[3];
    const float* b2 = (const float*)d_in[4];
    const float* Wr = (const float*)d_in[5];
    const float* br = (const float*)d_in[6];
    float* out = (float*)d_out;

    cudaFuncSetAttribute(expert_mma_kernel,
                         cudaFuncAttributeMaxDynamicSharedMemorySize, SMEM_DYN);

    convert_x_kernel<<<NTOK * DMODEL / (256 * 8), 256>>>(x);
    convert_w_kernel<<<NEXP * HDIM * DMODEL / 256, 256>>>(W1, W2);
    router_kernel<<<NTOK / 256, 256>>>(x, Wr, br);
    scan_loss_kernel<<<1, 32>>>(out, out_size);
    scatter_kernel<<<NTOK / 256, 256>>>();
    // max tiles = 2N/64 + NEXP = 2048 + 32
    expert_mma_kernel<<<2080, NTHR, SMEM_DYN>>>(b1, b2);
    combine_kernel<<<(NTOK * 32) / 256, 256>>>(out);
}

// round 10
// speedup vs baseline: 4.6325x; 1.0825x over previous
#include <cuda_runtime.h>
#include <cuda_fp16.h>
#include <math.h>
#include <stdint.h>

#define NTOK   65536
#define DMODEL 128
#define HDIM   256
#define NEXP   32
#define TM     64

// ================= helpers =================
__device__ __forceinline__ uint32_t smem_to_u32(const void* p) {
    uint32_t a;
    asm("{ .reg .u64 t; cvta.to.shared.u64 t, %1; cvt.u32.u64 %0, t; }" : "=r"(a) : "l"(p));
    return a;
}
__device__ __forceinline__ void ldsm4(uint32_t& r0, uint32_t& r1, uint32_t& r2, uint32_t& r3,
                                      uint32_t addr) {
    asm volatile("ldmatrix.sync.aligned.m8n8.x4.shared.b16 {%0,%1,%2,%3}, [%4];"
                 : "=r"(r0), "=r"(r1), "=r"(r2), "=r"(r3) : "r"(addr));
}
__device__ __forceinline__ void mma16816(float* c, uint32_t a0, uint32_t a1, uint32_t a2,
                                         uint32_t a3, uint32_t b0, uint32_t b1) {
    asm volatile("mma.sync.aligned.m16n8k16.row.col.f32.f16.f16.f32 "
                 "{%0,%1,%2,%3}, {%4,%5,%6,%7}, {%8,%9}, {%0,%1,%2,%3};"
                 : "+f"(c[0]), "+f"(c[1]), "+f"(c[2]), "+f"(c[3])
                 : "r"(a0), "r"(a1), "r"(a2), "r"(a3), "r"(b0), "r"(b1));
}
__device__ __forceinline__ void cp16(uint32_t dst, const void* src) {
    asm volatile("cp.async.cg.shared.global [%0], [%1], 16;" :: "r"(dst), "l"(src) : "memory");
}
#define CP_COMMIT() asm volatile("cp.async.commit_group;" ::: "memory")
#define CP_WAIT0()  asm volatile("cp.async.wait_group 0;" ::: "memory")

__device__ __forceinline__ uint32_t packh(__half a, __half b) {
    __half2 t(a, b);
    return *reinterpret_cast<uint32_t*>(&t);
}

// ================= device scratch =================
__device__ float g_top_v[2 * NTOK];
__device__ int   g_top_e[2 * NTOK];
__device__ float g_importance[NEXP];
__device__ int   g_counts[NEXP];
__device__ int   g_offsets[NEXP + 1];
__device__ int   g_cursor[NEXP];
__device__ int   g_tile_off[NEXP + 1];
__device__ int   g_total_tiles;
__device__ int   g_bucket_tok[2 * NTOK];
__device__ float g_bucket_w[2 * NTOK];
__device__ int   g_tok_slot[2 * NTOK];
__device__ __align__(16) __half g_partial_h[(size_t)2 * NTOK * DMODEL];  // fp16 partials

__device__ __align__(16) __half g_xh[NTOK * DMODEL];
__device__ __align__(16) __half g_w1h[NEXP * HDIM * DMODEL];   // [E,H,D] (transposed)
__device__ __align__(16) __half g_w2h[NEXP * DMODEL * HDIM];   // [E,D,H] (transposed)

// ================= kernel: convert + transpose weights (+ init in block 0) =================
__global__ void __launch_bounds__(256) convert_w_kernel(const float* __restrict__ W1,
                                                        const float* __restrict__ W2) {
    if (blockIdx.x == 0 && threadIdx.x < NEXP) {
        g_counts[threadIdx.x] = 0;
        g_importance[threadIdx.x] = 0.f;
    }
    int idx = blockIdx.x * 256 + threadIdx.x;
    {   // W1T[e][h][d] = W1[e][d][h]
        int d = idx & 127, h = (idx >> 7) & 255, e = idx >> 15;
        g_w1h[idx] = __float2half_rn(W1[((size_t)e * 128 + d) * 256 + h]);
    }
    {   // W2T[e][d][h] = W2[e][h][d]
        int h = idx & 255, d = (idx >> 8) & 127, e = idx >> 15;
        g_w2h[idx] = __float2half_rn(W2[((size_t)e * 256 + h) * 128 + d]);
    }
}

// ================= kernel: router (thread per token; also emits x as fp16) =================
__global__ void __launch_bounds__(256) router_kernel(
    const float* __restrict__ x, const float* __restrict__ Wr,
    const float* __restrict__ br)
{
    __shared__ float wr_s[DMODEL * NEXP];
    __shared__ float br_s[NEXP];
    __shared__ float imp_s[NEXP];
    __shared__ int   cnt_s[NEXP];

    const int tid = threadIdx.x;
    if (tid < NEXP) { imp_s[tid] = 0.f; cnt_s[tid] = 0; br_s[tid] = br[tid]; }
    #pragma unroll
    for (int i = tid; i < DMODEL * NEXP; i += 256) wr_s[i] = Wr[i];
    __syncthreads();

    const int n = blockIdx.x * 256 + tid;

    float acc[NEXP];
    #pragma unroll
    for (int e = 0; e < NEXP; ++e) acc[e] = br_s[e];

    const float4* xrow = reinterpret_cast<const float4*>(x + (size_t)n * DMODEL);
    float4 xv = xrow[0];
    uint32_t hprev0 = 0, hprev1 = 0;
    #pragma unroll 4
    for (int ch = 0; ch < 32; ++ch) {
        float4 xn;
        if (ch < 31) xn = xrow[ch + 1];

        // emit fp16 copy of x (fused convert_x)
        uint32_t p0 = packh(__float2half_rn(xv.x), __float2half_rn(xv.y));
        uint32_t p1 = packh(__float2half_rn(xv.z), __float2half_rn(xv.w));
        if (ch & 1) {
            *reinterpret_cast<uint4*>(g_xh + (size_t)n * DMODEL + (ch - 1) * 4) =
                make_uint4(hprev0, hprev1, p0, p1);
        } else { hprev0 = p0; hprev1 = p1; }

        float xd[4] = {xv.x, xv.y, xv.z, xv.w};
        #pragma unroll
        for (int dd = 0; dd < 4; ++dd) {
            const float4* wrow = reinterpret_cast<const float4*>(&wr_s[(ch * 4 + dd) * NEXP]);
            #pragma unroll
            for (int e4 = 0; e4 < 8; ++e4) {
                float4 w = wrow[e4];
                acc[e4 * 4 + 0] = fmaf(xd[dd], w.x, acc[e4 * 4 + 0]);
                acc[e4 * 4 + 1] = fmaf(xd[dd], w.y, acc[e4 * 4 + 1]);
                acc[e4 * 4 + 2] = fmaf(xd[dd], w.z, acc[e4 * 4 + 2]);
                acc[e4 * 4 + 3] = fmaf(xd[dd], w.w, acc[e4 * 4 + 3]);
            }
        }
        xv = xn;
    }

    float mx = acc[0];
    #pragma unroll
    for (int e = 1; e < NEXP; ++e) mx = fmaxf(mx, acc[e]);
    float s = 0.f;
    #pragma unroll
    for (int e = 0; e < NEXP; ++e) { acc[e] = expf(acc[e] - mx); s += acc[e]; }
    float inv = 1.f / s;
    #pragma unroll
    for (int e = 0; e < NEXP; ++e) acc[e] *= inv;

    float v1 = acc[0]; int i1 = 0;
    #pragma unroll
    for (int e = 1; e < NEXP; ++e) if (acc[e] > v1) { v1 = acc[e]; i1 = e; }
    float v2 = -1.f; int i2 = 0;
    #pragma unroll
    for (int e = 0; e < NEXP; ++e) {
        bool ok = (e != i1) && (acc[e] > v2);
        if (ok) { v2 = acc[e]; i2 = e; }
    }

    g_top_e[2 * n]     = i1;  g_top_v[2 * n]     = v1;
    g_top_e[2 * n + 1] = i2;  g_top_v[2 * n + 1] = v2;
    atomicAdd(&imp_s[i1], v1);
    atomicAdd(&imp_s[i2], v2);
    atomicAdd(&cnt_s[i1], 1);
    atomicAdd(&cnt_s[i2], 1);

    __syncthreads();
    if (tid < NEXP) {
        atomicAdd(&g_importance[tid], imp_s[tid]);
        atomicAdd(&g_counts[tid], cnt_s[tid]);
    }
}

// ================= kernel: scan + loss =================
__global__ void scan_loss_kernel(float* __restrict__ out, int out_size) {
    const int lane = threadIdx.x;
    const unsigned FULL = 0xffffffffu;

    int c = g_counts[lane];
    int sc = c;
    #pragma unroll
    for (int o = 1; o < 32; o <<= 1) {
        int v = __shfl_up_sync(FULL, sc, o);
        if (lane >= o) sc += v;
    }
    g_offsets[lane] = sc - c;
    g_cursor[lane]  = sc - c;
    if (lane == 31) g_offsets[NEXP] = sc;

    int nt = (c + TM - 1) / TM;
    int st = nt;
    #pragma unroll
    for (int o = 1; o < 32; o <<= 1) {
        int v = __shfl_up_sync(FULL, st, o);
        if (lane >= o) st += v;
    }
    g_tile_off[lane] = st - nt;
    if (lane == 31) { g_tile_off[NEXP] = st; g_total_tiles = st; }

    float imp = g_importance[lane];
    float s = imp;
    #pragma unroll
    for (int o = 16; o; o >>= 1) s += __shfl_xor_sync(FULL, s, o);
    float mean = s / 32.f;
    float d = imp - mean;
    float ss = d * d;
    #pragma unroll
    for (int o = 16; o; o >>= 1) ss += __shfl_xor_sync(FULL, ss, o);
    float var = ss / 31.f;
    if (lane == 0 && out_size > NTOK * DMODEL)
        out[NTOK * DMODEL] = var / (mean * mean + 1e-9f);
}

// ================= kernel: scatter =================
__global__ void __launch_bounds__(256) scatter_kernel() {
    __shared__ int lcnt[NEXP];
    __shared__ int gbase[NEXP];
    __shared__ int lcur[NEXP];

    const int tid = threadIdx.x;
    const int n = blockIdx.x * 256 + tid;
    if (tid < NEXP) lcnt[tid] = 0;
    __syncthreads();

    int e0 = g_top_e[2 * n];     float v0 = g_top_v[2 * n];
    int e1 = g_top_e[2 * n + 1]; float v1 = g_top_v[2 * n + 1];
    atomicAdd(&lcnt[e0], 1);
    atomicAdd(&lcnt[e1], 1);
    __syncthreads();

    if (tid < NEXP) { gbase[tid] = atomicAdd(&g_cursor[tid], lcnt[tid]); lcur[tid] = 0; }
    __syncthreads();

    int p0 = gbase[e0] + atomicAdd(&lcur[e0], 1);
    g_bucket_tok[p0] = n; g_bucket_w[p0] = v0; g_tok_slot[2 * n] = p0;
    int p1 = gbase[e1] + atomicAdd(&lcur[e1], 1);
    g_bucket_tok[p1] = n; g_bucket_w[p1] = v1; g_tok_slot[2 * n + 1] = p1;
}

// ================= kernel: grouped expert GEMM (pure fp16, TM=64, 4 CTA/SM) =================
#define RW128 272
#define RW64  144
#define O_XH  0
#define O_BH  17408
#define O_CH  35840
#define O_TOK 45056
#define O_WSM (O_TOK + 256)
#define O_B1  (O_TOK + 512)
#define O_B2  (O_TOK + 1536)
#define SMEM_DYN (O_TOK + 2048)   // 47104

#define NTHR 256

__global__ void __launch_bounds__(NTHR, 4) expert_mma_kernel(
    const float* __restrict__ b1, const float* __restrict__ b2)
{
    const int t = blockIdx.x;
    if (t >= g_total_tiles) return;

    extern __shared__ char smp[];
    const uint32_t sbase = smem_to_u32(smp);
    int*   toks_s = (int*)(smp + O_TOK);
    float* wsm_s  = (float*)(smp + O_WSM);
    float* b1s    = (float*)(smp + O_B1);
    float* b2s    = (float*)(smp + O_B2);

    const int tid = threadIdx.x;
    const int wid = tid >> 5;
    const int lane = tid & 31;

    int e = 0;
    #pragma unroll 1
    while (t >= g_tile_off[e + 1]) ++e;
    const int mtile = t - g_tile_off[e];
    const int off   = g_offsets[e];
    const int cnt   = g_counts[e];
    const int m0g   = mtile * TM;
    const int valid = min(TM, cnt - m0g);

    if (tid < 64) {
        if (tid < valid) {
            toks_s[tid] = g_bucket_tok[off + m0g + tid];
            wsm_s[tid]  = g_bucket_w[off + m0g + tid];
        } else { toks_s[tid] = 0; wsm_s[tid] = 0.f; }
    }
    if (tid < 128) b2s[tid] = b2[e * DMODEL + tid];
    b1s[tid] = b1[e * HDIM + tid];
    __syncthreads();

    // ---- async gather X rows [64,128] fp16 ----
    #pragma unroll
    for (int i = tid; i < 1024; i += NTHR) {
        int r = i >> 4, ch = i & 15;
        const size_t src = (size_t)toks_s[r] * DMODEL + ch * 8;
        cp16(sbase + O_XH + r * RW128 + ch * 16, g_xh + src);
    }

    const size_t w1base = (size_t)e * HDIM * DMODEL;
    const size_t w2base = (size_t)e * DMODEL * HDIM;

    // ---- async load W1 chunk 0: [64h, 128d] fp16 ----
    #pragma unroll
    for (int i = tid; i < 1024; i += NTHR) {
        int r = i >> 4, ch = i & 15;
        size_t src = w1base + (size_t)r * DMODEL + ch * 8;
        cp16(sbase + O_BH + r * RW128 + ch * 16, g_w1h + src);
    }
    CP_COMMIT();
    CP_WAIT0();
    __syncthreads();

    // warp tiling: 4 m-warps (16 rows) x 2 n-warps
    const int m0 = (wid >> 1) * 16;
    const int nw = wid & 1;
    const uint32_t arow  = m0 + (lane & 15);
    const uint32_t acolb = ((lane >> 4) & 1) * 16;
    const uint32_t brsub = ((lane >> 4) & 1) * 8 + (lane & 7);
    const uint32_t bcolb = ((lane >> 3) & 1) * 16;

    float acc2[8][4];
    #pragma unroll
    for (int j = 0; j < 8; ++j)
        #pragma unroll
        for (int q = 0; q < 4; ++q) acc2[j][q] = 0.f;

    #pragma unroll 1
    for (int c = 0; c < 4; ++c) {
        // ---- FC1: h_c[64,64] = X[64,128] @ W1c[64,128]^T ; warp m16 x n32 ----
        float acc1[4][4];
        #pragma unroll
        for (int j = 0; j < 4; ++j)
            #pragma unroll
            for (int q = 0; q < 4; ++q) acc1[j][q] = 0.f;

        #pragma unroll 1
        for (int k = 0; k < 8; ++k) {
            uint32_t aaddr = sbase + O_XH + arow * RW128 + k * 32 + acolb;
            uint32_t ah0, ah1, ah2, ah3;
            ldsm4(ah0, ah1, ah2, ah3, aaddr);
            #pragma unroll
            for (int jp = 0; jp < 2; ++jp) {
                uint32_t brow = nw * 32 + jp * 16 + brsub;
                uint32_t baddr = sbase + O_BH + brow * RW128 + k * 32 + bcolb;
                uint32_t bh0, bh1, bh2, bh3;
                ldsm4(bh0, bh1, bh2, bh3, baddr);
                mma16816(acc1[2 * jp],     ah0, ah1, ah2, ah3, bh0, bh1);
                mma16816(acc1[2 * jp + 1], ah0, ah1, ah2, ah3, bh2, bh3);
            }
        }
        __syncthreads();   // W1c consumed

        // ---- prefetch W2 chunk c: [128d, 64h] (overlaps epilogue) ----
        #pragma unroll
        for (int i = tid; i < 1024; i += NTHR) {
            int r = i >> 3, ch = i & 7;
            size_t src = w2base + (size_t)r * HDIM + c * 64 + ch * 8;
            cp16(sbase + O_BH + r * RW64 + ch * 16, g_w2h + src);
        }
        CP_COMMIT();

        // ---- epilogue 1: relu(acc1 + b1) -> fp16 into C [64,64] ----
        {
            const int r0 = m0 + (lane >> 2);
            const int cb = (lane & 3) * 2;
            #pragma unroll
            for (int jn = 0; jn < 4; ++jn) {
                const float* a = acc1[jn];
                int coll = nw * 32 + jn * 8 + cb;
                int colg = c * 64 + coll;
                float bb0 = b1s[colg], bb1 = b1s[colg + 1];
                __half h0 = __float2half_rn(fmaxf(a[0] + bb0, 0.f));
                __half h1 = __float2half_rn(fmaxf(a[1] + bb1, 0.f));
                __half h2 = __float2half_rn(fmaxf(a[2] + bb0, 0.f));
                __half h3 = __float2half_rn(fmaxf(a[3] + bb1, 0.f));
                *reinterpret_cast<uint32_t*>(smp + O_CH + r0 * RW64 + coll * 2) = packh(h0, h1);
                *reinterpret_cast<uint32_t*>(smp + O_CH + (r0 + 8) * RW64 + coll * 2) = packh(h2, h3);
            }
        }
        CP_WAIT0();
        __syncthreads();   // W2c ready, h visible

        // ---- FC2: acc2 += h_c[64,64] @ W2c[128,64]^T ; warp m16 x n64 ----
        #pragma unroll 1
        for (int k = 0; k < 4; ++k) {
            uint32_t aaddr = sbase + O_CH + arow * RW64 + k * 32 + acolb;
            uint32_t ah0, ah1, ah2, ah3;
            ldsm4(ah0, ah1, ah2, ah3, aaddr);
            #pragma unroll
            for (int jp = 0; jp < 4; ++jp) {
                uint32_t brow = nw * 64 + jp * 16 + brsub;
                uint32_t baddr = sbase + O_BH + brow * RW64 + k * 32 + bcolb;
                uint32_t bh0, bh1, bh2, bh3;
                ldsm4(bh0, bh1, bh2, bh3, baddr);
                mma16816(acc2[2 * jp],     ah0, ah1, ah2, ah3, bh0, bh1);
                mma16816(acc2[2 * jp + 1], ah0, ah1, ah2, ah3, bh2, bh3);
            }
        }
        __syncthreads();   // W2c + C consumed

        // ---- prefetch W1 chunk c+1 ----
        if (c < 3) {
            #pragma unroll
            for (int i = tid; i < 1024; i += NTHR) {
                int r = i >> 4, ch = i & 15;
                size_t src = w1base + (size_t)((c + 1) * 64 + r) * DMODEL + ch * 8;
                cp16(sbase + O_BH + r * RW128 + ch * 16, g_w1h + src);
            }
            CP_COMMIT();
            CP_WAIT0();
            __syncthreads();
        }
    }

    // ---- epilogue 2: w * (acc2 + b2) -> g_partial_h (fp16) ----
    {
        const int cb = (lane & 3) * 2;
        const int r0 = m0 + (lane >> 2);
        const int r1 = r0 + 8;
        const float w0 = (r0 < valid) ? wsm_s[r0] : 0.f;
        const float w1 = (r1 < valid) ? wsm_s[r1] : 0.f;
        const size_t s0 = (size_t)(off + m0g + r0) * DMODEL;
        const size_t s1 = (size_t)(off + m0g + r1) * DMODEL;
        #pragma unroll
        for (int jn = 0; jn < 8; ++jn) {
            const float* a = acc2[jn];
            int col = nw * 64 + jn * 8 + cb;
            float bb0 = b2s[col], bb1 = b2s[col + 1];
            if (r0 < valid) {
                __half q0 = __float2half_rn(w0 * (a[0] + bb0));
                __half q1 = __float2half_rn(w0 * (a[1] + bb1));
                *reinterpret_cast<uint32_t*>(&g_partial_h[s0 + col]) = packh(q0, q1);
            }
            if (r1 < valid) {
                __half q2 = __float2half_rn(w1 * (a[2] + bb0));
                __half q3 = __float2half_rn(w1 * (a[3] + bb1));
                *reinterpret_cast<uint32_t*>(&g_partial_h[s1 + col]) = packh(q2, q3);
            }
        }
    }
}

// ================= kernel: combine (fp16 partials -> fp32 out) =================
__global__ void __launch_bounds__(256) combine_kernel(float* __restrict__ out) {
    int gid = blockIdx.x * 256 + threadIdx.x;   // NTOK*16 threads, 8 cols each
    int n = gid >> 4;
    int q = gid & 15;
    int s0 = g_tok_slot[2 * n];
    int s1 = g_tok_slot[2 * n + 1];
    const uint4* P = reinterpret_cast<const uint4*>(g_partial_h);
    uint4 u0 = P[(size_t)s0 * 16 + q];
    uint4 u1 = P[(size_t)s1 * 16 + q];
    const __half2* h0 = reinterpret_cast<const __half2*>(&u0);
    const __half2* h1 = reinterpret_cast<const __half2*>(&u1);
    float4 o0, o1;
    float2 a0 = __half22float2(h0[0]), b0 = __half22float2(h1[0]);
    float2 a1 = __half22float2(h0[1]), b1 = __half22float2(h1[1]);
    float2 a2 = __half22float2(h0[2]), b2 = __half22float2(h1[2]);
    float2 a3 = __half22float2(h0[3]), b3 = __half22float2(h1[3]);
    o0.x = a0.x + b0.x; o0.y = a0.y + b0.y;
    o0.z = a1.x + b1.x; o0.w = a1.y + b1.y;
    o1.x = a2.x + b2.x; o1.y = a2.y + b2.y;
    o1.z = a3.x + b3.x; o1.w = a3.y + b3.y;
    float4* O = reinterpret_cast<float4*>(out);
    O[(size_t)n * 32 + q * 2]     = o0;
    O[(size_t)n * 32 + q * 2 + 1] = o1;
}

// ================= launch =================
extern "C" void kernel_launch(void* const* d_in, const int* in_sizes, int n_in,
                              void* d_out, int out_size) {
    const float* x  = (const float*)d_in[0];
    const float* W1 = (const float*)d_in[1];
    const float* b1 = (const float*)d_in[2];
    const float* W2 = (const float*)d_in[3];
    const float* b2 = (const float*)d_in[4];
    const float* Wr = (const float*)d_in[5];
    const float* br = (const float*)d_in[6];
    float* out = (float*)d_out;

    cudaFuncSetAttribute(expert_mma_kernel,
                         cudaFuncAttributeMaxDynamicSharedMemorySize, SMEM_DYN);

    convert_w_kernel<<<NEXP * HDIM * DMODEL / 256, 256>>>(W1, W2);
    router_kernel<<<NTOK / 256, 256>>>(x, Wr, br);
    scan_loss_kernel<<<1, 32>>>(out, out_size);
    scatter_kernel<<<NTOK / 256, 256>>>();
    // max tiles = 2N/64 + NEXP = 2048 + 32
    expert_mma_kernel<<<2080, NTHR, SMEM_DYN>>>(b1, b2);
    combine_kernel<<<(NTOK * 16) / 256, 256>>>(out);
}